// round 7
// baseline (speedup 1.0000x reference)
#include <cuda_runtime.h>
#include <math.h>

#define B   8
#define C   64
#define DW  128
#define IH  256
#define IW  256
#define HW  65536
#define EPS 1e-6f
#define XP  132   // smem pitch (floats) for 128-px tiles

// ---------- packed fp32x2 helpers ----------
__device__ __forceinline__ double pack2(float lo, float hi) {
    double r; asm("mov.b64 %0,{%1,%2};" : "=d"(r) : "f"(lo), "f"(hi)); return r;
}
__device__ __forceinline__ double fma2(double a, double b, double c) {
    double r; asm("fma.rn.f32x2 %0,%1,%2,%3;" : "=d"(r) : "d"(a), "d"(b), "d"(c)); return r;
}
__device__ __forceinline__ double add2(double a, double b) {
    double r; asm("add.rn.f32x2 %0,%1,%2;" : "=d"(r) : "d"(a), "d"(b)); return r;
}
__device__ __forceinline__ double mul2(double a, double b) {
    double r; asm("mul.rn.f32x2 %0,%1,%2;" : "=d"(r) : "d"(a), "d"(b)); return r;
}

// ---------------- device scratch ----------------------------------------------
__device__ float g_w1t[B*C*DW];   // k-major, ln1_w-folded
__device__ float g_s1 [B*DW];
__device__ float g_c1 [B*DW];
__device__ float g_w2 [B*DW*9];
__device__ float g_w3t[B*C*C];
__device__ float g_w4t[B*C*DW];   // ln2_w-folded
__device__ float g_s4 [B*DW];
__device__ float g_c4 [B*DW];
__device__ float g_w5t[B*C*C];
__device__ float g_t1[(size_t)B*DW*HW];
__device__ float g_t2[(size_t)B*C*HW];
__device__ float g_pool[B*C];

// ---------------- prep --------------------------------------------------------
__global__ void k_prep(const float* __restrict__ w1, const float* __restrict__ w2,
                       const float* __restrict__ w3, const float* __restrict__ w4,
                       const float* __restrict__ w5,
                       const float* __restrict__ ln1w, const float* __restrict__ ln1b,
                       const float* __restrict__ ln2w, const float* __restrict__ ln2b) {
    int blk = blockIdx.x, t = threadIdx.x;
    if (blk >= 4096) { for (int i = t; i < B*C; i += 32) g_pool[i] = 0.f; return; }

    if (blk < 1024 || (blk >= 2560 && blk < 3584)) {
        bool is1 = (blk < 1024);
        int r = is1 ? blk : blk - 2560;
        const float* src = (is1 ? w1 : w4) + r*64;
        int b = r >> 7, o = r & 127;
        float* dstT = (is1 ? g_w1t : g_w4t) + b*8192 + o;
        const float* lw = is1 ? ln1w : ln2w;
        const float* lb = is1 ? ln1b : ln2b;
        float sq = 0.f;
        for (int i = t; i < 64; i += 32) { float v = src[i]; sq += v*v; }
        #pragma unroll
        for (int off = 16; off; off >>= 1) sq += __shfl_xor_sync(0xffffffffu, sq, off);
        float rn = 1.0f / sqrtf(sq);
        float s = 0.f, cx = 0.f;
        for (int i = t; i < 64; i += 32) {
            float wn = src[i] * rn;
            float wf = wn * lw[i];
            dstT[(size_t)i*128] = wf;
            s += wf; cx += wn * lb[i];
        }
        #pragma unroll
        for (int off = 16; off; off >>= 1) {
            s  += __shfl_xor_sync(0xffffffffu, s,  off);
            cx += __shfl_xor_sync(0xffffffffu, cx, off);
        }
        if (t == 0) {
            if (is1) { g_s1[r] = s; g_c1[r] = cx; }
            else     { g_s4[r] = s; g_c4[r] = cx; }
        }
        return;
    }
    const float* src; float* dstT; int L, stride;
    if (blk < 2048)      { int r = blk - 1024; src=w2+r*9; dstT=g_w2+r*9; stride=1; L=9; }
    else if (blk < 2560) { int r = blk - 2048; int b=r>>6, o=r&63; src=w3+r*64; dstT=g_w3t+b*4096+o; stride=64; L=64; }
    else                 { int r = blk - 3584; int b=r>>6, o=r&63; src=w5+r*64; dstT=g_w5t+b*4096+o; stride=64; L=64; }
    float sq = 0.f;
    for (int i = t; i < L; i += 32) { float v = src[i]; sq += v*v; }
    #pragma unroll
    for (int off = 16; off; off >>= 1) sq += __shfl_xor_sync(0xffffffffu, sq, off);
    float rn = 1.0f / sqrtf(sq);
    for (int i = t; i < L; i += 32) dstT[(size_t)i*stride] = src[i] * rn;
}

// ---------------- K1: LN1(folded) + pw1 GEMM, 8o x 8px per thread -------------
__global__ void __launch_bounds__(256, 2) k1(const float* __restrict__ inp,
                                             const float* __restrict__ b1) {
    extern __shared__ float sm[];
    float* XS = sm;          float* WT = sm + 8448;
    float* BS = sm + 16640;  float* SS = sm + 16768; float* CC = sm + 16896;
    float* MU = sm + 17024;  float* RS = sm + 17152;
    int b = blockIdx.y, px0 = blockIdx.x * 128;
    int tid = threadIdx.x, tx = tid & 15, ty = tid >> 4;

    const float* ibase = inp + (size_t)b*C*HW + px0;
    for (int i = tid; i < 2048; i += 256) {
        int c = i >> 5, p4 = i & 31;
        *(float4*)(XS + c*XP + p4*4) = *(const float4*)(ibase + (size_t)c*HW + p4*4);
    }
    {
        const float4* wg = (const float4*)(g_w1t + (size_t)b*8192);
        float4* wd = (float4*)WT;
        for (int i = tid; i < 2048; i += 256) wd[i] = wg[i];
    }
    if (tid < 128) { BS[tid] = b1[b*DW + tid]; SS[tid] = g_s1[b*DW + tid]; CC[tid] = g_c1[b*DW + tid]; }
    __syncthreads();

    if (tid < 128) {
        float s = 0.f, q = 0.f;
        #pragma unroll
        for (int c = 0; c < 64; c++) { float v = XS[c*XP + tid]; s += v; q += v*v; }
        float mu = s * (1.f/64);
        MU[tid] = mu; RS[tid] = rsqrtf(q*(1.f/64) - mu*mu + EPS);
    }
    __syncthreads();

    double acc[8][4];
    #pragma unroll
    for (int u = 0; u < 8; u++) { acc[u][0]=0; acc[u][1]=0; acc[u][2]=0; acc[u][3]=0; }
    int o0 = ty * 8;
    #pragma unroll 4
    for (int k = 0; k < 64; k++) {
        float4 wlo = *(const float4*)(WT + k*128 + o0);
        float4 whi = *(const float4*)(WT + k*128 + o0 + 4);
        double2 xab = *(const double2*)(XS + k*XP + tx*4);
        double2 xcd = *(const double2*)(XS + k*XP + 64 + tx*4);
        double wp[8] = { pack2(wlo.x,wlo.x), pack2(wlo.y,wlo.y), pack2(wlo.z,wlo.z), pack2(wlo.w,wlo.w),
                         pack2(whi.x,whi.x), pack2(whi.y,whi.y), pack2(whi.z,whi.z), pack2(whi.w,whi.w) };
        #pragma unroll
        for (int u = 0; u < 8; u++) {
            acc[u][0] = fma2(wp[u], xab.x, acc[u][0]);
            acc[u][1] = fma2(wp[u], xab.y, acc[u][1]);
            acc[u][2] = fma2(wp[u], xcd.x, acc[u][2]);
            acc[u][3] = fma2(wp[u], xcd.y, acc[u][3]);
        }
    }

    double mu0 = *(const double*)(MU + tx*4), mu1 = *(const double*)(MU + tx*4 + 2);
    double mu2 = *(const double*)(MU + 64 + tx*4), mu3 = *(const double*)(MU + 64 + tx*4 + 2);
    double rs0 = *(const double*)(RS + tx*4), rs1 = *(const double*)(RS + tx*4 + 2);
    double rs2 = *(const double*)(RS + 64 + tx*4), rs3 = *(const double*)(RS + 64 + tx*4 + 2);
    float* op = g_t1 + (size_t)b*DW*HW + px0;
    #pragma unroll
    for (int u = 0; u < 8; u++) {
        int o = o0 + u;
        double nS = pack2(-SS[o], -SS[o]);
        float cbf = CC[o] + BS[o];
        double cb = pack2(cbf, cbf);
        double2 r0, r1;
        r0.x = add2(mul2(fma2(mu0, nS, acc[u][0]), rs0), cb);
        r0.y = add2(mul2(fma2(mu1, nS, acc[u][1]), rs1), cb);
        r1.x = add2(mul2(fma2(mu2, nS, acc[u][2]), rs2), cb);
        r1.y = add2(mul2(fma2(mu3, nS, acc[u][3]), rs3), cb);
        *(double2*)(op + (size_t)o*HW + tx*4)      = r0;
        *(double2*)(op + (size_t)o*HW + 64 + tx*4) = r1;
    }
}

// ---------------- K_dw: depthwise 3x3 + SimpleGate + pool ---------------------
__global__ void __launch_bounds__(256) kdw(const float* __restrict__ b2) {
    int bc = blockIdx.z; int b = bc >> 6; int c = bc & 63;
    __shared__ float s1[34][36];
    __shared__ float s2[34][36];
    __shared__ float wA[9], wB[9], bAB[2], red[8];

    const float* in1 = g_t1 + ((size_t)b*DW + c     ) * HW;
    const float* in2 = g_t1 + ((size_t)b*DW + c + 64) * HW;
    int x0 = blockIdx.x * 32, y0 = blockIdx.y * 32;

    for (int i = threadIdx.x; i < 34*34; i += 256) {
        int ly = i / 34, lx = i % 34;
        int gy = y0 + ly - 1, gx = x0 + lx - 1;
        bool ok = (gy >= 0 && gy < IH && gx >= 0 && gx < IW);
        s1[ly][lx] = ok ? in1[gy*IW + gx] : 0.f;
        s2[ly][lx] = ok ? in2[gy*IW + gx] : 0.f;
    }
    if (threadIdx.x < 9)        wA[threadIdx.x]     = g_w2[((size_t)b*DW + c     )*9 + threadIdx.x];
    else if (threadIdx.x < 18)  wB[threadIdx.x - 9] = g_w2[((size_t)b*DW + c + 64)*9 + threadIdx.x - 9];
    else if (threadIdx.x == 18) bAB[0] = b2[b*DW + c];
    else if (threadIdx.x == 19) bAB[1] = b2[b*DW + c + 64];
    __syncthreads();

    int lx = threadIdx.x & 31, ly0 = (threadIdx.x >> 5) * 4;
    float* obase = g_t2 + ((size_t)b*C + c)*HW;
    float psum = 0.f;
    #pragma unroll
    for (int r = 0; r < 4; r++) {
        int ly = ly0 + r;
        float a = bAB[0], d = bAB[1];
        #pragma unroll
        for (int ky = 0; ky < 3; ky++)
            #pragma unroll
            for (int kx = 0; kx < 3; kx++) {
                a += wA[ky*3 + kx] * s1[ly + ky][lx + kx];
                d += wB[ky*3 + kx] * s2[ly + ky][lx + kx];
            }
        float g = a * d;
        obase[(y0 + ly)*IW + (x0 + lx)] = g;
        psum += g;
    }
    #pragma unroll
    for (int off = 16; off; off >>= 1) psum += __shfl_down_sync(0xffffffffu, psum, off);
    if (lx == 0) red[threadIdx.x >> 5] = psum;
    __syncthreads();
    if (threadIdx.x == 0) {
        float t = 0.f;
        #pragma unroll
        for (int i = 0; i < 8; i++) t += red[i];
        atomicAdd(&g_pool[b*C + c], t);
    }
}

// ---------------- K2 fused: sca -> pw3 -> y(smem) -> LN2 -> pw4 -> gate -> pw5 -> out
// floats: XS@0(8448 raw t2 then raw y)  GS@8448(8448 gated)  WT@16896(8192 W3/W4/W5)
//   B3@25088 BET@25152 SCS@25216 PLS@25280 B4@25344(128) S4@25472(128) C4@25600(128)
//   B5@25728(64) GAM@25792(64) MU@25856(128) RS@25984(128)  total 26112 f = 104448 B
__global__ void __launch_bounds__(256, 2) k2(const float* __restrict__ inp,
                                             const float* __restrict__ b3,
                                             const float* __restrict__ b4,
                                             const float* __restrict__ b5,
                                             const float* __restrict__ beta,
                                             const float* __restrict__ gamma,
                                             const float* __restrict__ sca_w,
                                             const float* __restrict__ sca_b,
                                             float* __restrict__ out) {
    extern __shared__ float sm[];
    float* XS = sm;          float* GS = sm + 8448;   float* WT = sm + 16896;
    float* B3 = sm + 25088;  float* BET = sm + 25152;
    float* SCS = sm + 25216; float* PLS = sm + 25280;
    float* B4 = sm + 25344;  float* S4 = sm + 25472;  float* C4 = sm + 25600;
    float* B5 = sm + 25728;  float* GAM = sm + 25792;
    float* MU = sm + 25856;  float* RS = sm + 25984;
    int b = blockIdx.y, px0 = blockIdx.x * 128;
    int tid = threadIdx.x, tx = tid & 15, ty = tid >> 4;

    // stage t2 tile + W3 + constants
    const float* t2b = g_t2 + (size_t)b*C*HW + px0;
    for (int i = tid; i < 2048; i += 256) {
        int c = i >> 5, p4 = i & 31;
        *(float4*)(XS + c*XP + p4*4) = *(const float4*)(t2b + (size_t)c*HW + p4*4);
    }
    {
        const float4* wg = (const float4*)(g_w3t + (size_t)b*4096);
        float4* wd = (float4*)WT;
        for (int i = tid; i < 1024; i += 256) wd[i] = wg[i];
    }
    if (tid < 64) {
        B3[tid] = b3[b*C + tid]; BET[tid] = beta[tid];
        PLS[tid] = g_pool[b*C + tid] * (1.f/(float)HW);
        B5[tid] = b5[b*C + tid]; GAM[tid] = gamma[tid];
    } else if (tid < 192) {
        int u = tid - 64;
        B4[u] = b4[b*DW + u]; S4[u] = g_s4[b*DW + u]; C4[u] = g_c4[b*DW + u];
    }
    __syncthreads();

    if (tid < 64) {
        float acc = sca_b[tid];
        #pragma unroll 8
        for (int cc = 0; cc < 64; cc++) acc += sca_w[tid*64 + cc] * PLS[cc];
        SCS[tid] = acc;
    }
    __syncthreads();
    for (int i = tid; i < 4096; i += 256) WT[i] *= SCS[i >> 6];   // fold sca into W3
    __syncthreads();

    // ---- pw3 GEMM: 4o x 8px per thread (rows o0..o0+3)
    double acc3[4][4];
    #pragma unroll
    for (int u = 0; u < 4; u++) { acc3[u][0]=0; acc3[u][1]=0; acc3[u][2]=0; acc3[u][3]=0; }
    int o0 = ty * 4;
    #pragma unroll 4
    for (int k = 0; k < 64; k++) {
        float4 w = *(const float4*)(WT + k*64 + o0);
        double2 xab = *(const double2*)(XS + k*XP + tx*4);
        double2 xcd = *(const double2*)(XS + k*XP + 64 + tx*4);
        double wp[4] = { pack2(w.x,w.x), pack2(w.y,w.y), pack2(w.z,w.z), pack2(w.w,w.w) };
        #pragma unroll
        for (int u = 0; u < 4; u++) {
            acc3[u][0] = fma2(wp[u], xab.x, acc3[u][0]);
            acc3[u][1] = fma2(wp[u], xab.y, acc3[u][1]);
            acc3[u][2] = fma2(wp[u], xcd.x, acc3[u][2]);
            acc3[u][3] = fma2(wp[u], xcd.y, acc3[u][3]);
        }
    }
    __syncthreads();   // XS reads done, safe to overwrite with y

    // ---- pw3 epilogue: y = inp + (acc+b3)*beta -> XS (raw y) ; stage W4
    const float* ib = inp + (size_t)b*C*HW + px0;
    #pragma unroll
    for (int u = 0; u < 4; u++) {
        int o = o0 + u;
        double bp  = pack2(B3[o], B3[o]);
        double btp = pack2(BET[o], BET[o]);
        double2 i0 = *(const double2*)(ib + (size_t)o*HW + tx*4);
        double2 i1 = *(const double2*)(ib + (size_t)o*HW + 64 + tx*4);
        double2 r0, r1;
        r0.x = add2(i0.x, mul2(add2(acc3[u][0], bp), btp));
        r0.y = add2(i0.y, mul2(add2(acc3[u][1], bp), btp));
        r1.x = add2(i1.x, mul2(add2(acc3[u][2], bp), btp));
        r1.y = add2(i1.y, mul2(add2(acc3[u][3], bp), btp));
        *(double2*)(XS + o*XP + tx*4)      = r0;
        *(double2*)(XS + o*XP + 64 + tx*4) = r1;
    }
    {
        const float4* wg = (const float4*)(g_w4t + (size_t)b*8192);
        float4* wd = (float4*)WT;
        for (int i = tid; i < 2048; i += 256) wd[i] = wg[i];
    }
    __syncthreads();

    // ---- LN2 stats on raw y
    if (tid < 128) {
        float s = 0.f, q = 0.f;
        #pragma unroll
        for (int c = 0; c < 64; c++) { float v = XS[c*XP + tid]; s += v; q += v*v; }
        float mu = s * (1.f/64);
        MU[tid] = mu; RS[tid] = rsqrtf(q*(1.f/64) - mu*mu + EPS);
    }
    __syncthreads();

    // ---- pw4 GEMM on raw y (ln folded): rows oa = o0..o0+3 and +64
    double acc[8][4];
    #pragma unroll
    for (int u = 0; u < 8; u++) { acc[u][0]=0; acc[u][1]=0; acc[u][2]=0; acc[u][3]=0; }
    #pragma unroll 4
    for (int k = 0; k < 64; k++) {
        float4 wlo = *(const float4*)(WT + k*128 + o0);
        float4 whi = *(const float4*)(WT + k*128 + 64 + o0);
        double2 xab = *(const double2*)(XS + k*XP + tx*4);
        double2 xcd = *(const double2*)(XS + k*XP + 64 + tx*4);
        double wp[8] = { pack2(wlo.x,wlo.x), pack2(wlo.y,wlo.y), pack2(wlo.z,wlo.z), pack2(wlo.w,wlo.w),
                         pack2(whi.x,whi.x), pack2(whi.y,whi.y), pack2(whi.z,whi.z), pack2(whi.w,whi.w) };
        #pragma unroll
        for (int u = 0; u < 8; u++) {
            acc[u][0] = fma2(wp[u], xab.x, acc[u][0]);
            acc[u][1] = fma2(wp[u], xab.y, acc[u][1]);
            acc[u][2] = fma2(wp[u], xcd.x, acc[u][2]);
            acc[u][3] = fma2(wp[u], xcd.y, acc[u][3]);
        }
    }

    double mu0 = *(const double*)(MU + tx*4), mu1 = *(const double*)(MU + tx*4 + 2);
    double mu2 = *(const double*)(MU + 64 + tx*4), mu3 = *(const double*)(MU + 64 + tx*4 + 2);
    double rs0 = *(const double*)(RS + tx*4), rs1 = *(const double*)(RS + tx*4 + 2);
    double rs2 = *(const double*)(RS + 64 + tx*4), rs3 = *(const double*)(RS + 64 + tx*4 + 2);

    // gate channels o0..o0+3
    double gd[4][4];
    #pragma unroll
    for (int j = 0; j < 4; j++) {
        int oa = o0 + j, ob = oa + 64;
        double nSa = pack2(-S4[oa], -S4[oa]);
        double nSb = pack2(-S4[ob], -S4[ob]);
        float cbaf = C4[oa] + B4[oa], cbbf = C4[ob] + B4[ob];
        double cba = pack2(cbaf, cbaf), cbb = pack2(cbbf, cbbf);
        double va0 = add2(mul2(fma2(mu0, nSa, acc[j][0]), rs0), cba);
        double va1 = add2(mul2(fma2(mu1, nSa, acc[j][1]), rs1), cba);
        double va2 = add2(mul2(fma2(mu2, nSa, acc[j][2]), rs2), cba);
        double va3 = add2(mul2(fma2(mu3, nSa, acc[j][3]), rs3), cba);
        double vb0 = add2(mul2(fma2(mu0, nSb, acc[j+4][0]), rs0), cbb);
        double vb1 = add2(mul2(fma2(mu1, nSb, acc[j+4][1]), rs1), cbb);
        double vb2 = add2(mul2(fma2(mu2, nSb, acc[j+4][2]), rs2), cbb);
        double vb3 = add2(mul2(fma2(mu3, nSb, acc[j+4][3]), rs3), cbb);
        gd[j][0] = mul2(va0, vb0); gd[j][1] = mul2(va1, vb1);
        gd[j][2] = mul2(va2, vb2); gd[j][3] = mul2(va3, vb3);
    }
    __syncthreads();   // WT (W4) reads done

    // gated -> GS ; stage W5
    #pragma unroll
    for (int j = 0; j < 4; j++) {
        float* gr = GS + (o0 + j)*XP;
        *(double2*)(gr + tx*4)      = *(double2*)&gd[j][0];
        *(double2*)(gr + 64 + tx*4) = *(double2*)&gd[j][2];
    }
    {
        const float4* wg = (const float4*)(g_w5t + (size_t)b*4096);
        float4* wd = (float4*)WT;
        for (int i = tid; i < 1024; i += 256) wd[i] = wg[i];
    }
    __syncthreads();

    // ---- pw5 GEMM: 4o x 8px reading GS
    double acc2[4][4];
    #pragma unroll
    for (int u = 0; u < 4; u++) { acc2[u][0]=0; acc2[u][1]=0; acc2[u][2]=0; acc2[u][3]=0; }
    #pragma unroll 4
    for (int k = 0; k < 64; k++) {
        float4 w = *(const float4*)(WT + k*64 + o0);
        double2 xab = *(const double2*)(GS + k*XP + tx*4);
        double2 xcd = *(const double2*)(GS + k*XP + 64 + tx*4);
        double wp[4] = { pack2(w.x,w.x), pack2(w.y,w.y), pack2(w.z,w.z), pack2(w.w,w.w) };
        #pragma unroll
        for (int u = 0; u < 4; u++) {
            acc2[u][0] = fma2(wp[u], xab.x, acc2[u][0]);
            acc2[u][1] = fma2(wp[u], xab.y, acc2[u][1]);
            acc2[u][2] = fma2(wp[u], xcd.x, acc2[u][2]);
            acc2[u][3] = fma2(wp[u], xcd.y, acc2[u][3]);
        }
    }

    // ---- epilogue: out = y(XS) + (acc2+b5)*gamma
    float* ob = out + (size_t)b*C*HW + px0;
    #pragma unroll
    for (int u = 0; u < 4; u++) {
        int o = o0 + u;
        double bp = pack2(B5[o], B5[o]);
        double gp = pack2(GAM[o], GAM[o]);
        double2 y0 = *(const double2*)(XS + o*XP + tx*4);
        double2 y1 = *(const double2*)(XS + o*XP + 64 + tx*4);
        double2 r0, r1;
        r0.x = add2(y0.x, mul2(add2(acc2[u][0], bp), gp));
        r0.y = add2(y0.y, mul2(add2(acc2[u][1], bp), gp));
        r1.x = add2(y1.x, mul2(add2(acc2[u][2], bp), gp));
        r1.y = add2(y1.y, mul2(add2(acc2[u][3], bp), gp));
        *(double2*)(ob + (size_t)o*HW + tx*4)      = r0;
        *(double2*)(ob + (size_t)o*HW + 64 + tx*4) = r1;
    }
}

// ---------------- launch ------------------------------------------------------
extern "C" void kernel_launch(void* const* d_in, const int* in_sizes, int n_in,
                              void* d_out, int out_size) {
    const float* inp   = (const float*)d_in[0];
    const float* w1    = (const float*)d_in[1];
    const float* b1    = (const float*)d_in[2];
    const float* w2    = (const float*)d_in[3];
    const float* b2    = (const float*)d_in[4];
    const float* w3    = (const float*)d_in[5];
    const float* b3    = (const float*)d_in[6];
    const float* w4    = (const float*)d_in[7];
    const float* b4    = (const float*)d_in[8];
    const float* w5    = (const float*)d_in[9];
    const float* b5    = (const float*)d_in[10];
    const float* ln1w  = (const float*)d_in[11];
    const float* ln1b  = (const float*)d_in[12];
    const float* ln2w  = (const float*)d_in[13];
    const float* ln2b  = (const float*)d_in[14];
    const float* scaw  = (const float*)d_in[15];
    const float* scab  = (const float*)d_in[16];
    const float* beta  = (const float*)d_in[17];
    const float* gamma = (const float*)d_in[18];
    float* out = (float*)d_out;

    cudaFuncSetAttribute(k1, cudaFuncAttributeMaxDynamicSharedMemorySize, 69120);
    cudaFuncSetAttribute(k2, cudaFuncAttributeMaxDynamicSharedMemorySize, 104448);

    k_prep<<<4097, 32>>>(w1, w2, w3, w4, w5, ln1w, ln1b, ln2w, ln2b);
    k1 <<<dim3(HW/128, B), 256, 69120>>>(inp, b1);
    kdw<<<dim3(IW/32, IH/32, B*C), 256>>>(b2);
    k2 <<<dim3(HW/128, B), 256, 104448>>>(inp, b3, b4, b5, beta, gamma, scaw, scab, out);
}

// round 9
// speedup vs baseline: 1.0983x; 1.0983x over previous
#include <cuda_runtime.h>
#include <cuda_bf16.h>
#include <cstdint>
#include <math.h>

#define B   8
#define C   64
#define DW  128
#define IH  256
#define IW  256
#define HW  65536
#define EPS 1e-6f
#define XP  132

// ---------- packed fp32x2 helpers (k1) ----------
__device__ __forceinline__ double pack2(float lo, float hi) {
    double r; asm("mov.b64 %0,{%1,%2};" : "=d"(r) : "f"(lo), "f"(hi)); return r;
}
__device__ __forceinline__ double fma2(double a, double b, double c) {
    double r; asm("fma.rn.f32x2 %0,%1,%2,%3;" : "=d"(r) : "d"(a), "d"(b), "d"(c)); return r;
}
__device__ __forceinline__ double add2(double a, double b) {
    double r; asm("add.rn.f32x2 %0,%1,%2;" : "=d"(r) : "d"(a), "d"(b)); return r;
}
__device__ __forceinline__ double mul2(double a, double b) {
    double r; asm("mul.rn.f32x2 %0,%1,%2;" : "=d"(r) : "d"(a), "d"(b)); return r;
}

// ---------- bf16 split helpers ----------
__device__ __forceinline__ void bsplit2(float f0, float f1, uint32_t& h, uint32_t& l) {
    __nv_bfloat16 h0 = __float2bfloat16(f0), h1 = __float2bfloat16(f1);
    float r0 = f0 - __bfloat162float(h0), r1 = f1 - __bfloat162float(h1);
    __nv_bfloat16 l0 = __float2bfloat16(r0), l1 = __float2bfloat16(r1);
    h = (uint32_t)__bfloat16_as_ushort(h0) | ((uint32_t)__bfloat16_as_ushort(h1) << 16);
    l = (uint32_t)__bfloat16_as_ushort(l0) | ((uint32_t)__bfloat16_as_ushort(l1) << 16);
}

// ---------- mma.sync m16n8k16 bf16 (HMMA, plain sm_103) ----------
__device__ __forceinline__ void mma16816(float* d,
        uint32_t a0, uint32_t a1, uint32_t a2, uint32_t a3,
        uint32_t b0, uint32_t b1) {
    asm volatile("mma.sync.aligned.m16n8k16.row.col.f32.bf16.bf16.f32 "
        "{%0,%1,%2,%3}, {%4,%5,%6,%7}, {%8,%9}, {%0,%1,%2,%3};"
        : "+f"(d[0]), "+f"(d[1]), "+f"(d[2]), "+f"(d[3])
        : "r"(a0), "r"(a1), "r"(a2), "r"(a3), "r"(b0), "r"(b1));
}

// ---------------- device scratch ----------------------------------------------
__device__ float g_w1t[B*C*DW];   // k-major, ln1_w-folded (f32, for k1)
__device__ float g_s1 [B*DW];
__device__ float g_c1 [B*DW];
__device__ float g_w2 [B*DW*9];
__device__ unsigned short g_w3h[B*64*64], g_w3l[B*64*64];   // [b][o][k] bf16 split
__device__ unsigned short g_w4h[B*128*64], g_w4l[B*128*64]; // ln2-folded
__device__ float g_s4 [B*DW];
__device__ float g_c4 [B*DW];
__device__ unsigned short g_w5h[B*64*64], g_w5l[B*64*64];
__device__ float g_t1[(size_t)B*DW*HW];
__device__ float g_t2[(size_t)B*C*HW];
__device__ float g_pool[B*C];

// ---------------- prep --------------------------------------------------------
__global__ void k_prep(const float* __restrict__ w1, const float* __restrict__ w2,
                       const float* __restrict__ w3, const float* __restrict__ w4,
                       const float* __restrict__ w5,
                       const float* __restrict__ ln1w, const float* __restrict__ ln1b,
                       const float* __restrict__ ln2w, const float* __restrict__ ln2b) {
    int blk = blockIdx.x, t = threadIdx.x;
    if (blk >= 4096) { for (int i = t; i < B*C; i += 32) g_pool[i] = 0.f; return; }

    if (blk < 1024 || (blk >= 2560 && blk < 3584)) {
        bool is1 = (blk < 1024);
        int r = is1 ? blk : blk - 2560;
        const float* src = (is1 ? w1 : w4) + r*64;
        const float* lw = is1 ? ln1w : ln2w;
        const float* lb = is1 ? ln1b : ln2b;
        float sq = 0.f;
        for (int i = t; i < 64; i += 32) { float v = src[i]; sq += v*v; }
        #pragma unroll
        for (int off = 16; off; off >>= 1) sq += __shfl_xor_sync(0xffffffffu, sq, off);
        float rn = 1.0f / sqrtf(sq);
        float s = 0.f, cx = 0.f;
        if (is1) {
            int b = r >> 7, o = r & 127;
            float* dstT = g_w1t + b*8192 + o;
            for (int i = t; i < 64; i += 32) {
                float wn = src[i] * rn;
                float wf = wn * lw[i];
                dstT[(size_t)i*128] = wf;
                s += wf; cx += wn * lb[i];
            }
        } else {
            unsigned short* dh = g_w4h + r*64;
            unsigned short* dl = g_w4l + r*64;
            for (int i = t; i < 64; i += 32) {
                float wn = src[i] * rn;
                float wf = wn * lw[i];
                __nv_bfloat16 h = __float2bfloat16(wf);
                __nv_bfloat16 l = __float2bfloat16(wf - __bfloat162float(h));
                dh[i] = __bfloat16_as_ushort(h);
                dl[i] = __bfloat16_as_ushort(l);
                s += wf; cx += wn * lb[i];
            }
        }
        #pragma unroll
        for (int off = 16; off; off >>= 1) {
            s  += __shfl_xor_sync(0xffffffffu, s,  off);
            cx += __shfl_xor_sync(0xffffffffu, cx, off);
        }
        if (t == 0) {
            if (is1) { g_s1[r] = s; g_c1[r] = cx; }
            else     { g_s4[r] = s; g_c4[r] = cx; }
        }
        return;
    }
    if (blk < 2048) {
        int r = blk - 1024;
        const float* src = w2 + r*9;
        float sq = 0.f;
        for (int i = t; i < 9; i += 32) { float v = src[i]; sq += v*v; }
        #pragma unroll
        for (int off = 16; off; off >>= 1) sq += __shfl_xor_sync(0xffffffffu, sq, off);
        float rn = 1.0f / sqrtf(sq);
        for (int i = t; i < 9; i += 32) g_w2[r*9 + i] = src[i] * rn;
        return;
    }
    // w3 / w5 rows -> bf16 split row-major
    bool is3 = (blk < 2560);
    int r = is3 ? (blk - 2048) : (blk - 3584);
    const float* src = (is3 ? w3 : w5) + r*64;
    unsigned short* dh = (is3 ? g_w3h : g_w5h) + r*64;
    unsigned short* dl = (is3 ? g_w3l : g_w5l) + r*64;
    float sq = 0.f;
    for (int i = t; i < 64; i += 32) { float v = src[i]; sq += v*v; }
    #pragma unroll
    for (int off = 16; off; off >>= 1) sq += __shfl_xor_sync(0xffffffffu, sq, off);
    float rn = 1.0f / sqrtf(sq);
    for (int i = t; i < 64; i += 32) {
        float wn = src[i] * rn;
        __nv_bfloat16 h = __float2bfloat16(wn);
        __nv_bfloat16 l = __float2bfloat16(wn - __bfloat162float(h));
        dh[i] = __bfloat16_as_ushort(h);
        dl[i] = __bfloat16_as_ushort(l);
    }
}

// ---------------- K1: LN1(folded) + pw1 GEMM (scalar f32x2, from R6) ----------
__global__ void __launch_bounds__(256, 2) k1(const float* __restrict__ inp,
                                             const float* __restrict__ b1) {
    extern __shared__ float sm[];
    float* XS = sm;          float* WT = sm + 8448;
    float* BS = sm + 16640;  float* SS = sm + 16768; float* CC = sm + 16896;
    float* MU = sm + 17024;  float* RS = sm + 17152;
    int b = blockIdx.y, px0 = blockIdx.x * 128;
    int tid = threadIdx.x, tx = tid & 15, ty = tid >> 4;

    const float* ibase = inp + (size_t)b*C*HW + px0;
    for (int i = tid; i < 2048; i += 256) {
        int c = i >> 5, p4 = i & 31;
        *(float4*)(XS + c*XP + p4*4) = *(const float4*)(ibase + (size_t)c*HW + p4*4);
    }
    {
        const float4* wg = (const float4*)(g_w1t + (size_t)b*8192);
        float4* wd = (float4*)WT;
        for (int i = tid; i < 2048; i += 256) wd[i] = wg[i];
    }
    if (tid < 128) { BS[tid] = b1[b*DW + tid]; SS[tid] = g_s1[b*DW + tid]; CC[tid] = g_c1[b*DW + tid]; }
    __syncthreads();

    if (tid < 128) {
        float s = 0.f, q = 0.f;
        #pragma unroll
        for (int c = 0; c < 64; c++) { float v = XS[c*XP + tid]; s += v; q += v*v; }
        float mu = s * (1.f/64);
        MU[tid] = mu; RS[tid] = rsqrtf(q*(1.f/64) - mu*mu + EPS);
    }
    __syncthreads();

    double acc[8][4];
    #pragma unroll
    for (int u = 0; u < 8; u++) { acc[u][0]=0; acc[u][1]=0; acc[u][2]=0; acc[u][3]=0; }
    int o0 = ty * 8;
    #pragma unroll 4
    for (int k = 0; k < 64; k++) {
        float4 wlo = *(const float4*)(WT + k*128 + o0);
        float4 whi = *(const float4*)(WT + k*128 + o0 + 4);
        double2 xab = *(const double2*)(XS + k*XP + tx*4);
        double2 xcd = *(const double2*)(XS + k*XP + 64 + tx*4);
        double wp[8] = { pack2(wlo.x,wlo.x), pack2(wlo.y,wlo.y), pack2(wlo.z,wlo.z), pack2(wlo.w,wlo.w),
                         pack2(whi.x,whi.x), pack2(whi.y,whi.y), pack2(whi.z,whi.z), pack2(whi.w,whi.w) };
        #pragma unroll
        for (int u = 0; u < 8; u++) {
            acc[u][0] = fma2(wp[u], xab.x, acc[u][0]);
            acc[u][1] = fma2(wp[u], xab.y, acc[u][1]);
            acc[u][2] = fma2(wp[u], xcd.x, acc[u][2]);
            acc[u][3] = fma2(wp[u], xcd.y, acc[u][3]);
        }
    }

    double mu0 = *(const double*)(MU + tx*4), mu1 = *(const double*)(MU + tx*4 + 2);
    double mu2 = *(const double*)(MU + 64 + tx*4), mu3 = *(const double*)(MU + 64 + tx*4 + 2);
    double rs0 = *(const double*)(RS + tx*4), rs1 = *(const double*)(RS + tx*4 + 2);
    double rs2 = *(const double*)(RS + 64 + tx*4), rs3 = *(const double*)(RS + 64 + tx*4 + 2);
    float* op = g_t1 + (size_t)b*DW*HW + px0;
    #pragma unroll
    for (int u = 0; u < 8; u++) {
        int o = o0 + u;
        double nS = pack2(-SS[o], -SS[o]);
        float cbf = CC[o] + BS[o];
        double cb = pack2(cbf, cbf);
        double2 r0, r1;
        r0.x = add2(mul2(fma2(mu0, nS, acc[u][0]), rs0), cb);
        r0.y = add2(mul2(fma2(mu1, nS, acc[u][1]), rs1), cb);
        r1.x = add2(mul2(fma2(mu2, nS, acc[u][2]), rs2), cb);
        r1.y = add2(mul2(fma2(mu3, nS, acc[u][3]), rs3), cb);
        *(double2*)(op + (size_t)o*HW + tx*4)      = r0;
        *(double2*)(op + (size_t)o*HW + 64 + tx*4) = r1;
    }
}

// ---------------- K_dw: depthwise 3x3 + SimpleGate + pool ---------------------
__global__ void __launch_bounds__(256) kdw(const float* __restrict__ b2) {
    int bc = blockIdx.z; int b = bc >> 6; int c = bc & 63;
    __shared__ float s1[34][36];
    __shared__ float s2[34][36];
    __shared__ float wA[9], wB[9], bAB[2], red[8];

    const float* in1 = g_t1 + ((size_t)b*DW + c     ) * HW;
    const float* in2 = g_t1 + ((size_t)b*DW + c + 64) * HW;
    int x0 = blockIdx.x * 32, y0 = blockIdx.y * 32;

    for (int i = threadIdx.x; i < 34*34; i += 256) {
        int ly = i / 34, lx = i % 34;
        int gy = y0 + ly - 1, gx = x0 + lx - 1;
        bool ok = (gy >= 0 && gy < IH && gx >= 0 && gx < IW);
        s1[ly][lx] = ok ? in1[gy*IW + gx] : 0.f;
        s2[ly][lx] = ok ? in2[gy*IW + gx] : 0.f;
    }
    if (threadIdx.x < 9)        wA[threadIdx.x]     = g_w2[((size_t)b*DW + c     )*9 + threadIdx.x];
    else if (threadIdx.x < 18)  wB[threadIdx.x - 9] = g_w2[((size_t)b*DW + c + 64)*9 + threadIdx.x - 9];
    else if (threadIdx.x == 18) bAB[0] = b2[b*DW + c];
    else if (threadIdx.x == 19) bAB[1] = b2[b*DW + c + 64];
    __syncthreads();

    int lx = threadIdx.x & 31, ly0 = (threadIdx.x >> 5) * 4;
    float* obase = g_t2 + ((size_t)b*C + c)*HW;
    float psum = 0.f;
    #pragma unroll
    for (int r = 0; r < 4; r++) {
        int ly = ly0 + r;
        float a = bAB[0], d = bAB[1];
        #pragma unroll
        for (int ky = 0; ky < 3; ky++)
            #pragma unroll
            for (int kx = 0; kx < 3; kx++) {
                a += wA[ky*3 + kx] * s1[ly + ky][lx + kx];
                d += wB[ky*3 + kx] * s2[ly + ky][lx + kx];
            }
        float g = a * d;
        obase[(y0 + ly)*IW + (x0 + lx)] = g;
        psum += g;
    }
    #pragma unroll
    for (int off = 16; off; off >>= 1) psum += __shfl_down_sync(0xffffffffu, psum, off);
    if (lx == 0) red[threadIdx.x >> 5] = psum;
    __syncthreads();
    if (threadIdx.x == 0) {
        float t = 0.f;
        #pragma unroll
        for (int i = 0; i < 8; i++) t += red[i];
        atomicAdd(&g_pool[b*C + c], t);
    }
}

// ---------------- K2 fused with HMMA (mma.sync bf16-split) --------------------
// byte offsets:
#define O_XAH 0        // 128 rows * 36 u32 = 18432
#define O_XAL 18432
#define O_WH  36864    // up to 128 rows * 36 u32
#define O_WL  55296
#define O_YS  73728    // 128 * 66 f32 = 33792  (also TS[64][132] during staging)
#define O_MU  107520
#define O_RS  108032
#define O_S4  108544
#define O_C4B 109056
#define O_B3  109568
#define O_BET 109824
#define O_B5  110080
#define O_GAM 110336
#define O_SCS 110592
#define O_PLS 110848
#define K2_SMEM 111104

__global__ void __launch_bounds__(256) k2(const float* __restrict__ inp,
                                          const float* __restrict__ b3,
                                          const float* __restrict__ b4,
                                          const float* __restrict__ b5,
                                          const float* __restrict__ beta,
                                          const float* __restrict__ gamma,
                                          const float* __restrict__ sca_w,
                                          const float* __restrict__ sca_b,
                                          float* __restrict__ out) {
    extern __shared__ __align__(16) char smem[];
    uint32_t* XAh = (uint32_t*)(smem + O_XAH);
    uint32_t* XAl = (uint32_t*)(smem + O_XAL);
    uint32_t* WhU = (uint32_t*)(smem + O_WH);
    uint32_t* WlU = (uint32_t*)(smem + O_WL);
    float* YS  = (float*)(smem + O_YS);
    float* TS  = (float*)(smem + O_YS);     // staging alias: [64][132]
    float* MU  = (float*)(smem + O_MU);
    float* RS  = (float*)(smem + O_RS);
    float* S4  = (float*)(smem + O_S4);
    float* C4B = (float*)(smem + O_C4B);
    float* B3B = (float*)(smem + O_B3);
    float* BETB= (float*)(smem + O_BET);
    float* B5B = (float*)(smem + O_B5);
    float* GAMB= (float*)(smem + O_GAM);
    float* SCS = (float*)(smem + O_SCS);
    float* PLS = (float*)(smem + O_PLS);

    int b = blockIdx.y, px0 = blockIdx.x * 128;
    int tid = threadIdx.x, lane = tid & 31, warp = tid >> 5;
    int g = lane >> 2, t = lane & 3;
    int m0 = warp * 16;

    // ---- stage: consts, W3, t2 tile
    if (tid < 64) {
        B3B[tid] = b3[b*64 + tid]; BETB[tid] = beta[tid];
        B5B[tid] = b5[b*64 + tid]; GAMB[tid] = gamma[tid];
        PLS[tid] = g_pool[b*64 + tid] * (1.f/(float)HW);
    } else if (tid < 192) {
        int u = tid - 64;
        S4[u] = g_s4[b*128 + u];
        C4B[u] = g_c4[b*128 + u] + b4[b*128 + u];
    }
    {
        const uint32_t* wh = (const uint32_t*)g_w3h + b*2048;
        const uint32_t* wl = (const uint32_t*)g_w3l + b*2048;
        for (int i = tid; i < 2048; i += 256) {
            int o = i >> 5, w = i & 31;
            WhU[o*36 + w] = wh[i];
            WlU[o*36 + w] = wl[i];
        }
    }
    {
        const float* t2b = g_t2 + (size_t)b*C*HW + px0;
        for (int i = tid; i < 2048; i += 256) {
            int c = i >> 5, p4 = i & 31;
            *(float4*)(TS + c*132 + p4*4) = *(const float4*)(t2b + (size_t)c*HW + p4*4);
        }
    }
    __syncthreads();

    if (tid < 64) {
        float acc = sca_b[tid];
        #pragma unroll 8
        for (int cc = 0; cc < 64; cc++) acc += sca_w[tid*64 + cc] * PLS[cc];
        SCS[tid] = acc;
    }
    __syncthreads();

    // ---- convert X = sca * t2 to bf16 hi/lo A-layout [px][k]
    {
        int px = tid & 127, ch0 = (tid >> 7) * 32;
        #pragma unroll 4
        for (int c = ch0; c < ch0 + 32; c += 2) {
            float v0 = TS[c*132 + px] * SCS[c];
            float v1 = TS[(c+1)*132 + px] * SCS[c+1];
            uint32_t h, l; bsplit2(v0, v1, h, l);
            XAh[px*36 + (c>>1)] = h;
            XAl[px*36 + (c>>1)] = l;
        }
    }
    __syncthreads();

    // ---- pw3 GEMM (HMMA): d3[8][4]
    float d3[8][4];
    #pragma unroll
    for (int n = 0; n < 8; n++) { d3[n][0]=0; d3[n][1]=0; d3[n][2]=0; d3[n][3]=0; }
    #pragma unroll
    for (int k = 0; k < 4; k++) {
        int ab = (m0 + g)*36 + k*8 + t;
        uint32_t ah0 = XAh[ab], ah1 = XAh[ab + 288], ah2 = XAh[ab + 4], ah3 = XAh[ab + 292];
        uint32_t al0 = XAl[ab], al1 = XAl[ab + 288], al2 = XAl[ab + 4], al3 = XAl[ab + 292];
        #pragma unroll
        for (int n = 0; n < 8; n++) {
            int bb = (n*8 + g)*36 + k*8 + t;
            uint32_t bh0 = WhU[bb], bh1 = WhU[bb + 4];
            uint32_t bl0 = WlU[bb], bl1 = WlU[bb + 4];
            mma16816(d3[n], ah0, ah1, ah2, ah3, bh0, bh1);
            mma16816(d3[n], al0, al1, al2, al3, bh0, bh1);
            mma16816(d3[n], ah0, ah1, ah2, ah3, bl0, bl1);
        }
    }
    // store frags into YS (D staging)
    #pragma unroll
    for (int n = 0; n < 8; n++) {
        float2 lo; lo.x = d3[n][0]; lo.y = d3[n][1];
        float2 hi; hi.x = d3[n][2]; hi.y = d3[n][3];
        *(float2*)&YS[(m0 + g)*66 + n*8 + t*2]     = lo;
        *(float2*)&YS[(m0 + g + 8)*66 + n*8 + t*2] = hi;
    }
    __syncthreads();

    // ---- epilogue1: y = inp + (D+b3)*beta; LN2 stats; bf16-split y into XA
    //      (tid<128); W4 staging (tid>=128)
    if (tid < 128) {
        int px = tid;
        float* ysr = YS + px*66;
        const float* ibp = inp + (size_t)b*C*HW + px0 + px;
        float s = 0.f, q = 0.f;
        #pragma unroll 8
        for (int c = 0; c < 64; c += 2) {
            float y0 = ibp[(size_t)c*HW]     + (ysr[c]   + B3B[c])   * BETB[c];
            float y1 = ibp[(size_t)(c+1)*HW] + (ysr[c+1] + B3B[c+1]) * BETB[c+1];
            ysr[c] = y0; ysr[c+1] = y1;
            s += y0 + y1; q += y0*y0 + y1*y1;
            uint32_t h, l; bsplit2(y0, y1, h, l);
            XAh[px*36 + (c>>1)] = h;
            XAl[px*36 + (c>>1)] = l;
        }
        float mu = s * (1.f/64);
        MU[px] = mu; RS[px] = rsqrtf(q*(1.f/64) - mu*mu + EPS);
    } else {
        const uint32_t* wh = (const uint32_t*)g_w4h + b*4096;
        const uint32_t* wl = (const uint32_t*)g_w4l + b*4096;
        for (int i = tid - 128; i < 4096; i += 128) {
            int o = i >> 5, w = i & 31;
            WhU[o*36 + w] = wh[i];
            WlU[o*36 + w] = wl[i];
        }
    }
    __syncthreads();

    // ---- pw4 GEMM (HMMA, ln2-folded weights on raw y): d4[16][4]
    float d4[16][4];
    #pragma unroll
    for (int n = 0; n < 16; n++) { d4[n][0]=0; d4[n][1]=0; d4[n][2]=0; d4[n][3]=0; }
    #pragma unroll
    for (int k = 0; k < 4; k++) {
        int ab = (m0 + g)*36 + k*8 + t;
        uint32_t ah0 = XAh[ab], ah1 = XAh[ab + 288], ah2 = XAh[ab + 4], ah3 = XAh[ab + 292];
        uint32_t al0 = XAl[ab], al1 = XAl[ab + 288], al2 = XAl[ab + 4], al3 = XAl[ab + 292];
        #pragma unroll
        for (int n = 0; n < 16; n++) {
            int bb = (n*8 + g)*36 + k*8 + t;
            uint32_t bh0 = WhU[bb], bh1 = WhU[bb + 4];
            uint32_t bl0 = WlU[bb], bl1 = WlU[bb + 4];
            mma16816(d4[n], ah0, ah1, ah2, ah3, bh0, bh1);
            mma16816(d4[n], al0, al1, al2, al3, bh0, bh1);
            mma16816(d4[n], ah0, ah1, ah2, ah3, bl0, bl1);
        }
    }

    // ---- gate + LN-unfold in registers
    float mu_lo = MU[m0 + g], rs_lo = RS[m0 + g];
    float mu_hi = MU[m0 + g + 8], rs_hi = RS[m0 + g + 8];
    uint32_t gh_lo[8], gl_lo[8], gh_hi[8], gl_hi[8];
    #pragma unroll
    for (int n = 0; n < 8; n++) {
        int oa = n*8 + t*2;
        float s4a0 = S4[oa],    s4a1 = S4[oa+1];
        float s4b0 = S4[oa+64], s4b1 = S4[oa+65];
        float ca0 = C4B[oa],    ca1 = C4B[oa+1];
        float cb0 = C4B[oa+64], cb1 = C4B[oa+65];
        float g00 = (rs_lo*(d4[n][0]   - mu_lo*s4a0) + ca0) * (rs_lo*(d4[n+8][0] - mu_lo*s4b0) + cb0);
        float g01 = (rs_lo*(d4[n][1]   - mu_lo*s4a1) + ca1) * (rs_lo*(d4[n+8][1] - mu_lo*s4b1) + cb1);
        float g10 = (rs_hi*(d4[n][2]   - mu_hi*s4a0) + ca0) * (rs_hi*(d4[n+8][2] - mu_hi*s4b0) + cb0);
        float g11 = (rs_hi*(d4[n][3]   - mu_hi*s4a1) + ca1) * (rs_hi*(d4[n+8][3] - mu_hi*s4b1) + cb1);
        bsplit2(g00, g01, gh_lo[n], gl_lo[n]);
        bsplit2(g10, g11, gh_hi[n], gl_hi[n]);
    }
    __syncthreads();   // pw4 A-reads done

    // ---- store gated tile into XA; stage W5
    #pragma unroll
    for (int n = 0; n < 8; n++) {
        XAh[(m0 + g)*36 + n*4 + t]     = gh_lo[n];
        XAl[(m0 + g)*36 + n*4 + t]     = gl_lo[n];
        XAh[(m0 + g + 8)*36 + n*4 + t] = gh_hi[n];
        XAl[(m0 + g + 8)*36 + n*4 + t] = gl_hi[n];
    }
    {
        const uint32_t* wh = (const uint32_t*)g_w5h + b*2048;
        const uint32_t* wl = (const uint32_t*)g_w5l + b*2048;
        for (int i = tid; i < 2048; i += 256) {
            int o = i >> 5, w = i & 31;
            WhU[o*36 + w] = wh[i];
            WlU[o*36 + w] = wl[i];
        }
    }
    __syncthreads();

    // ---- pw5 GEMM (HMMA): d5[8][4]
    float d5[8][4];
    #pragma unroll
    for (int n = 0; n < 8; n++) { d5[n][0]=0; d5[n][1]=0; d5[n][2]=0; d5[n][3]=0; }
    #pragma unroll
    for (int k = 0; k < 4; k++) {
        int ab = (m0 + g)*36 + k*8 + t;
        uint32_t ah0 = XAh[ab], ah1 = XAh[ab + 288], ah2 = XAh[ab + 4], ah3 = XAh[ab + 292];
        uint32_t al0 = XAl[ab], al1 = XAl[ab + 288], al2 = XAl[ab + 4], al3 = XAl[ab + 292];
        #pragma unroll
        for (int n = 0; n < 8; n++) {
            int bb = (n*8 + g)*36 + k*8 + t;
            uint32_t bh0 = WhU[bb], bh1 = WhU[bb + 4];
            uint32_t bl0 = WlU[bb], bl1 = WlU[bb + 4];
            mma16816(d5[n], ah0, ah1, ah2, ah3, bh0, bh1);
            mma16816(d5[n], al0, al1, al2, al3, bh0, bh1);
            mma16816(d5[n], ah0, ah1, ah2, ah3, bl0, bl1);
        }
    }

    // ---- final: YS <- y + (d5+b5)*gamma (in-place; lane owns its elements)
    #pragma unroll
    for (int n = 0; n < 8; n++) {
        int oa = n*8 + t*2;
        float* yl = &YS[(m0 + g)*66 + oa];
        float* yh = &YS[(m0 + g + 8)*66 + oa];
        float f00 = yl[0] + (d5[n][0] + B5B[oa])   * GAMB[oa];
        float f01 = yl[1] + (d5[n][1] + B5B[oa+1]) * GAMB[oa+1];
        float f10 = yh[0] + (d5[n][2] + B5B[oa])   * GAMB[oa];
        float f11 = yh[1] + (d5[n][3] + B5B[oa+1]) * GAMB[oa+1];
        float2 a; a.x = f00; a.y = f01; *(float2*)yl = a;
        float2 c; c.x = f10; c.y = f11; *(float2*)yh = c;
    }
    __syncthreads();

    // ---- coalesced writeout
    float* ob = out + (size_t)b*C*HW + px0;
    for (int i = tid; i < 8192; i += 256) {
        int o = i >> 7, p = i & 127;
        ob[(size_t)o*HW + p] = YS[p*66 + o];
    }
}

// ---------------- launch ------------------------------------------------------
extern "C" void kernel_launch(void* const* d_in, const int* in_sizes, int n_in,
                              void* d_out, int out_size) {
    const float* inp   = (const float*)d_in[0];
    const float* w1    = (const float*)d_in[1];
    const float* b1    = (const float*)d_in[2];
    const float* w2    = (const float*)d_in[3];
    const float* b2    = (const float*)d_in[4];
    const float* w3    = (const float*)d_in[5];
    const float* b3    = (const float*)d_in[6];
    const float* w4    = (const float*)d_in[7];
    const float* b4    = (const float*)d_in[8];
    const float* w5    = (const float*)d_in[9];
    const float* b5    = (const float*)d_in[10];
    const float* ln1w  = (const float*)d_in[11];
    const float* ln1b  = (const float*)d_in[12];
    const float* ln2w  = (const float*)d_in[13];
    const float* ln2b  = (const float*)d_in[14];
    const float* scaw  = (const float*)d_in[15];
    const float* scab  = (const float*)d_in[16];
    const float* beta  = (const float*)d_in[17];
    const float* gamma = (const float*)d_in[18];
    float* out = (float*)d_out;

    cudaFuncSetAttribute(k1, cudaFuncAttributeMaxDynamicSharedMemorySize, 69120);
    cudaFuncSetAttribute(k2, cudaFuncAttributeMaxDynamicSharedMemorySize, K2_SMEM);

    k_prep<<<4097, 32>>>(w1, w2, w3, w4, w5, ln1w, ln1b, ln2w, ln2b);
    k1 <<<dim3(HW/128, B), 256, 69120>>>(inp, b1);
    kdw<<<dim3(IW/32, IH/32, B*C), 256>>>(b2);
    k2 <<<dim3(HW/128, B), 256, K2_SMEM>>>(inp, b3, b4, b5, beta, gamma, scaw, scab, out);
}

// round 10
// speedup vs baseline: 1.2791x; 1.1647x over previous
#include <cuda_runtime.h>
#include <cuda_bf16.h>
#include <cstdint>
#include <math.h>

#define B   8
#define C   64
#define DW  128
#define IH  256
#define IW  256
#define HW  65536
#define EPS 1e-6f

// ---------- bf16 split helper ----------
__device__ __forceinline__ void bsplit2(float f0, float f1, uint32_t& h, uint32_t& l) {
    __nv_bfloat16 h0 = __float2bfloat16(f0), h1 = __float2bfloat16(f1);
    float r0 = f0 - __bfloat162float(h0), r1 = f1 - __bfloat162float(h1);
    __nv_bfloat16 l0 = __float2bfloat16(r0), l1 = __float2bfloat16(r1);
    h = (uint32_t)__bfloat16_as_ushort(h0) | ((uint32_t)__bfloat16_as_ushort(h1) << 16);
    l = (uint32_t)__bfloat16_as_ushort(l0) | ((uint32_t)__bfloat16_as_ushort(l1) << 16);
}

// ---------- mma.sync m16n8k16 bf16 ----------
__device__ __forceinline__ void mma16816(float* d,
        uint32_t a0, uint32_t a1, uint32_t a2, uint32_t a3,
        uint32_t b0, uint32_t b1) {
    asm volatile("mma.sync.aligned.m16n8k16.row.col.f32.bf16.bf16.f32 "
        "{%0,%1,%2,%3}, {%4,%5,%6,%7}, {%8,%9}, {%0,%1,%2,%3};"
        : "+f"(d[0]), "+f"(d[1]), "+f"(d[2]), "+f"(d[3])
        : "r"(a0), "r"(a1), "r"(a2), "r"(a3), "r"(b0), "r"(b1));
}

// ---------------- device scratch ----------------------------------------------
__device__ unsigned short g_w1h[B*128*64], g_w1l[B*128*64];   // ln1-folded
__device__ float g_s1 [B*DW];
__device__ float g_c1 [B*DW];
__device__ float g_w2 [B*DW*9];
__device__ unsigned short g_w3h[B*64*64], g_w3l[B*64*64];
__device__ unsigned short g_w4h[B*128*64], g_w4l[B*128*64];   // ln2-folded
__device__ float g_s4 [B*DW];
__device__ float g_c4 [B*DW];
__device__ unsigned short g_w5h[B*64*64], g_w5l[B*64*64];
__device__ float g_t1[(size_t)B*DW*HW];
__device__ float g_t2[(size_t)B*C*HW];
__device__ float g_pool[B*C];

// ---------------- prep --------------------------------------------------------
__global__ void k_prep(const float* __restrict__ w1, const float* __restrict__ w2,
                       const float* __restrict__ w3, const float* __restrict__ w4,
                       const float* __restrict__ w5,
                       const float* __restrict__ ln1w, const float* __restrict__ ln1b,
                       const float* __restrict__ ln2w, const float* __restrict__ ln2b) {
    int blk = blockIdx.x, t = threadIdx.x;
    if (blk >= 4096) { for (int i = t; i < B*C; i += 32) g_pool[i] = 0.f; return; }

    if (blk < 1024 || (blk >= 2560 && blk < 3584)) {
        bool is1 = (blk < 1024);
        int r = is1 ? blk : blk - 2560;
        const float* src = (is1 ? w1 : w4) + r*64;
        const float* lw = is1 ? ln1w : ln2w;
        const float* lb = is1 ? ln1b : ln2b;
        unsigned short* dh = (is1 ? g_w1h : g_w4h) + r*64;
        unsigned short* dl = (is1 ? g_w1l : g_w4l) + r*64;
        float sq = 0.f;
        for (int i = t; i < 64; i += 32) { float v = src[i]; sq += v*v; }
        #pragma unroll
        for (int off = 16; off; off >>= 1) sq += __shfl_xor_sync(0xffffffffu, sq, off);
        float rn = 1.0f / sqrtf(sq);
        float s = 0.f, cx = 0.f;
        for (int i = t; i < 64; i += 32) {
            float wn = src[i] * rn;
            float wf = wn * lw[i];
            __nv_bfloat16 h = __float2bfloat16(wf);
            __nv_bfloat16 l = __float2bfloat16(wf - __bfloat162float(h));
            dh[i] = __bfloat16_as_ushort(h);
            dl[i] = __bfloat16_as_ushort(l);
            s += wf; cx += wn * lb[i];
        }
        #pragma unroll
        for (int off = 16; off; off >>= 1) {
            s  += __shfl_xor_sync(0xffffffffu, s,  off);
            cx += __shfl_xor_sync(0xffffffffu, cx, off);
        }
        if (t == 0) {
            if (is1) { g_s1[r] = s; g_c1[r] = cx; }
            else     { g_s4[r] = s; g_c4[r] = cx; }
        }
        return;
    }
    if (blk < 2048) {
        int r = blk - 1024;
        const float* src = w2 + r*9;
        float sq = 0.f;
        for (int i = t; i < 9; i += 32) { float v = src[i]; sq += v*v; }
        #pragma unroll
        for (int off = 16; off; off >>= 1) sq += __shfl_xor_sync(0xffffffffu, sq, off);
        float rn = 1.0f / sqrtf(sq);
        for (int i = t; i < 9; i += 32) g_w2[r*9 + i] = src[i] * rn;
        return;
    }
    bool is3 = (blk < 2560);
    int r = is3 ? (blk - 2048) : (blk - 3584);
    const float* src = (is3 ? w3 : w5) + r*64;
    unsigned short* dh = (is3 ? g_w3h : g_w5h) + r*64;
    unsigned short* dl = (is3 ? g_w3l : g_w5l) + r*64;
    float sq = 0.f;
    for (int i = t; i < 64; i += 32) { float v = src[i]; sq += v*v; }
    #pragma unroll
    for (int off = 16; off; off >>= 1) sq += __shfl_xor_sync(0xffffffffu, sq, off);
    float rn = 1.0f / sqrtf(sq);
    for (int i = t; i < 64; i += 32) {
        float wn = src[i] * rn;
        __nv_bfloat16 h = __float2bfloat16(wn);
        __nv_bfloat16 l = __float2bfloat16(wn - __bfloat162float(h));
        dh[i] = __bfloat16_as_ushort(h);
        dl[i] = __bfloat16_as_ushort(l);
    }
}

// ---------------- K1: HMMA LN1(folded)+pw1, register-resident A ---------------
// smem: WH@0 (128*36 u32 =18432B), WL@18432, S1B@36864(512B), C1B@37376(512B) = 37888
__global__ void __launch_bounds__(256) k1(const float* __restrict__ inp,
                                          const float* __restrict__ b1) {
    extern __shared__ __align__(16) char smem[];
    uint32_t* WH = (uint32_t*)smem;
    uint32_t* WL = (uint32_t*)(smem + 18432);
    float* S1B = (float*)(smem + 36864);
    float* C1B = (float*)(smem + 37376);
    int b = blockIdx.y, px0 = blockIdx.x * 128;
    int tid = threadIdx.x, lane = tid & 31, warp = tid >> 5;
    int g = lane >> 2, t = lane & 3;
    int m0 = warp * 16;
    int r0 = m0 + g, r1 = m0 + g + 8;

    {
        const uint32_t* wh = (const uint32_t*)g_w1h + b*4096;
        const uint32_t* wl = (const uint32_t*)g_w1l + b*4096;
        for (int i = tid; i < 4096; i += 256) {
            int o = i >> 5, w = i & 31;
            WH[o*36 + w] = wh[i];
            WL[o*36 + w] = wl[i];
        }
    }
    if (tid < 128) { S1B[tid] = g_s1[b*DW + tid]; C1B[tid] = g_c1[b*DW + tid] + b1[b*DW + tid]; }
    __syncthreads();

    // A: per-lane LDG of inp, stats on the fly
    const float* ip = inp + (size_t)b*C*HW + px0;
    float xv0[16], xv1[16];
    float s0 = 0.f, q0 = 0.f, s1 = 0.f, q1 = 0.f;
    #pragma unroll
    for (int kk = 0; kk < 4; kk++)
        #pragma unroll
        for (int j = 0; j < 4; j++) {
            int ch = kk*16 + ((j < 2) ? (2*t + j) : (2*t + 8 + (j - 2)));
            float v0 = ip[(size_t)ch*HW + r0];
            float v1 = ip[(size_t)ch*HW + r1];
            xv0[kk*4 + j] = v0; xv1[kk*4 + j] = v1;
            s0 += v0; q0 += v0*v0; s1 += v1; q1 += v1*v1;
        }
    #pragma unroll
    for (int off = 1; off < 4; off <<= 1) {
        s0 += __shfl_xor_sync(0xffffffffu, s0, off);
        q0 += __shfl_xor_sync(0xffffffffu, q0, off);
        s1 += __shfl_xor_sync(0xffffffffu, s1, off);
        q1 += __shfl_xor_sync(0xffffffffu, q1, off);
    }
    float mu0 = s0*(1.f/64), mu1 = s1*(1.f/64);
    float rs0 = rsqrtf(q0*(1.f/64) - mu0*mu0 + EPS);
    float rs1 = rsqrtf(q1*(1.f/64) - mu1*mu1 + EPS);

    uint32_t ah[4][4], al[4][4];
    #pragma unroll
    for (int kk = 0; kk < 4; kk++) {
        bsplit2(xv0[kk*4+0], xv0[kk*4+1], ah[kk][0], al[kk][0]);
        bsplit2(xv1[kk*4+0], xv1[kk*4+1], ah[kk][1], al[kk][1]);
        bsplit2(xv0[kk*4+2], xv0[kk*4+3], ah[kk][2], al[kk][2]);
        bsplit2(xv1[kk*4+2], xv1[kk*4+3], ah[kk][3], al[kk][3]);
    }

    float d[16][4];
    #pragma unroll
    for (int n = 0; n < 16; n++) { d[n][0]=0; d[n][1]=0; d[n][2]=0; d[n][3]=0; }
    #pragma unroll
    for (int kk = 0; kk < 4; kk++)
        #pragma unroll
        for (int n = 0; n < 16; n++) {
            int bb = (n*8 + g)*36 + kk*8 + t;
            uint32_t bh0 = WH[bb], bh1 = WH[bb + 4];
            uint32_t bl0 = WL[bb], bl1 = WL[bb + 4];
            mma16816(d[n], ah[kk][0], ah[kk][1], ah[kk][2], ah[kk][3], bh0, bh1);
            mma16816(d[n], al[kk][0], al[kk][1], al[kk][2], al[kk][3], bh0, bh1);
            mma16816(d[n], ah[kk][0], ah[kk][1], ah[kk][2], ah[kk][3], bl0, bl1);
        }

    float* op = g_t1 + (size_t)b*DW*HW + px0;
    #pragma unroll
    for (int n = 0; n < 16; n++) {
        int oa = n*8 + 2*t;
        float S0 = S1B[oa], Sv1 = S1B[oa+1], Cc0 = C1B[oa], Cc1 = C1B[oa+1];
        op[(size_t)oa*HW + r0]     = rs0*(d[n][0] - mu0*S0)  + Cc0;
        op[(size_t)(oa+1)*HW + r0] = rs0*(d[n][1] - mu0*Sv1) + Cc1;
        op[(size_t)oa*HW + r1]     = rs1*(d[n][2] - mu1*S0)  + Cc0;
        op[(size_t)(oa+1)*HW + r1] = rs1*(d[n][3] - mu1*Sv1) + Cc1;
    }
}

// ---------------- K_dw: depthwise 3x3 + SimpleGate + pool ---------------------
__global__ void __launch_bounds__(256) kdw(const float* __restrict__ b2) {
    int bc = blockIdx.z; int b = bc >> 6; int c = bc & 63;
    __shared__ float s1[34][36];
    __shared__ float s2[34][36];
    __shared__ float wA[9], wB[9], bAB[2], red[8];

    const float* in1 = g_t1 + ((size_t)b*DW + c     ) * HW;
    const float* in2 = g_t1 + ((size_t)b*DW + c + 64) * HW;
    int x0 = blockIdx.x * 32, y0 = blockIdx.y * 32;

    for (int i = threadIdx.x; i < 34*34; i += 256) {
        int ly = i / 34, lx = i % 34;
        int gy = y0 + ly - 1, gx = x0 + lx - 1;
        bool ok = (gy >= 0 && gy < IH && gx >= 0 && gx < IW);
        s1[ly][lx] = ok ? in1[gy*IW + gx] : 0.f;
        s2[ly][lx] = ok ? in2[gy*IW + gx] : 0.f;
    }
    if (threadIdx.x < 9)        wA[threadIdx.x]     = g_w2[((size_t)b*DW + c     )*9 + threadIdx.x];
    else if (threadIdx.x < 18)  wB[threadIdx.x - 9] = g_w2[((size_t)b*DW + c + 64)*9 + threadIdx.x - 9];
    else if (threadIdx.x == 18) bAB[0] = b2[b*DW + c];
    else if (threadIdx.x == 19) bAB[1] = b2[b*DW + c + 64];
    __syncthreads();

    int lx = threadIdx.x & 31, ly0 = (threadIdx.x >> 5) * 4;
    float* obase = g_t2 + ((size_t)b*C + c)*HW;
    float psum = 0.f;
    #pragma unroll
    for (int r = 0; r < 4; r++) {
        int ly = ly0 + r;
        float a = bAB[0], d = bAB[1];
        #pragma unroll
        for (int ky = 0; ky < 3; ky++)
            #pragma unroll
            for (int kx = 0; kx < 3; kx++) {
                a += wA[ky*3 + kx] * s1[ly + ky][lx + kx];
                d += wB[ky*3 + kx] * s2[ly + ky][lx + kx];
            }
        float g = a * d;
        obase[(y0 + ly)*IW + (x0 + lx)] = g;
        psum += g;
    }
    #pragma unroll
    for (int off = 16; off; off >>= 1) psum += __shfl_down_sync(0xffffffffu, psum, off);
    if (lx == 0) red[threadIdx.x >> 5] = psum;
    __syncthreads();
    if (threadIdx.x == 0) {
        float t = 0.f;
        #pragma unroll
        for (int i = 0; i < 8; i++) t += red[i];
        atomicAdd(&g_pool[b*C + c], t);
    }
}

// ---------------- K2: fused HMMA, register-resident A chain -------------------
// smem: WH@0(18432) WL@18432(18432) YS@36864(128*72*4=36864)
// consts@73728: S4(512) C4B(512) B3(256) BET(256) B5(256) GAM(256) SCS(256) PLS(256)
#define KO_WH 0
#define KO_WL 18432
#define KO_YS 36864
#define KO_S4 73728
#define KO_C4 74240
#define KO_B3 74752
#define KO_BT 75008
#define KO_B5 75264
#define KO_GM 75520
#define KO_SC 75776
#define KO_PL 76032
#define K2_SMEM 76288

__global__ void __launch_bounds__(256) k2(const float* __restrict__ inp,
                                          const float* __restrict__ b3,
                                          const float* __restrict__ b4,
                                          const float* __restrict__ b5,
                                          const float* __restrict__ beta,
                                          const float* __restrict__ gamma,
                                          const float* __restrict__ sca_w,
                                          const float* __restrict__ sca_b,
                                          float* __restrict__ out) {
    extern __shared__ __align__(16) char smem[];
    uint32_t* WH = (uint32_t*)(smem + KO_WH);
    uint32_t* WL = (uint32_t*)(smem + KO_WL);
    float* YS  = (float*)(smem + KO_YS);
    float* S4  = (float*)(smem + KO_S4);
    float* C4B = (float*)(smem + KO_C4);
    float* B3B = (float*)(smem + KO_B3);
    float* BETB= (float*)(smem + KO_BT);
    float* B5B = (float*)(smem + KO_B5);
    float* GAMB= (float*)(smem + KO_GM);
    float* SCS = (float*)(smem + KO_SC);
    float* PLS = (float*)(smem + KO_PL);

    int b = blockIdx.y, px0 = blockIdx.x * 128;
    int tid = threadIdx.x, lane = tid & 31, warp = tid >> 5;
    int g = lane >> 2, t = lane & 3;
    int m0 = warp * 16;
    int r0 = m0 + g, r1 = m0 + g + 8;

    // ---- stage W3 + consts
    {
        const uint32_t* wh = (const uint32_t*)g_w3h + b*2048;
        const uint32_t* wl = (const uint32_t*)g_w3l + b*2048;
        for (int i = tid; i < 2048; i += 256) {
            int o = i >> 5, w = i & 31;
            WH[o*36 + w] = wh[i];
            WL[o*36 + w] = wl[i];
        }
    }
    if (tid < 64) {
        B3B[tid] = b3[b*64 + tid]; BETB[tid] = beta[tid];
        B5B[tid] = b5[b*64 + tid]; GAMB[tid] = gamma[tid];
        PLS[tid] = g_pool[b*64 + tid] * (1.f/(float)HW);
    } else if (tid < 192) {
        int u = tid - 64;
        S4[u] = g_s4[b*128 + u];
        C4B[u] = g_c4[b*128 + u] + b4[b*128 + u];
    }
    __syncthreads();
    if (tid < 64) {
        float acc = sca_b[tid];
        #pragma unroll 8
        for (int cc = 0; cc < 64; cc++) acc += sca_w[tid*64 + cc] * PLS[cc];
        SCS[tid] = acc;
    }
    __syncthreads();

    // ---- A-frags of X = sca*t2 via per-lane LDG
    const float* t2b = g_t2 + (size_t)b*C*HW + px0;
    uint32_t xh[4][4], xl[4][4];
    #pragma unroll
    for (int kk = 0; kk < 4; kk++) {
        float v0[4], v1[4];
        #pragma unroll
        for (int j = 0; j < 4; j++) {
            int ch = kk*16 + ((j < 2) ? (2*t + j) : (2*t + 8 + (j - 2)));
            float sc = SCS[ch];
            v0[j] = t2b[(size_t)ch*HW + r0] * sc;
            v1[j] = t2b[(size_t)ch*HW + r1] * sc;
        }
        bsplit2(v0[0], v0[1], xh[kk][0], xl[kk][0]);
        bsplit2(v1[0], v1[1], xh[kk][1], xl[kk][1]);
        bsplit2(v0[2], v0[3], xh[kk][2], xl[kk][2]);
        bsplit2(v1[2], v1[3], xh[kk][3], xl[kk][3]);
    }

    // ---- pw3 GEMM
    float d3[8][4];
    #pragma unroll
    for (int n = 0; n < 8; n++) { d3[n][0]=0; d3[n][1]=0; d3[n][2]=0; d3[n][3]=0; }
    #pragma unroll
    for (int kk = 0; kk < 4; kk++)
        #pragma unroll
        for (int n = 0; n < 8; n++) {
            int bb = (n*8 + g)*36 + kk*8 + t;
            uint32_t bh0 = WH[bb], bh1 = WH[bb + 4];
            uint32_t bl0 = WL[bb], bl1 = WL[bb + 4];
            mma16816(d3[n], xh[kk][0], xh[kk][1], xh[kk][2], xh[kk][3], bh0, bh1);
            mma16816(d3[n], xl[kk][0], xl[kk][1], xl[kk][2], xl[kk][3], bh0, bh1);
            mma16816(d3[n], xh[kk][0], xh[kk][1], xh[kk][2], xh[kk][3], bl0, bl1);
        }

    // ---- y = inp + (d3+b3)*beta; stats; y->YS; y-frags
    const float* ib = inp + (size_t)b*C*HW + px0;
    float y0v[16], y1v[16];
    float s0 = 0.f, q0 = 0.f, s1 = 0.f, q1 = 0.f;
    #pragma unroll
    for (int n = 0; n < 8; n++) {
        int oa = n*8 + 2*t;
        float bb0 = B3B[oa], bb1 = B3B[oa+1], bt0 = BETB[oa], bt1 = BETB[oa+1];
        float a0 = ib[(size_t)oa*HW + r0]     + (d3[n][0] + bb0) * bt0;
        float a1 = ib[(size_t)(oa+1)*HW + r0] + (d3[n][1] + bb1) * bt1;
        float a2 = ib[(size_t)oa*HW + r1]     + (d3[n][2] + bb0) * bt0;
        float a3 = ib[(size_t)(oa+1)*HW + r1] + (d3[n][3] + bb1) * bt1;
        y0v[n*2] = a0; y0v[n*2+1] = a1; y1v[n*2] = a2; y1v[n*2+1] = a3;
        s0 += a0 + a1; q0 += a0*a0 + a1*a1;
        s1 += a2 + a3; q1 += a2*a2 + a3*a3;
        float2 p0; p0.x = a0; p0.y = a1;
        float2 p1; p1.x = a2; p1.y = a3;
        *(float2*)&YS[r0*72 + oa] = p0;
        *(float2*)&YS[r1*72 + oa] = p1;
    }
    #pragma unroll
    for (int off = 1; off < 4; off <<= 1) {
        s0 += __shfl_xor_sync(0xffffffffu, s0, off);
        q0 += __shfl_xor_sync(0xffffffffu, q0, off);
        s1 += __shfl_xor_sync(0xffffffffu, s1, off);
        q1 += __shfl_xor_sync(0xffffffffu, q1, off);
    }
    float mu0 = s0*(1.f/64), mu1 = s1*(1.f/64);
    float rs0 = rsqrtf(q0*(1.f/64) - mu0*mu0 + EPS);
    float rs1 = rsqrtf(q1*(1.f/64) - mu1*mu1 + EPS);

    uint32_t yh[4][4], yl[4][4];   // A-frags for pw4 (D->A mapping)
    #pragma unroll
    for (int kk = 0; kk < 4; kk++) {
        bsplit2(y0v[4*kk],   y0v[4*kk+1], yh[kk][0], yl[kk][0]);
        bsplit2(y1v[4*kk],   y1v[4*kk+1], yh[kk][1], yl[kk][1]);
        bsplit2(y0v[4*kk+2], y0v[4*kk+3], yh[kk][2], yl[kk][2]);
        bsplit2(y1v[4*kk+2], y1v[4*kk+3], yh[kk][3], yl[kk][3]);
    }

    __syncthreads();   // pw3 W-reads done
    {
        const uint32_t* wh = (const uint32_t*)g_w4h + b*4096;
        const uint32_t* wl = (const uint32_t*)g_w4l + b*4096;
        for (int i = tid; i < 4096; i += 256) {
            int o = i >> 5, w = i & 31;
            WH[o*36 + w] = wh[i];
            WL[o*36 + w] = wl[i];
        }
    }
    __syncthreads();

    // ---- pw4 GEMM (ln2 folded)
    float d4[16][4];
    #pragma unroll
    for (int n = 0; n < 16; n++) { d4[n][0]=0; d4[n][1]=0; d4[n][2]=0; d4[n][3]=0; }
    #pragma unroll
    for (int kk = 0; kk < 4; kk++)
        #pragma unroll
        for (int n = 0; n < 16; n++) {
            int bb = (n*8 + g)*36 + kk*8 + t;
            uint32_t bh0 = WH[bb], bh1 = WH[bb + 4];
            uint32_t bl0 = WL[bb], bl1 = WL[bb + 4];
            mma16816(d4[n], yh[kk][0], yh[kk][1], yh[kk][2], yh[kk][3], bh0, bh1);
            mma16816(d4[n], yl[kk][0], yl[kk][1], yl[kk][2], yl[kk][3], bh0, bh1);
            mma16816(d4[n], yh[kk][0], yh[kk][1], yh[kk][2], yh[kk][3], bl0, bl1);
        }

    // ---- gate + LN-unfold in registers -> pw5 A-frags
    float g0v[16], g1v[16];
    #pragma unroll
    for (int n = 0; n < 8; n++) {
        int oa = n*8 + 2*t;
        float s4a0 = S4[oa],    s4a1 = S4[oa+1];
        float s4b0 = S4[oa+64], s4b1 = S4[oa+65];
        float ca0 = C4B[oa],    ca1 = C4B[oa+1];
        float cb0 = C4B[oa+64], cb1 = C4B[oa+65];
        g0v[n*2]   = (rs0*(d4[n][0] - mu0*s4a0) + ca0) * (rs0*(d4[n+8][0] - mu0*s4b0) + cb0);
        g0v[n*2+1] = (rs0*(d4[n][1] - mu0*s4a1) + ca1) * (rs0*(d4[n+8][1] - mu0*s4b1) + cb1);
        g1v[n*2]   = (rs1*(d4[n][2] - mu1*s4a0) + ca0) * (rs1*(d4[n+8][2] - mu1*s4b0) + cb0);
        g1v[n*2+1] = (rs1*(d4[n][3] - mu1*s4a1) + ca1) * (rs1*(d4[n+8][3] - mu1*s4b1) + cb1);
    }
    uint32_t gh[4][4], gl[4][4];
    #pragma unroll
    for (int kk = 0; kk < 4; kk++) {
        bsplit2(g0v[4*kk],   g0v[4*kk+1], gh[kk][0], gl[kk][0]);
        bsplit2(g1v[4*kk],   g1v[4*kk+1], gh[kk][1], gl[kk][1]);
        bsplit2(g0v[4*kk+2], g0v[4*kk+3], gh[kk][2], gl[kk][2]);
        bsplit2(g1v[4*kk+2], g1v[4*kk+3], gh[kk][3], gl[kk][3]);
    }

    __syncthreads();   // pw4 W-reads done
    {
        const uint32_t* wh = (const uint32_t*)g_w5h + b*2048;
        const uint32_t* wl = (const uint32_t*)g_w5l + b*2048;
        for (int i = tid; i < 2048; i += 256) {
            int o = i >> 5, w = i & 31;
            WH[o*36 + w] = wh[i];
            WL[o*36 + w] = wl[i];
        }
    }
    __syncthreads();

    // ---- pw5 GEMM
    float d5[8][4];
    #pragma unroll
    for (int n = 0; n < 8; n++) { d5[n][0]=0; d5[n][1]=0; d5[n][2]=0; d5[n][3]=0; }
    #pragma unroll
    for (int kk = 0; kk < 4; kk++)
        #pragma unroll
        for (int n = 0; n < 8; n++) {
            int bb = (n*8 + g)*36 + kk*8 + t;
            uint32_t bh0 = WH[bb], bh1 = WH[bb + 4];
            uint32_t bl0 = WL[bb], bl1 = WL[bb + 4];
            mma16816(d5[n], gh[kk][0], gh[kk][1], gh[kk][2], gh[kk][3], bh0, bh1);
            mma16816(d5[n], gl[kk][0], gl[kk][1], gl[kk][2], gl[kk][3], bh0, bh1);
            mma16816(d5[n], gh[kk][0], gh[kk][1], gh[kk][2], gh[kk][3], bl0, bl1);
        }

    // ---- final: out = y + (d5+b5)*gamma  (y from YS, lane-private)
    float* ob = out + (size_t)b*C*HW + px0;
    #pragma unroll
    for (int n = 0; n < 8; n++) {
        int oa = n*8 + 2*t;
        float bp0 = B5B[oa], bp1 = B5B[oa+1], gp0 = GAMB[oa], gp1 = GAMB[oa+1];
        float2 p0 = *(float2*)&YS[r0*72 + oa];
        float2 p1 = *(float2*)&YS[r1*72 + oa];
        ob[(size_t)oa*HW + r0]     = p0.x + (d5[n][0] + bp0) * gp0;
        ob[(size_t)(oa+1)*HW + r0] = p0.y + (d5[n][1] + bp1) * gp1;
        ob[(size_t)oa*HW + r1]     = p1.x + (d5[n][2] + bp0) * gp0;
        ob[(size_t)(oa+1)*HW + r1] = p1.y + (d5[n][3] + bp1) * gp1;
    }
}

// ---------------- launch ------------------------------------------------------
extern "C" void kernel_launch(void* const* d_in, const int* in_sizes, int n_in,
                              void* d_out, int out_size) {
    const float* inp   = (const float*)d_in[0];
    const float* w1    = (const float*)d_in[1];
    const float* b1    = (const float*)d_in[2];
    const float* w2    = (const float*)d_in[3];
    const float* b2    = (const float*)d_in[4];
    const float* w3    = (const float*)d_in[5];
    const float* b3    = (const float*)d_in[6];
    const float* w4    = (const float*)d_in[7];
    const float* b4    = (const float*)d_in[8];
    const float* w5    = (const float*)d_in[9];
    const float* b5    = (const float*)d_in[10];
    const float* ln1w  = (const float*)d_in[11];
    const float* ln1b  = (const float*)d_in[12];
    const float* ln2w  = (const float*)d_in[13];
    const float* ln2b  = (const float*)d_in[14];
    const float* scaw  = (const float*)d_in[15];
    const float* scab  = (const float*)d_in[16];
    const float* beta  = (const float*)d_in[17];
    const float* gamma = (const float*)d_in[18];
    float* out = (float*)d_out;

    cudaFuncSetAttribute(k1, cudaFuncAttributeMaxDynamicSharedMemorySize, 37888);
    cudaFuncSetAttribute(k2, cudaFuncAttributeMaxDynamicSharedMemorySize, K2_SMEM);

    k_prep<<<4097, 32>>>(w1, w2, w3, w4, w5, ln1w, ln1b, ln2w, ln2b);
    k1 <<<dim3(HW/128, B), 256, 37888>>>(inp, b1);
    kdw<<<dim3(IW/32, IH/32, B*C), 256>>>(b2);
    k2 <<<dim3(HW/128, B), 256, K2_SMEM>>>(inp, b3, b4, b5, beta, gamma, scaw, scab, out);
}

// round 11
// speedup vs baseline: 1.3903x; 1.0869x over previous
#include <cuda_runtime.h>
#include <cuda_bf16.h>
#include <cstdint>
#include <math.h>

#define B   8
#define C   64
#define DW  128
#define IH  256
#define IW  256
#define HW  65536
#define EPS 1e-6f

// ---------- bf16 split helper ----------
__device__ __forceinline__ void bsplit2(float f0, float f1, uint32_t& h, uint32_t& l) {
    __nv_bfloat16 h0 = __float2bfloat16(f0), h1 = __float2bfloat16(f1);
    float r0 = f0 - __bfloat162float(h0), r1 = f1 - __bfloat162float(h1);
    __nv_bfloat16 l0 = __float2bfloat16(r0), l1 = __float2bfloat16(r1);
    h = (uint32_t)__bfloat16_as_ushort(h0) | ((uint32_t)__bfloat16_as_ushort(h1) << 16);
    l = (uint32_t)__bfloat16_as_ushort(l0) | ((uint32_t)__bfloat16_as_ushort(l1) << 16);
}
__device__ __forceinline__ uint32_t bhi2(float f0, float f1) {
    __nv_bfloat16 h0 = __float2bfloat16(f0), h1 = __float2bfloat16(f1);
    return (uint32_t)__bfloat16_as_ushort(h0) | ((uint32_t)__bfloat16_as_ushort(h1) << 16);
}

// ---------- mma.sync m16n8k16 bf16 ----------
__device__ __forceinline__ void mma16816(float* d,
        uint32_t a0, uint32_t a1, uint32_t a2, uint32_t a3,
        uint32_t b0, uint32_t b1) {
    asm volatile("mma.sync.aligned.m16n8k16.row.col.f32.bf16.bf16.f32 "
        "{%0,%1,%2,%3}, {%4,%5,%6,%7}, {%8,%9}, {%0,%1,%2,%3};"
        : "+f"(d[0]), "+f"(d[1]), "+f"(d[2]), "+f"(d[3])
        : "r"(a0), "r"(a1), "r"(a2), "r"(a3), "r"(b0), "r"(b1));
}

// ---------- cp.async ----------
__device__ __forceinline__ uint32_t smem_u32(const void* p) {
    uint32_t a;
    asm("{ .reg .u64 t; cvta.to.shared.u64 t, %1; cvt.u32.u64 %0, t; }" : "=r"(a) : "l"(p));
    return a;
}
__device__ __forceinline__ void cpasync16(uint32_t s, const void* g) {
    asm volatile("cp.async.ca.shared.global [%0], [%1], 16;" :: "r"(s), "l"(g) : "memory");
}
#define CP_COMMIT() asm volatile("cp.async.commit_group;" ::: "memory")
#define CP_WAIT(n)  asm volatile("cp.async.wait_group %0;" :: "n"(n) : "memory")

// ---------------- device scratch (frag-ordered weights) -----------------------
// frag layout: [(n*4 + kk)*32 + lane] -> uint2{b0,b1}
__device__ __align__(16) uint2 g_w1f_h[B*2048], g_w1f_l[B*2048];   // 16 n-tiles
__device__ float g_s1 [B*DW];
__device__ float g_c1 [B*DW];
__device__ float g_w2 [B*DW*9];
__device__ __align__(16) uint2 g_w3f_h[B*1024], g_w3f_l[B*1024];   // 8 n-tiles
__device__ __align__(16) uint2 g_w4f_h[B*2048], g_w4f_l[B*2048];   // 16 n-tiles, ln2-folded
__device__ float g_s4 [B*DW];
__device__ float g_c4 [B*DW];
__device__ __align__(16) uint2 g_w5f_h[B*1024], g_w5f_l[B*1024];
__device__ float g_t1[(size_t)B*DW*HW];
__device__ float g_t2[(size_t)B*C*HW];
__device__ float g_pool[B*C];

// ---------------- prep --------------------------------------------------------
__global__ void k_prep(const float* __restrict__ w1, const float* __restrict__ w2,
                       const float* __restrict__ w3, const float* __restrict__ w4,
                       const float* __restrict__ w5,
                       const float* __restrict__ ln1w, const float* __restrict__ ln1b,
                       const float* __restrict__ ln2w, const float* __restrict__ ln2b) {
    int blk = blockIdx.x, t = threadIdx.x;
    if (blk >= 4096) { for (int i = t; i < B*C; i += 32) g_pool[i] = 0.f; return; }

    if (blk < 1024 || (blk >= 2560 && blk < 3584)) {
        // w1 / w4: normalize, fold LN weight, frag-order bf16-split store + S,C sums
        bool is1 = (blk < 1024);
        int r = is1 ? blk : blk - 2560;           // row index (b*128 + o)
        const float* src = (is1 ? w1 : w4) + r*64;
        const float* lw = is1 ? ln1w : ln2w;
        const float* lb = is1 ? ln1b : ln2b;
        int b = r >> 7, o = r & 127;
        int n = o >> 3, g = o & 7;
        float sq = 0.f;
        for (int i = t; i < 64; i += 32) { float v = src[i]; sq += v*v; }
        #pragma unroll
        for (int off = 16; off; off >>= 1) sq += __shfl_xor_sync(0xffffffffu, sq, off);
        float rn = 1.0f / sqrtf(sq);
        float s = 0.f, cx = 0.f;
        for (int i = t; i < 64; i += 32) {
            float wn = src[i] * rn;
            s += wn * lw[i]; cx += wn * lb[i];
        }
        #pragma unroll
        for (int off = 16; off; off >>= 1) {
            s  += __shfl_xor_sync(0xffffffffu, s,  off);
            cx += __shfl_xor_sync(0xffffffffu, cx, off);
        }
        if (t == 0) {
            if (is1) { g_s1[r] = s; g_c1[r] = cx; }
            else     { g_s4[r] = s; g_c4[r] = cx; }
        }
        if (t < 16) {
            int kk = t >> 2, tt = t & 3;
            int k0 = kk*16 + 2*tt;
            float f0 = src[k0]   * rn * lw[k0];
            float f1 = src[k0+1] * rn * lw[k0+1];
            float f2 = src[k0+8] * rn * lw[k0+8];
            float f3 = src[k0+9] * rn * lw[k0+9];
            uint32_t h0, l0, h1, l1;
            bsplit2(f0, f1, h0, l0);
            bsplit2(f2, f3, h1, l1);
            int idx = b*2048 + (n*4 + kk)*32 + g*4 + tt;
            uint2 vh; vh.x = h0; vh.y = h1;
            uint2 vl; vl.x = l0; vl.y = l1;
            if (is1) { g_w1f_h[idx] = vh; g_w1f_l[idx] = vl; }
            else     { g_w4f_h[idx] = vh; g_w4f_l[idx] = vl; }
        }
        return;
    }
    if (blk < 2048) {
        int r = blk - 1024;
        const float* src = w2 + r*9;
        float sq = 0.f;
        for (int i = t; i < 9; i += 32) { float v = src[i]; sq += v*v; }
        #pragma unroll
        for (int off = 16; off; off >>= 1) sq += __shfl_xor_sync(0xffffffffu, sq, off);
        float rn = 1.0f / sqrtf(sq);
        for (int i = t; i < 9; i += 32) g_w2[r*9 + i] = src[i] * rn;
        return;
    }
    // w3 / w5: normalize, frag-order bf16-split store
    bool is3 = (blk < 2560);
    int r = is3 ? (blk - 2048) : (blk - 3584);    // b*64 + o
    const float* src = (is3 ? w3 : w5) + r*64;
    int b = r >> 6, o = r & 63;
    int n = o >> 3, g = o & 7;
    float sq = 0.f;
    for (int i = t; i < 64; i += 32) { float v = src[i]; sq += v*v; }
    #pragma unroll
    for (int off = 16; off; off >>= 1) sq += __shfl_xor_sync(0xffffffffu, sq, off);
    float rn = 1.0f / sqrtf(sq);
    if (t < 16) {
        int kk = t >> 2, tt = t & 3;
        int k0 = kk*16 + 2*tt;
        uint32_t h0, l0, h1, l1;
        bsplit2(src[k0]*rn,   src[k0+1]*rn, h0, l0);
        bsplit2(src[k0+8]*rn, src[k0+9]*rn, h1, l1);
        int idx = b*1024 + (n*4 + kk)*32 + g*4 + tt;
        uint2 vh; vh.x = h0; vh.y = h1;
        uint2 vl; vl.x = l0; vl.y = l1;
        if (is3) { g_w3f_h[idx] = vh; g_w3f_l[idx] = vl; }
        else     { g_w5f_h[idx] = vh; g_w5f_l[idx] = vl; }
    }
}

// ---------------- K1: HMMA LN1(folded)+pw1 ------------------------------------
// smem: W1H@0(16384) W1L@16384(16384) S1B@32768(512) C1B@33280(512) = 33792
__global__ void __launch_bounds__(256) k1(const float* __restrict__ inp,
                                          const float* __restrict__ b1) {
    extern __shared__ __align__(16) char smem[];
    uint2* W1H = (uint2*)smem;
    uint2* W1L = (uint2*)(smem + 16384);
    float* S1B = (float*)(smem + 32768);
    float* C1B = (float*)(smem + 33280);
    int b = blockIdx.y, px0 = blockIdx.x * 128;
    int tid = threadIdx.x, lane = tid & 31, warp = tid >> 5;
    int g = lane >> 2, t = lane & 3;
    int m0 = warp * 16;
    int r0 = m0 + g, r1 = m0 + g + 8;

    // prefetch weights (overlaps with A-frag LDG + stats)
    {
        uint32_t sh = smem_u32(W1H), sl = smem_u32(W1L);
        const char* gh = (const char*)(g_w1f_h + b*2048);
        const char* gl = (const char*)(g_w1f_l + b*2048);
        for (int i = tid; i < 1024; i += 256) {
            cpasync16(sh + i*16, gh + i*16);
            cpasync16(sl + i*16, gl + i*16);
        }
        CP_COMMIT();
    }
    if (tid < 128) { S1B[tid] = g_s1[b*DW + tid]; C1B[tid] = g_c1[b*DW + tid] + b1[b*DW + tid]; }

    // A: per-lane LDG of inp, stats on the fly
    const float* ip = inp + (size_t)b*C*HW + px0;
    float xv0[16], xv1[16];
    float s0 = 0.f, q0 = 0.f, s1 = 0.f, q1 = 0.f;
    #pragma unroll
    for (int kk = 0; kk < 4; kk++)
        #pragma unroll
        for (int j = 0; j < 4; j++) {
            int ch = kk*16 + ((j < 2) ? (2*t + j) : (2*t + 8 + (j - 2)));
            float v0 = ip[(size_t)ch*HW + r0];
            float v1 = ip[(size_t)ch*HW + r1];
            xv0[kk*4 + j] = v0; xv1[kk*4 + j] = v1;
            s0 += v0; q0 += v0*v0; s1 += v1; q1 += v1*v1;
        }
    #pragma unroll
    for (int off = 1; off < 4; off <<= 1) {
        s0 += __shfl_xor_sync(0xffffffffu, s0, off);
        q0 += __shfl_xor_sync(0xffffffffu, q0, off);
        s1 += __shfl_xor_sync(0xffffffffu, s1, off);
        q1 += __shfl_xor_sync(0xffffffffu, q1, off);
    }
    float mu0 = s0*(1.f/64), mu1 = s1*(1.f/64);
    float rs0 = rsqrtf(q0*(1.f/64) - mu0*mu0 + EPS);
    float rs1 = rsqrtf(q1*(1.f/64) - mu1*mu1 + EPS);

    uint32_t ah[4][4], al[4][4];
    #pragma unroll
    for (int kk = 0; kk < 4; kk++) {
        bsplit2(xv0[kk*4+0], xv0[kk*4+1], ah[kk][0], al[kk][0]);
        bsplit2(xv1[kk*4+0], xv1[kk*4+1], ah[kk][1], al[kk][1]);
        bsplit2(xv0[kk*4+2], xv0[kk*4+3], ah[kk][2], al[kk][2]);
        bsplit2(xv1[kk*4+2], xv1[kk*4+3], ah[kk][3], al[kk][3]);
    }

    CP_WAIT(0);
    __syncthreads();

    float d[16][4];
    #pragma unroll
    for (int n = 0; n < 16; n++) { d[n][0]=0; d[n][1]=0; d[n][2]=0; d[n][3]=0; }
    #pragma unroll
    for (int kk = 0; kk < 4; kk++)
        #pragma unroll
        for (int n = 0; n < 16; n++) {
            int bb = (n*4 + kk)*32 + lane;
            uint2 bh = W1H[bb];
            uint2 bl = W1L[bb];
            mma16816(d[n], ah[kk][0], ah[kk][1], ah[kk][2], ah[kk][3], bh.x, bh.y);
            mma16816(d[n], al[kk][0], al[kk][1], al[kk][2], al[kk][3], bh.x, bh.y);
            mma16816(d[n], ah[kk][0], ah[kk][1], ah[kk][2], ah[kk][3], bl.x, bl.y);
        }

    float* op = g_t1 + (size_t)b*DW*HW + px0;
    #pragma unroll
    for (int n = 0; n < 16; n++) {
        int oa = n*8 + 2*t;
        float S0 = S1B[oa], Sv1 = S1B[oa+1], Cc0 = C1B[oa], Cc1 = C1B[oa+1];
        op[(size_t)oa*HW + r0]     = rs0*(d[n][0] - mu0*S0)  + Cc0;
        op[(size_t)(oa+1)*HW + r0] = rs0*(d[n][1] - mu0*Sv1) + Cc1;
        op[(size_t)oa*HW + r1]     = rs1*(d[n][2] - mu1*S0)  + Cc0;
        op[(size_t)(oa+1)*HW + r1] = rs1*(d[n][3] - mu1*Sv1) + Cc1;
    }
}

// ---------------- K_dw: depthwise 3x3 + SimpleGate + pool ---------------------
__global__ void __launch_bounds__(256) kdw(const float* __restrict__ b2) {
    int bc = blockIdx.z; int b = bc >> 6; int c = bc & 63;
    __shared__ float s1[34][36];
    __shared__ float s2[34][36];
    __shared__ float wA[9], wB[9], bAB[2], red[8];

    const float* in1 = g_t1 + ((size_t)b*DW + c     ) * HW;
    const float* in2 = g_t1 + ((size_t)b*DW + c + 64) * HW;
    int x0 = blockIdx.x * 32, y0 = blockIdx.y * 32;

    for (int i = threadIdx.x; i < 34*34; i += 256) {
        int ly = i / 34, lx = i % 34;
        int gy = y0 + ly - 1, gx = x0 + lx - 1;
        bool ok = (gy >= 0 && gy < IH && gx >= 0 && gx < IW);
        s1[ly][lx] = ok ? in1[gy*IW + gx] : 0.f;
        s2[ly][lx] = ok ? in2[gy*IW + gx] : 0.f;
    }
    if (threadIdx.x < 9)        wA[threadIdx.x]     = g_w2[((size_t)b*DW + c     )*9 + threadIdx.x];
    else if (threadIdx.x < 18)  wB[threadIdx.x - 9] = g_w2[((size_t)b*DW + c + 64)*9 + threadIdx.x - 9];
    else if (threadIdx.x == 18) bAB[0] = b2[b*DW + c];
    else if (threadIdx.x == 19) bAB[1] = b2[b*DW + c + 64];
    __syncthreads();

    int lx = threadIdx.x & 31, ly0 = (threadIdx.x >> 5) * 4;
    float* obase = g_t2 + ((size_t)b*C + c)*HW;
    float psum = 0.f;
    #pragma unroll
    for (int r = 0; r < 4; r++) {
        int ly = ly0 + r;
        float a = bAB[0], d = bAB[1];
        #pragma unroll
        for (int ky = 0; ky < 3; ky++)
            #pragma unroll
            for (int kx = 0; kx < 3; kx++) {
                a += wA[ky*3 + kx] * s1[ly + ky][lx + kx];
                d += wB[ky*3 + kx] * s2[ly + ky][lx + kx];
            }
        float g = a * d;
        obase[(y0 + ly)*IW + (x0 + lx)] = g;
        psum += g;
    }
    #pragma unroll
    for (int off = 16; off; off >>= 1) psum += __shfl_down_sync(0xffffffffu, psum, off);
    if (lx == 0) red[threadIdx.x >> 5] = psum;
    __syncthreads();
    if (threadIdx.x == 0) {
        float t = 0.f;
        #pragma unroll
        for (int i = 0; i < 8; i++) t += red[i];
        atomicAdd(&g_pool[b*C + c], t);
    }
}

// ---------------- K2: fused HMMA, frag-ordered weights, cp.async --------------
// smem: W3H@0(8192) W3L@8192 W4H@16384(16384) W4L@32768 W5H@49152(8192) W5L@57344
//       YS@65536(36864)  consts@102400: S4(512) C4(512) B3(256) BT(256) B5(256)
//       GM(256) SC(256) PL(256)  total 104960
#define KO_W3H 0
#define KO_W3L 8192
#define KO_W4H 16384
#define KO_W4L 32768
#define KO_W5H 49152
#define KO_W5L 57344
#define KO_YS  65536
#define KO_S4  102400
#define KO_C4  102912
#define KO_B3  103424
#define KO_BT  103680
#define KO_B5  103936
#define KO_GM  104192
#define KO_SC  104448
#define KO_PL  104704
#define K2_SMEM 104960

__global__ void __launch_bounds__(256) k2(const float* __restrict__ inp,
                                          const float* __restrict__ b3,
                                          const float* __restrict__ b4,
                                          const float* __restrict__ b5,
                                          const float* __restrict__ beta,
                                          const float* __restrict__ gamma,
                                          const float* __restrict__ sca_w,
                                          const float* __restrict__ sca_b,
                                          float* __restrict__ out) {
    extern __shared__ __align__(16) char smem[];
    uint2* W3H = (uint2*)(smem + KO_W3H);
    uint2* W3L = (uint2*)(smem + KO_W3L);
    uint2* W4H = (uint2*)(smem + KO_W4H);
    uint2* W4L = (uint2*)(smem + KO_W4L);
    uint2* W5H = (uint2*)(smem + KO_W5H);
    uint2* W5L = (uint2*)(smem + KO_W5L);
    float* YS  = (float*)(smem + KO_YS);
    float* S4  = (float*)(smem + KO_S4);
    float* C4B = (float*)(smem + KO_C4);
    float* B3B = (float*)(smem + KO_B3);
    float* BETB= (float*)(smem + KO_BT);
    float* B5B = (float*)(smem + KO_B5);
    float* GAMB= (float*)(smem + KO_GM);
    float* SCS = (float*)(smem + KO_SC);
    float* PLS = (float*)(smem + KO_PL);

    int b = blockIdx.y, px0 = blockIdx.x * 128;
    int tid = threadIdx.x, lane = tid & 31, warp = tid >> 5;
    int g = lane >> 2, t = lane & 3;
    int m0 = warp * 16;
    int r0 = m0 + g, r1 = m0 + g + 8;

    // ---- prefetch: W3 (group 0), W4+W5 (group 1)
    {
        uint32_t s3h = smem_u32(W3H), s3l = smem_u32(W3L);
        const char* g3h = (const char*)(g_w3f_h + b*1024);
        const char* g3l = (const char*)(g_w3f_l + b*1024);
        for (int i = tid; i < 512; i += 256) {
            cpasync16(s3h + i*16, g3h + i*16);
            cpasync16(s3l + i*16, g3l + i*16);
        }
        CP_COMMIT();
        uint32_t s4h = smem_u32(W4H), s4l = smem_u32(W4L);
        const char* g4h = (const char*)(g_w4f_h + b*2048);
        const char* g4l = (const char*)(g_w4f_l + b*2048);
        for (int i = tid; i < 1024; i += 256) {
            cpasync16(s4h + i*16, g4h + i*16);
            cpasync16(s4l + i*16, g4l + i*16);
        }
        uint32_t s5h = smem_u32(W5H), s5l = smem_u32(W5L);
        const char* g5h = (const char*)(g_w5f_h + b*1024);
        const char* g5l = (const char*)(g_w5f_l + b*1024);
        for (int i = tid; i < 512; i += 256) {
            cpasync16(s5h + i*16, g5h + i*16);
            cpasync16(s5l + i*16, g5l + i*16);
        }
        CP_COMMIT();
    }
    if (tid < 64) {
        B3B[tid] = b3[b*64 + tid]; BETB[tid] = beta[tid];
        B5B[tid] = b5[b*64 + tid]; GAMB[tid] = gamma[tid];
        PLS[tid] = g_pool[b*64 + tid] * (1.f/(float)HW);
    } else if (tid < 192) {
        int u = tid - 64;
        S4[u] = g_s4[b*128 + u];
        C4B[u] = g_c4[b*128 + u] + b4[b*128 + u];
    }
    CP_WAIT(1);         // W3 complete
    __syncthreads();    // consts + W3 visible
    if (tid < 64) {
        float acc = sca_b[tid];
        #pragma unroll 8
        for (int cc = 0; cc < 64; cc++) acc += sca_w[tid*64 + cc] * PLS[cc];
        SCS[tid] = acc;
    }
    __syncthreads();

    // ---- A-frags of X = sca*t2 via per-lane LDG
    const float* t2b = g_t2 + (size_t)b*C*HW + px0;
    uint32_t xh[4][4], xl[4][4];
    #pragma unroll
    for (int kk = 0; kk < 4; kk++) {
        float v0[4], v1[4];
        #pragma unroll
        for (int j = 0; j < 4; j++) {
            int ch = kk*16 + ((j < 2) ? (2*t + j) : (2*t + 8 + (j - 2)));
            float sc = SCS[ch];
            v0[j] = t2b[(size_t)ch*HW + r0] * sc;
            v1[j] = t2b[(size_t)ch*HW + r1] * sc;
        }
        bsplit2(v0[0], v0[1], xh[kk][0], xl[kk][0]);
        bsplit2(v1[0], v1[1], xh[kk][1], xl[kk][1]);
        bsplit2(v0[2], v0[3], xh[kk][2], xl[kk][2]);
        bsplit2(v1[2], v1[3], xh[kk][3], xl[kk][3]);
    }

    // ---- pw3 GEMM
    float d3[8][4];
    #pragma unroll
    for (int n = 0; n < 8; n++) { d3[n][0]=0; d3[n][1]=0; d3[n][2]=0; d3[n][3]=0; }
    #pragma unroll
    for (int kk = 0; kk < 4; kk++)
        #pragma unroll
        for (int n = 0; n < 8; n++) {
            int bb = (n*4 + kk)*32 + lane;
            uint2 bh = W3H[bb];
            uint2 bl = W3L[bb];
            mma16816(d3[n], xh[kk][0], xh[kk][1], xh[kk][2], xh[kk][3], bh.x, bh.y);
            mma16816(d3[n], xl[kk][0], xl[kk][1], xl[kk][2], xl[kk][3], bh.x, bh.y);
            mma16816(d3[n], xh[kk][0], xh[kk][1], xh[kk][2], xh[kk][3], bl.x, bl.y);
        }

    // ---- y = inp + (d3+b3)*beta; stats; y->YS; y-frags (register D->A identity)
    const float* ib = inp + (size_t)b*C*HW + px0;
    float y0v[16], y1v[16];
    float s0 = 0.f, q0 = 0.f, s1 = 0.f, q1 = 0.f;
    #pragma unroll
    for (int n = 0; n < 8; n++) {
        int oa = n*8 + 2*t;
        float bb0 = B3B[oa], bb1 = B3B[oa+1], bt0 = BETB[oa], bt1 = BETB[oa+1];
        float a0 = ib[(size_t)oa*HW + r0]     + (d3[n][0] + bb0) * bt0;
        float a1 = ib[(size_t)(oa+1)*HW + r0] + (d3[n][1] + bb1) * bt1;
        float a2 = ib[(size_t)oa*HW + r1]     + (d3[n][2] + bb0) * bt0;
        float a3 = ib[(size_t)(oa+1)*HW + r1] + (d3[n][3] + bb1) * bt1;
        y0v[n*2] = a0; y0v[n*2+1] = a1; y1v[n*2] = a2; y1v[n*2+1] = a3;
        s0 += a0 + a1; q0 += a0*a0 + a1*a1;
        s1 += a2 + a3; q1 += a2*a2 + a3*a3;
        float2 p0; p0.x = a0; p0.y = a1;
        float2 p1; p1.x = a2; p1.y = a3;
        *(float2*)&YS[r0*72 + oa] = p0;
        *(float2*)&YS[r1*72 + oa] = p1;
    }
    #pragma unroll
    for (int off = 1; off < 4; off <<= 1) {
        s0 += __shfl_xor_sync(0xffffffffu, s0, off);
        q0 += __shfl_xor_sync(0xffffffffu, q0, off);
        s1 += __shfl_xor_sync(0xffffffffu, s1, off);
        q1 += __shfl_xor_sync(0xffffffffu, q1, off);
    }
    float mu0 = s0*(1.f/64), mu1 = s1*(1.f/64);
    float rs0 = rsqrtf(q0*(1.f/64) - mu0*mu0 + EPS);
    float rs1 = rsqrtf(q1*(1.f/64) - mu1*mu1 + EPS);

    uint32_t yh[4][4], yl[4][4];
    #pragma unroll
    for (int kk = 0; kk < 4; kk++) {
        bsplit2(y0v[4*kk],   y0v[4*kk+1], yh[kk][0], yl[kk][0]);
        bsplit2(y1v[4*kk],   y1v[4*kk+1], yh[kk][1], yl[kk][1]);
        bsplit2(y0v[4*kk+2], y0v[4*kk+3], yh[kk][2], yl[kk][2]);
        bsplit2(y1v[4*kk+2], y1v[4*kk+3], yh[kk][3], yl[kk][3]);
    }

    CP_WAIT(0);         // W4 + W5 complete
    __syncthreads();

    // ---- pw4 GEMM (ln2 folded)
    float d4[16][4];
    #pragma unroll
    for (int n = 0; n < 16; n++) { d4[n][0]=0; d4[n][1]=0; d4[n][2]=0; d4[n][3]=0; }
    #pragma unroll
    for (int kk = 0; kk < 4; kk++)
        #pragma unroll
        for (int n = 0; n < 16; n++) {
            int bb = (n*4 + kk)*32 + lane;
            uint2 bh = W4H[bb];
            uint2 bl = W4L[bb];
            mma16816(d4[n], yh[kk][0], yh[kk][1], yh[kk][2], yh[kk][3], bh.x, bh.y);
            mma16816(d4[n], yl[kk][0], yl[kk][1], yl[kk][2], yl[kk][3], bh.x, bh.y);
            mma16816(d4[n], yh[kk][0], yh[kk][1], yh[kk][2], yh[kk][3], bl.x, bl.y);
        }

    // ---- gate + LN-unfold in registers -> pw5 A-frags
    float g0v[16], g1v[16];
    #pragma unroll
    for (int n = 0; n < 8; n++) {
        int oa = n*8 + 2*t;
        float s4a0 = S4[oa],    s4a1 = S4[oa+1];
        float s4b0 = S4[oa+64], s4b1 = S4[oa+65];
        float ca0 = C4B[oa],    ca1 = C4B[oa+1];
        float cb0 = C4B[oa+64], cb1 = C4B[oa+65];
        g0v[n*2]   = (rs0*(d4[n][0] - mu0*s4a0) + ca0) * (rs0*(d4[n+8][0] - mu0*s4b0) + cb0);
        g0v[n*2+1] = (rs0*(d4[n][1] - mu0*s4a1) + ca1) * (rs0*(d4[n+8][1] - mu0*s4b1) + cb1);
        g1v[n*2]   = (rs1*(d4[n][2] - mu1*s4a0) + ca0) * (rs1*(d4[n+8][2] - mu1*s4b0) + cb0);
        g1v[n*2+1] = (rs1*(d4[n][3] - mu1*s4a1) + ca1) * (rs1*(d4[n+8][3] - mu1*s4b1) + cb1);
    }
    uint32_t gh[4][4], gl[4][4];
    #pragma unroll
    for (int kk = 0; kk < 4; kk++) {
        bsplit2(g0v[4*kk],   g0v[4*kk+1], gh[kk][0], gl[kk][0]);
        bsplit2(g1v[4*kk],   g1v[4*kk+1], gh[kk][1], gl[kk][1]);
        bsplit2(g0v[4*kk+2], g0v[4*kk+3], gh[kk][2], gl[kk][2]);
        bsplit2(g1v[4*kk+2], g1v[4*kk+3], gh[kk][3], gl[kk][3]);
    }

    // ---- pw5 GEMM (weights already resident — no barrier needed)
    float d5[8][4];
    #pragma unroll
    for (int n = 0; n < 8; n++) { d5[n][0]=0; d5[n][1]=0; d5[n][2]=0; d5[n][3]=0; }
    #pragma unroll
    for (int kk = 0; kk < 4; kk++)
        #pragma unroll
        for (int n = 0; n < 8; n++) {
            int bb = (n*4 + kk)*32 + lane;
            uint2 bh = W5H[bb];
            uint2 bl = W5L[bb];
            mma16816(d5[n], gh[kk][0], gh[kk][1], gh[kk][2], gh[kk][3], bh.x, bh.y);
            mma16816(d5[n], gl[kk][0], gl[kk][1], gl[kk][2], gl[kk][3], bh.x, bh.y);
            mma16816(d5[n], gh[kk][0], gh[kk][1], gh[kk][2], gh[kk][3], bl.x, bl.y);
        }

    // ---- final: out = y + (d5+b5)*gamma  (y from YS, lane-private)
    float* ob = out + (size_t)b*C*HW + px0;
    #pragma unroll
    for (int n = 0; n < 8; n++) {
        int oa = n*8 + 2*t;
        float bp0 = B5B[oa], bp1 = B5B[oa+1], gp0 = GAMB[oa], gp1 = GAMB[oa+1];
        float2 p0 = *(float2*)&YS[r0*72 + oa];
        float2 p1 = *(float2*)&YS[r1*72 + oa];
        ob[(size_t)oa*HW + r0]     = p0.x + (d5[n][0] + bp0) * gp0;
        ob[(size_t)(oa+1)*HW + r0] = p0.y + (d5[n][1] + bp1) * gp1;
        ob[(size_t)oa*HW + r1]     = p1.x + (d5[n][2] + bp0) * gp0;
        ob[(size_t)(oa+1)*HW + r1] = p1.y + (d5[n][3] + bp1) * gp1;
    }
}

// ---------------- launch ------------------------------------------------------
extern "C" void kernel_launch(void* const* d_in, const int* in_sizes, int n_in,
                              void* d_out, int out_size) {
    const float* inp   = (const float*)d_in[0];
    const float* w1    = (const float*)d_in[1];
    const float* b1    = (const float*)d_in[2];
    const float* w2    = (const float*)d_in[3];
    const float* b2    = (const float*)d_in[4];
    const float* w3    = (const float*)d_in[5];
    const float* b3    = (const float*)d_in[6];
    const float* w4    = (const float*)d_in[7];
    const float* b4    = (const float*)d_in[8];
    const float* w5    = (const float*)d_in[9];
    const float* b5    = (const float*)d_in[10];
    const float* ln1w  = (const float*)d_in[11];
    const float* ln1b  = (const float*)d_in[12];
    const float* ln2w  = (const float*)d_in[13];
    const float* ln2b  = (const float*)d_in[14];
    const float* scaw  = (const float*)d_in[15];
    const float* scab  = (const float*)d_in[16];
    const float* beta  = (const float*)d_in[17];
    const float* gamma = (const float*)d_in[18];
    float* out = (float*)d_out;

    cudaFuncSetAttribute(k1, cudaFuncAttributeMaxDynamicSharedMemorySize, 33792);
    cudaFuncSetAttribute(k2, cudaFuncAttributeMaxDynamicSharedMemorySize, K2_SMEM);

    k_prep<<<4097, 32>>>(w1, w2, w3, w4, w5, ln1w, ln1b, ln2w, ln2b);
    k1 <<<dim3(HW/128, B), 256, 33792>>>(inp, b1);
    kdw<<<dim3(IW/32, IH/32, B*C), 256>>>(b2);
    k2 <<<dim3(HW/128, B), 256, K2_SMEM>>>(inp, b3, b4, b5, beta, gamma, scaw, scab, out);
}

// round 12
// speedup vs baseline: 1.6329x; 1.1745x over previous
#include <cuda_runtime.h>
#include <cuda_bf16.h>
#include <cstdint>
#include <math.h>

#define B   8
#define C   64
#define DW  128
#define IH  256
#define IW  256
#define HW  65536
#define EPS 1e-6f

// ---------- bf16 split helper ----------
__device__ __forceinline__ void bsplit2(float f0, float f1, uint32_t& h, uint32_t& l) {
    __nv_bfloat16 h0 = __float2bfloat16(f0), h1 = __float2bfloat16(f1);
    float r0 = f0 - __bfloat162float(h0), r1 = f1 - __bfloat162float(h1);
    __nv_bfloat16 l0 = __float2bfloat16(r0), l1 = __float2bfloat16(r1);
    h = (uint32_t)__bfloat16_as_ushort(h0) | ((uint32_t)__bfloat16_as_ushort(h1) << 16);
    l = (uint32_t)__bfloat16_as_ushort(l0) | ((uint32_t)__bfloat16_as_ushort(l1) << 16);
}

// ---------- mma.sync m16n8k16 bf16 ----------
__device__ __forceinline__ void mma16816(float* d,
        uint32_t a0, uint32_t a1, uint32_t a2, uint32_t a3,
        uint32_t b0, uint32_t b1) {
    asm volatile("mma.sync.aligned.m16n8k16.row.col.f32.bf16.bf16.f32 "
        "{%0,%1,%2,%3}, {%4,%5,%6,%7}, {%8,%9}, {%0,%1,%2,%3};"
        : "+f"(d[0]), "+f"(d[1]), "+f"(d[2]), "+f"(d[3])
        : "r"(a0), "r"(a1), "r"(a2), "r"(a3), "r"(b0), "r"(b1));
}

// ---------- cp.async ----------
__device__ __forceinline__ uint32_t smem_u32(const void* p) {
    uint32_t a;
    asm("{ .reg .u64 t; cvta.to.shared.u64 t, %1; cvt.u32.u64 %0, t; }" : "=r"(a) : "l"(p));
    return a;
}
__device__ __forceinline__ void cpasync16(uint32_t s, const void* g) {
    asm volatile("cp.async.ca.shared.global [%0], [%1], 16;" :: "r"(s), "l"(g) : "memory");
}
#define CP_COMMIT() asm volatile("cp.async.commit_group;" ::: "memory")
#define CP_WAIT(n)  asm volatile("cp.async.wait_group %0;" :: "n"(n) : "memory")

// ---------------- device scratch (frag-ordered weights) -----------------------
__device__ __align__(16) uint2 g_w1f_h[B*2048], g_w1f_l[B*2048];
__device__ float g_s1 [B*DW];
__device__ float g_c1 [B*DW];
__device__ float g_w2 [B*DW*9];
__device__ __align__(16) uint2 g_w3f_h[B*1024], g_w3f_l[B*1024];
__device__ __align__(16) uint2 g_w4f_h[B*2048], g_w4f_l[B*2048];
__device__ float g_s4 [B*DW];
__device__ float g_c4 [B*DW];
__device__ __align__(16) uint2 g_w5f_h[B*1024], g_w5f_l[B*1024];
__device__ float g_t1[(size_t)B*DW*HW];
__device__ float g_t2[(size_t)B*C*HW];
__device__ float g_pool[B*C];

// ---------------- prep --------------------------------------------------------
__global__ void k_prep(const float* __restrict__ w1, const float* __restrict__ w2,
                       const float* __restrict__ w3, const float* __restrict__ w4,
                       const float* __restrict__ w5,
                       const float* __restrict__ ln1w, const float* __restrict__ ln1b,
                       const float* __restrict__ ln2w, const float* __restrict__ ln2b) {
    int blk = blockIdx.x, t = threadIdx.x;
    if (blk >= 4096) { for (int i = t; i < B*C; i += 32) g_pool[i] = 0.f; return; }

    if (blk < 1024 || (blk >= 2560 && blk < 3584)) {
        bool is1 = (blk < 1024);
        int r = is1 ? blk : blk - 2560;
        const float* src = (is1 ? w1 : w4) + r*64;
        const float* lw = is1 ? ln1w : ln2w;
        const float* lb = is1 ? ln1b : ln2b;
        int b = r >> 7, o = r & 127;
        int n = o >> 3, g = o & 7;
        float sq = 0.f;
        for (int i = t; i < 64; i += 32) { float v = src[i]; sq += v*v; }
        #pragma unroll
        for (int off = 16; off; off >>= 1) sq += __shfl_xor_sync(0xffffffffu, sq, off);
        float rn = 1.0f / sqrtf(sq);
        float s = 0.f, cx = 0.f;
        for (int i = t; i < 64; i += 32) {
            float wn = src[i] * rn;
            s += wn * lw[i]; cx += wn * lb[i];
        }
        #pragma unroll
        for (int off = 16; off; off >>= 1) {
            s  += __shfl_xor_sync(0xffffffffu, s,  off);
            cx += __shfl_xor_sync(0xffffffffu, cx, off);
        }
        if (t == 0) {
            if (is1) { g_s1[r] = s; g_c1[r] = cx; }
            else     { g_s4[r] = s; g_c4[r] = cx; }
        }
        if (t < 16) {
            int kk = t >> 2, tt = t & 3;
            int k0 = kk*16 + 2*tt;
            float f0 = src[k0]   * rn * lw[k0];
            float f1 = src[k0+1] * rn * lw[k0+1];
            float f2 = src[k0+8] * rn * lw[k0+8];
            float f3 = src[k0+9] * rn * lw[k0+9];
            uint32_t h0, l0, h1, l1;
            bsplit2(f0, f1, h0, l0);
            bsplit2(f2, f3, h1, l1);
            int idx = b*2048 + (n*4 + kk)*32 + g*4 + tt;
            uint2 vh; vh.x = h0; vh.y = h1;
            uint2 vl; vl.x = l0; vl.y = l1;
            if (is1) { g_w1f_h[idx] = vh; g_w1f_l[idx] = vl; }
            else     { g_w4f_h[idx] = vh; g_w4f_l[idx] = vl; }
        }
        return;
    }
    if (blk < 2048) {
        int r = blk - 1024;
        const float* src = w2 + r*9;
        float sq = 0.f;
        for (int i = t; i < 9; i += 32) { float v = src[i]; sq += v*v; }
        #pragma unroll
        for (int off = 16; off; off >>= 1) sq += __shfl_xor_sync(0xffffffffu, sq, off);
        float rn = 1.0f / sqrtf(sq);
        for (int i = t; i < 9; i += 32) g_w2[r*9 + i] = src[i] * rn;
        return;
    }
    bool is3 = (blk < 2560);
    int r = is3 ? (blk - 2048) : (blk - 3584);
    const float* src = (is3 ? w3 : w5) + r*64;
    int b = r >> 6, o = r & 63;
    int n = o >> 3, g = o & 7;
    float sq = 0.f;
    for (int i = t; i < 64; i += 32) { float v = src[i]; sq += v*v; }
    #pragma unroll
    for (int off = 16; off; off >>= 1) sq += __shfl_xor_sync(0xffffffffu, sq, off);
    float rn = 1.0f / sqrtf(sq);
    if (t < 16) {
        int kk = t >> 2, tt = t & 3;
        int k0 = kk*16 + 2*tt;
        uint32_t h0, l0, h1, l1;
        bsplit2(src[k0]*rn,   src[k0+1]*rn, h0, l0);
        bsplit2(src[k0+8]*rn, src[k0+9]*rn, h1, l1);
        int idx = b*1024 + (n*4 + kk)*32 + g*4 + tt;
        uint2 vh; vh.x = h0; vh.y = h1;
        uint2 vl; vl.x = l0; vl.y = l1;
        if (is3) { g_w3f_h[idx] = vh; g_w3f_l[idx] = vl; }
        else     { g_w5f_h[idx] = vh; g_w5f_l[idx] = vl; }
    }
}

// ---------------- K1: HMMA LN1(folded)+pw1, 2 CTAs/SM forced ------------------
__global__ void __launch_bounds__(256, 2) k1(const float* __restrict__ inp,
                                             const float* __restrict__ b1) {
    extern __shared__ __align__(16) char smem[];
    uint2* W1H = (uint2*)smem;
    uint2* W1L = (uint2*)(smem + 16384);
    float* S1B = (float*)(smem + 32768);
    float* C1B = (float*)(smem + 33280);
    int b = blockIdx.y, px0 = blockIdx.x * 128;
    int tid = threadIdx.x, lane = tid & 31, warp = tid >> 5;
    int g = lane >> 2, t = lane & 3;
    int m0 = warp * 16;
    int r0 = m0 + g, r1 = m0 + g + 8;

    {
        uint32_t sh = smem_u32(W1H), sl = smem_u32(W1L);
        const char* gh = (const char*)(g_w1f_h + b*2048);
        const char* gl = (const char*)(g_w1f_l + b*2048);
        for (int i = tid; i < 1024; i += 256) {
            cpasync16(sh + i*16, gh + i*16);
            cpasync16(sl + i*16, gl + i*16);
        }
        CP_COMMIT();
    }
    if (tid < 128) { S1B[tid] = g_s1[b*DW + tid]; C1B[tid] = g_c1[b*DW + tid] + b1[b*DW + tid]; }

    const float* ip = inp + (size_t)b*C*HW + px0;
    float xv0[16], xv1[16];
    float s0 = 0.f, q0 = 0.f, s1 = 0.f, q1 = 0.f;
    #pragma unroll
    for (int kk = 0; kk < 4; kk++)
        #pragma unroll
        for (int j = 0; j < 4; j++) {
            int ch = kk*16 + ((j < 2) ? (2*t + j) : (2*t + 8 + (j - 2)));
            float v0 = ip[(size_t)ch*HW + r0];
            float v1 = ip[(size_t)ch*HW + r1];
            xv0[kk*4 + j] = v0; xv1[kk*4 + j] = v1;
            s0 += v0; q0 += v0*v0; s1 += v1; q1 += v1*v1;
        }
    #pragma unroll
    for (int off = 1; off < 4; off <<= 1) {
        s0 += __shfl_xor_sync(0xffffffffu, s0, off);
        q0 += __shfl_xor_sync(0xffffffffu, q0, off);
        s1 += __shfl_xor_sync(0xffffffffu, s1, off);
        q1 += __shfl_xor_sync(0xffffffffu, q1, off);
    }
    float mu0 = s0*(1.f/64), mu1 = s1*(1.f/64);
    float rs0 = rsqrtf(q0*(1.f/64) - mu0*mu0 + EPS);
    float rs1 = rsqrtf(q1*(1.f/64) - mu1*mu1 + EPS);

    uint32_t ah[4][4], al[4][4];
    #pragma unroll
    for (int kk = 0; kk < 4; kk++) {
        bsplit2(xv0[kk*4+0], xv0[kk*4+1], ah[kk][0], al[kk][0]);
        bsplit2(xv1[kk*4+0], xv1[kk*4+1], ah[kk][1], al[kk][1]);
        bsplit2(xv0[kk*4+2], xv0[kk*4+3], ah[kk][2], al[kk][2]);
        bsplit2(xv1[kk*4+2], xv1[kk*4+3], ah[kk][3], al[kk][3]);
    }

    CP_WAIT(0);
    __syncthreads();

    float d[16][4];
    #pragma unroll
    for (int n = 0; n < 16; n++) { d[n][0]=0; d[n][1]=0; d[n][2]=0; d[n][3]=0; }
    #pragma unroll
    for (int kk = 0; kk < 4; kk++)
        #pragma unroll
        for (int n = 0; n < 16; n++) {
            int bb = (n*4 + kk)*32 + lane;
            uint2 bh = W1H[bb];
            uint2 bl = W1L[bb];
            mma16816(d[n], ah[kk][0], ah[kk][1], ah[kk][2], ah[kk][3], bh.x, bh.y);
            mma16816(d[n], al[kk][0], al[kk][1], al[kk][2], al[kk][3], bh.x, bh.y);
            mma16816(d[n], ah[kk][0], ah[kk][1], ah[kk][2], ah[kk][3], bl.x, bl.y);
        }

    float* op = g_t1 + (size_t)b*DW*HW + px0;
    #pragma unroll
    for (int n = 0; n < 16; n++) {
        int oa = n*8 + 2*t;
        float S0 = S1B[oa], Sv1 = S1B[oa+1], Cc0 = C1B[oa], Cc1 = C1B[oa+1];
        op[(size_t)oa*HW + r0]     = rs0*(d[n][0] - mu0*S0)  + Cc0;
        op[(size_t)(oa+1)*HW + r0] = rs0*(d[n][1] - mu0*Sv1) + Cc1;
        op[(size_t)oa*HW + r1]     = rs1*(d[n][2] - mu1*S0)  + Cc0;
        op[(size_t)(oa+1)*HW + r1] = rs1*(d[n][3] - mu1*Sv1) + Cc1;
    }
}

// ---------------- K_dw: depthwise 3x3 + SimpleGate + pool ---------------------
__global__ void __launch_bounds__(256) kdw(const float* __restrict__ b2) {
    int bc = blockIdx.z; int b = bc >> 6; int c = bc & 63;
    __shared__ float s1[34][36];
    __shared__ float s2[34][36];
    __shared__ float wA[9], wB[9], bAB[2], red[8];

    const float* in1 = g_t1 + ((size_t)b*DW + c     ) * HW;
    const float* in2 = g_t1 + ((size_t)b*DW + c + 64) * HW;
    int x0 = blockIdx.x * 32, y0 = blockIdx.y * 32;

    for (int i = threadIdx.x; i < 34*34; i += 256) {
        int ly = i / 34, lx = i % 34;
        int gy = y0 + ly - 1, gx = x0 + lx - 1;
        bool ok = (gy >= 0 && gy < IH && gx >= 0 && gx < IW);
        s1[ly][lx] = ok ? in1[gy*IW + gx] : 0.f;
        s2[ly][lx] = ok ? in2[gy*IW + gx] : 0.f;
    }
    if (threadIdx.x < 9)        wA[threadIdx.x]     = g_w2[((size_t)b*DW + c     )*9 + threadIdx.x];
    else if (threadIdx.x < 18)  wB[threadIdx.x - 9] = g_w2[((size_t)b*DW + c + 64)*9 + threadIdx.x - 9];
    else if (threadIdx.x == 18) bAB[0] = b2[b*DW + c];
    else if (threadIdx.x == 19) bAB[1] = b2[b*DW + c + 64];
    __syncthreads();

    int lx = threadIdx.x & 31, ly0 = (threadIdx.x >> 5) * 4;
    float* obase = g_t2 + ((size_t)b*C + c)*HW;
    float psum = 0.f;
    #pragma unroll
    for (int r = 0; r < 4; r++) {
        int ly = ly0 + r;
        float a = bAB[0], d = bAB[1];
        #pragma unroll
        for (int ky = 0; ky < 3; ky++)
            #pragma unroll
            for (int kx = 0; kx < 3; kx++) {
                a += wA[ky*3 + kx] * s1[ly + ky][lx + kx];
                d += wB[ky*3 + kx] * s2[ly + ky][lx + kx];
            }
        float g = a * d;
        obase[(y0 + ly)*IW + (x0 + lx)] = g;
        psum += g;
    }
    #pragma unroll
    for (int off = 16; off; off >>= 1) psum += __shfl_down_sync(0xffffffffu, psum, off);
    if (lx == 0) red[threadIdx.x >> 5] = psum;
    __syncthreads();
    if (threadIdx.x == 0) {
        float t = 0.f;
        #pragma unroll
        for (int i = 0; i < 8; i++) t += red[i];
        atomicAdd(&g_pool[b*C + c], t);
    }
}

// ---------------- K2: fused HMMA, 2 CTAs/SM forced ----------------------------
#define KO_W3H 0
#define KO_W3L 8192
#define KO_W4H 16384
#define KO_W4L 32768
#define KO_W5H 49152
#define KO_W5L 57344
#define KO_YS  65536
#define KO_S4  102400
#define KO_C4  102912
#define KO_B3  103424
#define KO_BT  103680
#define KO_B5  103936
#define KO_GM  104192
#define KO_SC  104448
#define KO_PL  104704
#define K2_SMEM 104960

__global__ void __launch_bounds__(256, 2) k2(const float* __restrict__ inp,
                                             const float* __restrict__ b3,
                                             const float* __restrict__ b4,
                                             const float* __restrict__ b5,
                                             const float* __restrict__ beta,
                                             const float* __restrict__ gamma,
                                             const float* __restrict__ sca_w,
                                             const float* __restrict__ sca_b,
                                             float* __restrict__ out) {
    extern __shared__ __align__(16) char smem[];
    uint2* W3H = (uint2*)(smem + KO_W3H);
    uint2* W3L = (uint2*)(smem + KO_W3L);
    uint2* W4H = (uint2*)(smem + KO_W4H);
    uint2* W4L = (uint2*)(smem + KO_W4L);
    uint2* W5H = (uint2*)(smem + KO_W5H);
    uint2* W5L = (uint2*)(smem + KO_W5L);
    float* YS  = (float*)(smem + KO_YS);
    float* S4  = (float*)(smem + KO_S4);
    float* C4B = (float*)(smem + KO_C4);
    float* B3B = (float*)(smem + KO_B3);
    float* BETB= (float*)(smem + KO_BT);
    float* B5B = (float*)(smem + KO_B5);
    float* GAMB= (float*)(smem + KO_GM);
    float* SCS = (float*)(smem + KO_SC);
    float* PLS = (float*)(smem + KO_PL);

    int b = blockIdx.y, px0 = blockIdx.x * 128;
    int tid = threadIdx.x, lane = tid & 31, warp = tid >> 5;
    int g = lane >> 2, t = lane & 3;
    int m0 = warp * 16;
    int r0 = m0 + g, r1 = m0 + g + 8;

    // ---- prefetch: W3 (group 0), W4+W5 (group 1)
    {
        uint32_t s3h = smem_u32(W3H), s3l = smem_u32(W3L);
        const char* g3h = (const char*)(g_w3f_h + b*1024);
        const char* g3l = (const char*)(g_w3f_l + b*1024);
        for (int i = tid; i < 512; i += 256) {
            cpasync16(s3h + i*16, g3h + i*16);
            cpasync16(s3l + i*16, g3l + i*16);
        }
        CP_COMMIT();
        uint32_t s4h = smem_u32(W4H), s4l = smem_u32(W4L);
        const char* g4h = (const char*)(g_w4f_h + b*2048);
        const char* g4l = (const char*)(g_w4f_l + b*2048);
        for (int i = tid; i < 1024; i += 256) {
            cpasync16(s4h + i*16, g4h + i*16);
            cpasync16(s4l + i*16, g4l + i*16);
        }
        uint32_t s5h = smem_u32(W5H), s5l = smem_u32(W5L);
        const char* g5h = (const char*)(g_w5f_h + b*1024);
        const char* g5l = (const char*)(g_w5f_l + b*1024);
        for (int i = tid; i < 512; i += 256) {
            cpasync16(s5h + i*16, g5h + i*16);
            cpasync16(s5l + i*16, g5l + i*16);
        }
        CP_COMMIT();
    }
    if (tid < 64) {
        B3B[tid] = b3[b*64 + tid]; BETB[tid] = beta[tid];
        B5B[tid] = b5[b*64 + tid]; GAMB[tid] = gamma[tid];
        PLS[tid] = g_pool[b*64 + tid] * (1.f/(float)HW);
    } else if (tid < 192) {
        int u = tid - 64;
        S4[u] = g_s4[b*128 + u];
        C4B[u] = g_c4[b*128 + u] + b4[b*128 + u];
    }
    CP_WAIT(1);
    __syncthreads();
    if (tid < 64) {
        float acc = sca_b[tid];
        #pragma unroll 8
        for (int cc = 0; cc < 64; cc++) acc += sca_w[tid*64 + cc] * PLS[cc];
        SCS[tid] = acc;
    }
    __syncthreads();

    // ---- A-frags of X = sca*t2 via per-lane LDG
    const float* t2b = g_t2 + (size_t)b*C*HW + px0;
    uint32_t xh[4][4], xl[4][4];
    #pragma unroll
    for (int kk = 0; kk < 4; kk++) {
        float v0[4], v1[4];
        #pragma unroll
        for (int j = 0; j < 4; j++) {
            int ch = kk*16 + ((j < 2) ? (2*t + j) : (2*t + 8 + (j - 2)));
            float sc = SCS[ch];
            v0[j] = t2b[(size_t)ch*HW + r0] * sc;
            v1[j] = t2b[(size_t)ch*HW + r1] * sc;
        }
        bsplit2(v0[0], v0[1], xh[kk][0], xl[kk][0]);
        bsplit2(v1[0], v1[1], xh[kk][1], xl[kk][1]);
        bsplit2(v0[2], v0[3], xh[kk][2], xl[kk][2]);
        bsplit2(v1[2], v1[3], xh[kk][3], xl[kk][3]);
    }

    // ---- pw3 GEMM
    float d3[8][4];
    #pragma unroll
    for (int n = 0; n < 8; n++) { d3[n][0]=0; d3[n][1]=0; d3[n][2]=0; d3[n][3]=0; }
    #pragma unroll
    for (int kk = 0; kk < 4; kk++)
        #pragma unroll
        for (int n = 0; n < 8; n++) {
            int bb = (n*4 + kk)*32 + lane;
            uint2 bh = W3H[bb];
            uint2 bl = W3L[bb];
            mma16816(d3[n], xh[kk][0], xh[kk][1], xh[kk][2], xh[kk][3], bh.x, bh.y);
            mma16816(d3[n], xl[kk][0], xl[kk][1], xl[kk][2], xl[kk][3], bh.x, bh.y);
            mma16816(d3[n], xh[kk][0], xh[kk][1], xh[kk][2], xh[kk][3], bl.x, bl.y);
        }

    // ---- y = inp + (d3+b3)*beta; stats; y->YS; y-frags
    const float* ib = inp + (size_t)b*C*HW + px0;
    float y0v[16], y1v[16];
    float s0 = 0.f, q0 = 0.f, s1 = 0.f, q1 = 0.f;
    #pragma unroll
    for (int n = 0; n < 8; n++) {
        int oa = n*8 + 2*t;
        float bb0 = B3B[oa], bb1 = B3B[oa+1], bt0 = BETB[oa], bt1 = BETB[oa+1];
        float a0 = ib[(size_t)oa*HW + r0]     + (d3[n][0] + bb0) * bt0;
        float a1 = ib[(size_t)(oa+1)*HW + r0] + (d3[n][1] + bb1) * bt1;
        float a2 = ib[(size_t)oa*HW + r1]     + (d3[n][2] + bb0) * bt0;
        float a3 = ib[(size_t)(oa+1)*HW + r1] + (d3[n][3] + bb1) * bt1;
        y0v[n*2] = a0; y0v[n*2+1] = a1; y1v[n*2] = a2; y1v[n*2+1] = a3;
        s0 += a0 + a1; q0 += a0*a0 + a1*a1;
        s1 += a2 + a3; q1 += a2*a2 + a3*a3;
        float2 p0; p0.x = a0; p0.y = a1;
        float2 p1; p1.x = a2; p1.y = a3;
        *(float2*)&YS[r0*72 + oa] = p0;
        *(float2*)&YS[r1*72 + oa] = p1;
    }
    #pragma unroll
    for (int off = 1; off < 4; off <<= 1) {
        s0 += __shfl_xor_sync(0xffffffffu, s0, off);
        q0 += __shfl_xor_sync(0xffffffffu, q0, off);
        s1 += __shfl_xor_sync(0xffffffffu, s1, off);
        q1 += __shfl_xor_sync(0xffffffffu, q1, off);
    }
    float mu0 = s0*(1.f/64), mu1 = s1*(1.f/64);
    float rs0 = rsqrtf(q0*(1.f/64) - mu0*mu0 + EPS);
    float rs1 = rsqrtf(q1*(1.f/64) - mu1*mu1 + EPS);

    uint32_t yh[4][4], yl[4][4];
    #pragma unroll
    for (int kk = 0; kk < 4; kk++) {
        bsplit2(y0v[4*kk],   y0v[4*kk+1], yh[kk][0], yl[kk][0]);
        bsplit2(y1v[4*kk],   y1v[4*kk+1], yh[kk][1], yl[kk][1]);
        bsplit2(y0v[4*kk+2], y0v[4*kk+3], yh[kk][2], yl[kk][2]);
        bsplit2(y1v[4*kk+2], y1v[4*kk+3], yh[kk][3], yl[kk][3]);
    }

    CP_WAIT(0);
    __syncthreads();

    // ---- pw4 GEMM (ln2 folded)
    float d4[16][4];
    #pragma unroll
    for (int n = 0; n < 16; n++) { d4[n][0]=0; d4[n][1]=0; d4[n][2]=0; d4[n][3]=0; }
    #pragma unroll
    for (int kk = 0; kk < 4; kk++)
        #pragma unroll
        for (int n = 0; n < 16; n++) {
            int bb = (n*4 + kk)*32 + lane;
            uint2 bh = W4H[bb];
            uint2 bl = W4L[bb];
            mma16816(d4[n], yh[kk][0], yh[kk][1], yh[kk][2], yh[kk][3], bh.x, bh.y);
            mma16816(d4[n], yl[kk][0], yl[kk][1], yl[kk][2], yl[kk][3], bh.x, bh.y);
            mma16816(d4[n], yh[kk][0], yh[kk][1], yh[kk][2], yh[kk][3], bl.x, bl.y);
        }

    // ---- gate + LN-unfold in registers -> pw5 A-frags
    float g0v[16], g1v[16];
    #pragma unroll
    for (int n = 0; n < 8; n++) {
        int oa = n*8 + 2*t;
        float s4a0 = S4[oa],    s4a1 = S4[oa+1];
        float s4b0 = S4[oa+64], s4b1 = S4[oa+65];
        float ca0 = C4B[oa],    ca1 = C4B[oa+1];
        float cb0 = C4B[oa+64], cb1 = C4B[oa+65];
        g0v[n*2]   = (rs0*(d4[n][0] - mu0*s4a0) + ca0) * (rs0*(d4[n+8][0] - mu0*s4b0) + cb0);
        g0v[n*2+1] = (rs0*(d4[n][1] - mu0*s4a1) + ca1) * (rs0*(d4[n+8][1] - mu0*s4b1) + cb1);
        g1v[n*2]   = (rs1*(d4[n][2] - mu1*s4a0) + ca0) * (rs1*(d4[n+8][2] - mu1*s4b0) + cb0);
        g1v[n*2+1] = (rs1*(d4[n][3] - mu1*s4a1) + ca1) * (rs1*(d4[n+8][3] - mu1*s4b1) + cb1);
    }
    uint32_t gh[4][4], gl[4][4];
    #pragma unroll
    for (int kk = 0; kk < 4; kk++) {
        bsplit2(g0v[4*kk],   g0v[4*kk+1], gh[kk][0], gl[kk][0]);
        bsplit2(g1v[4*kk],   g1v[4*kk+1], gh[kk][1], gl[kk][1]);
        bsplit2(g0v[4*kk+2], g0v[4*kk+3], gh[kk][2], gl[kk][2]);
        bsplit2(g1v[4*kk+2], g1v[4*kk+3], gh[kk][3], gl[kk][3]);
    }

    // ---- pw5 GEMM
    float d5[8][4];
    #pragma unroll
    for (int n = 0; n < 8; n++) { d5[n][0]=0; d5[n][1]=0; d5[n][2]=0; d5[n][3]=0; }
    #pragma unroll
    for (int kk = 0; kk < 4; kk++)
        #pragma unroll
        for (int n = 0; n < 8; n++) {
            int bb = (n*4 + kk)*32 + lane;
            uint2 bh = W5H[bb];
            uint2 bl = W5L[bb];
            mma16816(d5[n], gh[kk][0], gh[kk][1], gh[kk][2], gh[kk][3], bh.x, bh.y);
            mma16816(d5[n], gl[kk][0], gl[kk][1], gl[kk][2], gl[kk][3], bh.x, bh.y);
            mma16816(d5[n], gh[kk][0], gh[kk][1], gh[kk][2], gh[kk][3], bl.x, bl.y);
        }

    // ---- final: out = y + (d5+b5)*gamma
    float* ob = out + (size_t)b*C*HW + px0;
    #pragma unroll
    for (int n = 0; n < 8; n++) {
        int oa = n*8 + 2*t;
        float bp0 = B5B[oa], bp1 = B5B[oa+1], gp0 = GAMB[oa], gp1 = GAMB[oa+1];
        float2 p0 = *(float2*)&YS[r0*72 + oa];
        float2 p1 = *(float2*)&YS[r1*72 + oa];
        ob[(size_t)oa*HW + r0]     = p0.x + (d5[n][0] + bp0) * gp0;
        ob[(size_t)(oa+1)*HW + r0] = p0.y + (d5[n][1] + bp1) * gp1;
        ob[(size_t)oa*HW + r1]     = p1.x + (d5[n][2] + bp0) * gp0;
        ob[(size_t)(oa+1)*HW + r1] = p1.y + (d5[n][3] + bp1) * gp1;
    }
}

// ---------------- launch ------------------------------------------------------
extern "C" void kernel_launch(void* const* d_in, const int* in_sizes, int n_in,
                              void* d_out, int out_size) {
    const float* inp   = (const float*)d_in[0];
    const float* w1    = (const float*)d_in[1];
    const float* b1    = (const float*)d_in[2];
    const float* w2    = (const float*)d_in[3];
    const float* b2    = (const float*)d_in[4];
    const float* w3    = (const float*)d_in[5];
    const float* b3    = (const float*)d_in[6];
    const float* w4    = (const float*)d_in[7];
    const float* b4    = (const float*)d_in[8];
    const float* w5    = (const float*)d_in[9];
    const float* b5    = (const float*)d_in[10];
    const float* ln1w  = (const float*)d_in[11];
    const float* ln1b  = (const float*)d_in[12];
    const float* ln2w  = (const float*)d_in[13];
    const float* ln2b  = (const float*)d_in[14];
    const float* scaw  = (const float*)d_in[15];
    const float* scab  = (const float*)d_in[16];
    const float* beta  = (const float*)d_in[17];
    const float* gamma = (const float*)d_in[18];
    float* out = (float*)d_out;

    cudaFuncSetAttribute(k1, cudaFuncAttributeMaxDynamicSharedMemorySize, 33792);
    cudaFuncSetAttribute(k2, cudaFuncAttributeMaxDynamicSharedMemorySize, K2_SMEM);

    k_prep<<<4097, 32>>>(w1, w2, w3, w4, w5, ln1w, ln1b, ln2w, ln2b);
    k1 <<<dim3(HW/128, B), 256, 33792>>>(inp, b1);
    kdw<<<dim3(IW/32, IH/32, B*C), 256>>>(b2);
    k2 <<<dim3(HW/128, B), 256, K2_SMEM>>>(inp, b3, b4, b5, beta, gamma, scaw, scab, out);
}

// round 13
// speedup vs baseline: 1.6918x; 1.0361x over previous
#include <cuda_runtime.h>
#include <cuda_bf16.h>
#include <cuda_fp16.h>
#include <cstdint>
#include <math.h>

#define B   8
#define C   64
#define DW  128
#define IH  256
#define IW  256
#define HW  65536
#define EPS 1e-6f

// ---------- bf16 split helper ----------
__device__ __forceinline__ void bsplit2(float f0, float f1, uint32_t& h, uint32_t& l) {
    __nv_bfloat16 h0 = __float2bfloat16(f0), h1 = __float2bfloat16(f1);
    float r0 = f0 - __bfloat162float(h0), r1 = f1 - __bfloat162float(h1);
    __nv_bfloat16 l0 = __float2bfloat16(r0), l1 = __float2bfloat16(r1);
    h = (uint32_t)__bfloat16_as_ushort(h0) | ((uint32_t)__bfloat16_as_ushort(h1) << 16);
    l = (uint32_t)__bfloat16_as_ushort(l0) | ((uint32_t)__bfloat16_as_ushort(l1) << 16);
}

// ---------- mma.sync m16n8k16 bf16 ----------
__device__ __forceinline__ void mma16816(float* d,
        uint32_t a0, uint32_t a1, uint32_t a2, uint32_t a3,
        uint32_t b0, uint32_t b1) {
    asm volatile("mma.sync.aligned.m16n8k16.row.col.f32.bf16.bf16.f32 "
        "{%0,%1,%2,%3}, {%4,%5,%6,%7}, {%8,%9}, {%0,%1,%2,%3};"
        : "+f"(d[0]), "+f"(d[1]), "+f"(d[2]), "+f"(d[3])
        : "r"(a0), "r"(a1), "r"(a2), "r"(a3), "r"(b0), "r"(b1));
}

// ---------- cp.async ----------
__device__ __forceinline__ uint32_t smem_u32(const void* p) {
    uint32_t a;
    asm("{ .reg .u64 t; cvta.to.shared.u64 t, %1; cvt.u32.u64 %0, t; }" : "=r"(a) : "l"(p));
    return a;
}
__device__ __forceinline__ void cpasync16(uint32_t s, const void* g) {
    asm volatile("cp.async.ca.shared.global [%0], [%1], 16;" :: "r"(s), "l"(g) : "memory");
}
#define CP_COMMIT() asm volatile("cp.async.commit_group;" ::: "memory")
#define CP_WAIT(n)  asm volatile("cp.async.wait_group %0;" :: "n"(n) : "memory")

// ---------------- device scratch (frag-ordered weights; fp16 activations) -----
__device__ __align__(16) uint2 g_w1f_h[B*2048], g_w1f_l[B*2048];
__device__ float g_s1 [B*DW];
__device__ float g_c1 [B*DW];
__device__ float g_w2 [B*DW*9];
__device__ __align__(16) uint2 g_w3f_h[B*1024], g_w3f_l[B*1024];
__device__ __align__(16) uint2 g_w4f_h[B*2048], g_w4f_l[B*2048];
__device__ float g_s4 [B*DW];
__device__ float g_c4 [B*DW];
__device__ __align__(16) uint2 g_w5f_h[B*1024], g_w5f_l[B*1024];
__device__ __half g_t1[(size_t)B*DW*HW];   // fp16 intermediates
__device__ __half g_t2[(size_t)B*C*HW];
__device__ float g_pool[B*C];

// ---------------- prep --------------------------------------------------------
__global__ void k_prep(const float* __restrict__ w1, const float* __restrict__ w2,
                       const float* __restrict__ w3, const float* __restrict__ w4,
                       const float* __restrict__ w5,
                       const float* __restrict__ ln1w, const float* __restrict__ ln1b,
                       const float* __restrict__ ln2w, const float* __restrict__ ln2b) {
    int blk = blockIdx.x, t = threadIdx.x;
    if (blk >= 4096) { for (int i = t; i < B*C; i += 32) g_pool[i] = 0.f; return; }

    if (blk < 1024 || (blk >= 2560 && blk < 3584)) {
        bool is1 = (blk < 1024);
        int r = is1 ? blk : blk - 2560;
        const float* src = (is1 ? w1 : w4) + r*64;
        const float* lw = is1 ? ln1w : ln2w;
        const float* lb = is1 ? ln1b : ln2b;
        int b = r >> 7, o = r & 127;
        int n = o >> 3, g = o & 7;
        float sq = 0.f;
        for (int i = t; i < 64; i += 32) { float v = src[i]; sq += v*v; }
        #pragma unroll
        for (int off = 16; off; off >>= 1) sq += __shfl_xor_sync(0xffffffffu, sq, off);
        float rn = 1.0f / sqrtf(sq);
        float s = 0.f, cx = 0.f;
        for (int i = t; i < 64; i += 32) {
            float wn = src[i] * rn;
            s += wn * lw[i]; cx += wn * lb[i];
        }
        #pragma unroll
        for (int off = 16; off; off >>= 1) {
            s  += __shfl_xor_sync(0xffffffffu, s,  off);
            cx += __shfl_xor_sync(0xffffffffu, cx, off);
        }
        if (t == 0) {
            if (is1) { g_s1[r] = s; g_c1[r] = cx; }
            else     { g_s4[r] = s; g_c4[r] = cx; }
        }
        if (t < 16) {
            int kk = t >> 2, tt = t & 3;
            int k0 = kk*16 + 2*tt;
            float f0 = src[k0]   * rn * lw[k0];
            float f1 = src[k0+1] * rn * lw[k0+1];
            float f2 = src[k0+8] * rn * lw[k0+8];
            float f3 = src[k0+9] * rn * lw[k0+9];
            uint32_t h0, l0, h1, l1;
            bsplit2(f0, f1, h0, l0);
            bsplit2(f2, f3, h1, l1);
            int idx = b*2048 + (n*4 + kk)*32 + g*4 + tt;
            uint2 vh; vh.x = h0; vh.y = h1;
            uint2 vl; vl.x = l0; vl.y = l1;
            if (is1) { g_w1f_h[idx] = vh; g_w1f_l[idx] = vl; }
            else     { g_w4f_h[idx] = vh; g_w4f_l[idx] = vl; }
        }
        return;
    }
    if (blk < 2048) {
        int r = blk - 1024;
        const float* src = w2 + r*9;
        float sq = 0.f;
        for (int i = t; i < 9; i += 32) { float v = src[i]; sq += v*v; }
        #pragma unroll
        for (int off = 16; off; off >>= 1) sq += __shfl_xor_sync(0xffffffffu, sq, off);
        float rn = 1.0f / sqrtf(sq);
        for (int i = t; i < 9; i += 32) g_w2[r*9 + i] = src[i] * rn;
        return;
    }
    bool is3 = (blk < 2560);
    int r = is3 ? (blk - 2048) : (blk - 3584);
    const float* src = (is3 ? w3 : w5) + r*64;
    int b = r >> 6, o = r & 63;
    int n = o >> 3, g = o & 7;
    float sq = 0.f;
    for (int i = t; i < 64; i += 32) { float v = src[i]; sq += v*v; }
    #pragma unroll
    for (int off = 16; off; off >>= 1) sq += __shfl_xor_sync(0xffffffffu, sq, off);
    float rn = 1.0f / sqrtf(sq);
    if (t < 16) {
        int kk = t >> 2, tt = t & 3;
        int k0 = kk*16 + 2*tt;
        uint32_t h0, l0, h1, l1;
        bsplit2(src[k0]*rn,   src[k0+1]*rn, h0, l0);
        bsplit2(src[k0+8]*rn, src[k0+9]*rn, h1, l1);
        int idx = b*1024 + (n*4 + kk)*32 + g*4 + tt;
        uint2 vh; vh.x = h0; vh.y = h1;
        uint2 vl; vl.x = l0; vl.y = l1;
        if (is3) { g_w3f_h[idx] = vh; g_w3f_l[idx] = vl; }
        else     { g_w5f_h[idx] = vh; g_w5f_l[idx] = vl; }
    }
}

// ---------------- K1: HMMA LN1(folded)+pw1, fp16 output -----------------------
__global__ void __launch_bounds__(256, 2) k1(const float* __restrict__ inp,
                                             const float* __restrict__ b1) {
    extern __shared__ __align__(16) char smem[];
    uint2* W1H = (uint2*)smem;
    uint2* W1L = (uint2*)(smem + 16384);
    float* S1B = (float*)(smem + 32768);
    float* C1B = (float*)(smem + 33280);
    int b = blockIdx.y, px0 = blockIdx.x * 128;
    int tid = threadIdx.x, lane = tid & 31, warp = tid >> 5;
    int g = lane >> 2, t = lane & 3;
    int m0 = warp * 16;
    int r0 = m0 + g, r1 = m0 + g + 8;

    {
        uint32_t sh = smem_u32(W1H), sl = smem_u32(W1L);
        const char* gh = (const char*)(g_w1f_h + b*2048);
        const char* gl = (const char*)(g_w1f_l + b*2048);
        for (int i = tid; i < 1024; i += 256) {
            cpasync16(sh + i*16, gh + i*16);
            cpasync16(sl + i*16, gl + i*16);
        }
        CP_COMMIT();
    }
    if (tid < 128) { S1B[tid] = g_s1[b*DW + tid]; C1B[tid] = g_c1[b*DW + tid] + b1[b*DW + tid]; }

    const float* ip = inp + (size_t)b*C*HW + px0;
    float xv0[16], xv1[16];
    float s0 = 0.f, q0 = 0.f, s1 = 0.f, q1 = 0.f;
    #pragma unroll
    for (int kk = 0; kk < 4; kk++)
        #pragma unroll
        for (int j = 0; j < 4; j++) {
            int ch = kk*16 + ((j < 2) ? (2*t + j) : (2*t + 8 + (j - 2)));
            float v0 = ip[(size_t)ch*HW + r0];
            float v1 = ip[(size_t)ch*HW + r1];
            xv0[kk*4 + j] = v0; xv1[kk*4 + j] = v1;
            s0 += v0; q0 += v0*v0; s1 += v1; q1 += v1*v1;
        }
    #pragma unroll
    for (int off = 1; off < 4; off <<= 1) {
        s0 += __shfl_xor_sync(0xffffffffu, s0, off);
        q0 += __shfl_xor_sync(0xffffffffu, q0, off);
        s1 += __shfl_xor_sync(0xffffffffu, s1, off);
        q1 += __shfl_xor_sync(0xffffffffu, q1, off);
    }
    float mu0 = s0*(1.f/64), mu1 = s1*(1.f/64);
    float rs0 = rsqrtf(q0*(1.f/64) - mu0*mu0 + EPS);
    float rs1 = rsqrtf(q1*(1.f/64) - mu1*mu1 + EPS);

    uint32_t ah[4][4], al[4][4];
    #pragma unroll
    for (int kk = 0; kk < 4; kk++) {
        bsplit2(xv0[kk*4+0], xv0[kk*4+1], ah[kk][0], al[kk][0]);
        bsplit2(xv1[kk*4+0], xv1[kk*4+1], ah[kk][1], al[kk][1]);
        bsplit2(xv0[kk*4+2], xv0[kk*4+3], ah[kk][2], al[kk][2]);
        bsplit2(xv1[kk*4+2], xv1[kk*4+3], ah[kk][3], al[kk][3]);
    }

    CP_WAIT(0);
    __syncthreads();

    float d[16][4];
    #pragma unroll
    for (int n = 0; n < 16; n++) { d[n][0]=0; d[n][1]=0; d[n][2]=0; d[n][3]=0; }
    #pragma unroll
    for (int kk = 0; kk < 4; kk++)
        #pragma unroll
        for (int n = 0; n < 16; n++) {
            int bb = (n*4 + kk)*32 + lane;
            uint2 bh = W1H[bb];
            uint2 bl = W1L[bb];
            mma16816(d[n], ah[kk][0], ah[kk][1], ah[kk][2], ah[kk][3], bh.x, bh.y);
            mma16816(d[n], al[kk][0], al[kk][1], al[kk][2], al[kk][3], bh.x, bh.y);
            mma16816(d[n], ah[kk][0], ah[kk][1], ah[kk][2], ah[kk][3], bl.x, bl.y);
        }

    __half* op = g_t1 + (size_t)b*DW*HW + px0;
    #pragma unroll
    for (int n = 0; n < 16; n++) {
        int oa = n*8 + 2*t;
        float S0 = S1B[oa], Sv1 = S1B[oa+1], Cc0 = C1B[oa], Cc1 = C1B[oa+1];
        op[(size_t)oa*HW + r0]     = __float2half(rs0*(d[n][0] - mu0*S0)  + Cc0);
        op[(size_t)(oa+1)*HW + r0] = __float2half(rs0*(d[n][1] - mu0*Sv1) + Cc1);
        op[(size_t)oa*HW + r1]     = __float2half(rs1*(d[n][2] - mu1*S0)  + Cc0);
        op[(size_t)(oa+1)*HW + r1] = __float2half(rs1*(d[n][3] - mu1*Sv1) + Cc1);
    }
}

// ---------------- K_dw: depthwise 3x3 + SimpleGate + pool (fp16 io) -----------
__global__ void __launch_bounds__(256) kdw(const float* __restrict__ b2) {
    int bc = blockIdx.z; int b = bc >> 6; int c = bc & 63;
    __shared__ float s1[34][36];
    __shared__ float s2[34][36];
    __shared__ float wA[9], wB[9], bAB[2], red[8];

    const __half* in1 = g_t1 + ((size_t)b*DW + c     ) * HW;
    const __half* in2 = g_t1 + ((size_t)b*DW + c + 64) * HW;
    int x0 = blockIdx.x * 32, y0 = blockIdx.y * 32;

    for (int i = threadIdx.x; i < 34*34; i += 256) {
        int ly = i / 34, lx = i % 34;
        int gy = y0 + ly - 1, gx = x0 + lx - 1;
        bool ok = (gy >= 0 && gy < IH && gx >= 0 && gx < IW);
        s1[ly][lx] = ok ? __half2float(in1[gy*IW + gx]) : 0.f;
        s2[ly][lx] = ok ? __half2float(in2[gy*IW + gx]) : 0.f;
    }
    if (threadIdx.x < 9)        wA[threadIdx.x]     = g_w2[((size_t)b*DW + c     )*9 + threadIdx.x];
    else if (threadIdx.x < 18)  wB[threadIdx.x - 9] = g_w2[((size_t)b*DW + c + 64)*9 + threadIdx.x - 9];
    else if (threadIdx.x == 18) bAB[0] = b2[b*DW + c];
    else if (threadIdx.x == 19) bAB[1] = b2[b*DW + c + 64];
    __syncthreads();

    int lx = threadIdx.x & 31, ly0 = (threadIdx.x >> 5) * 4;
    __half* obase = g_t2 + ((size_t)b*C + c)*HW;
    float psum = 0.f;
    #pragma unroll
    for (int r = 0; r < 4; r++) {
        int ly = ly0 + r;
        float a = bAB[0], d = bAB[1];
        #pragma unroll
        for (int ky = 0; ky < 3; ky++)
            #pragma unroll
            for (int kx = 0; kx < 3; kx++) {
                a += wA[ky*3 + kx] * s1[ly + ky][lx + kx];
                d += wB[ky*3 + kx] * s2[ly + ky][lx + kx];
            }
        float g = a * d;
        obase[(y0 + ly)*IW + (x0 + lx)] = __float2half(g);
        psum += g;
    }
    #pragma unroll
    for (int off = 16; off; off >>= 1) psum += __shfl_down_sync(0xffffffffu, psum, off);
    if (lx == 0) red[threadIdx.x >> 5] = psum;
    __syncthreads();
    if (threadIdx.x == 0) {
        float t = 0.f;
        #pragma unroll
        for (int i = 0; i < 8; i++) t += red[i];
        atomicAdd(&g_pool[b*C + c], t);
    }
}

// ---------------- K2: fused HMMA, 2 CTAs/SM, fp16 t2 input --------------------
#define KO_W3H 0
#define KO_W3L 8192
#define KO_W4H 16384
#define KO_W4L 32768
#define KO_W5H 49152
#define KO_W5L 57344
#define KO_YS  65536
#define KO_S4  102400
#define KO_C4  102912
#define KO_B3  103424
#define KO_BT  103680
#define KO_B5  103936
#define KO_GM  104192
#define KO_SC  104448
#define KO_PL  104704
#define K2_SMEM 104960

__global__ void __launch_bounds__(256, 2) k2(const float* __restrict__ inp,
                                             const float* __restrict__ b3,
                                             const float* __restrict__ b4,
                                             const float* __restrict__ b5,
                                             const float* __restrict__ beta,
                                             const float* __restrict__ gamma,
                                             const float* __restrict__ sca_w,
                                             const float* __restrict__ sca_b,
                                             float* __restrict__ out) {
    extern __shared__ __align__(16) char smem[];
    uint2* W3H = (uint2*)(smem + KO_W3H);
    uint2* W3L = (uint2*)(smem + KO_W3L);
    uint2* W4H = (uint2*)(smem + KO_W4H);
    uint2* W4L = (uint2*)(smem + KO_W4L);
    uint2* W5H = (uint2*)(smem + KO_W5H);
    uint2* W5L = (uint2*)(smem + KO_W5L);
    float* YS  = (float*)(smem + KO_YS);
    float* S4  = (float*)(smem + KO_S4);
    float* C4B = (float*)(smem + KO_C4);
    float* B3B = (float*)(smem + KO_B3);
    float* BETB= (float*)(smem + KO_BT);
    float* B5B = (float*)(smem + KO_B5);
    float* GAMB= (float*)(smem + KO_GM);
    float* SCS = (float*)(smem + KO_SC);
    float* PLS = (float*)(smem + KO_PL);

    int b = blockIdx.y, px0 = blockIdx.x * 128;
    int tid = threadIdx.x, lane = tid & 31, warp = tid >> 5;
    int g = lane >> 2, t = lane & 3;
    int m0 = warp * 16;
    int r0 = m0 + g, r1 = m0 + g + 8;

    {
        uint32_t s3h = smem_u32(W3H), s3l = smem_u32(W3L);
        const char* g3h = (const char*)(g_w3f_h + b*1024);
        const char* g3l = (const char*)(g_w3f_l + b*1024);
        for (int i = tid; i < 512; i += 256) {
            cpasync16(s3h + i*16, g3h + i*16);
            cpasync16(s3l + i*16, g3l + i*16);
        }
        CP_COMMIT();
        uint32_t s4h = smem_u32(W4H), s4l = smem_u32(W4L);
        const char* g4h = (const char*)(g_w4f_h + b*2048);
        const char* g4l = (const char*)(g_w4f_l + b*2048);
        for (int i = tid; i < 1024; i += 256) {
            cpasync16(s4h + i*16, g4h + i*16);
            cpasync16(s4l + i*16, g4l + i*16);
        }
        uint32_t s5h = smem_u32(W5H), s5l = smem_u32(W5L);
        const char* g5h = (const char*)(g_w5f_h + b*1024);
        const char* g5l = (const char*)(g_w5f_l + b*1024);
        for (int i = tid; i < 512; i += 256) {
            cpasync16(s5h + i*16, g5h + i*16);
            cpasync16(s5l + i*16, g5l + i*16);
        }
        CP_COMMIT();
    }
    if (tid < 64) {
        B3B[tid] = b3[b*64 + tid]; BETB[tid] = beta[tid];
        B5B[tid] = b5[b*64 + tid]; GAMB[tid] = gamma[tid];
        PLS[tid] = g_pool[b*64 + tid] * (1.f/(float)HW);
    } else if (tid < 192) {
        int u = tid - 64;
        S4[u] = g_s4[b*128 + u];
        C4B[u] = g_c4[b*128 + u] + b4[b*128 + u];
    }
    CP_WAIT(1);
    __syncthreads();
    if (tid < 64) {
        float acc = sca_b[tid];
        #pragma unroll 8
        for (int cc = 0; cc < 64; cc++) acc += sca_w[tid*64 + cc] * PLS[cc];
        SCS[tid] = acc;
    }
    __syncthreads();

    // ---- A-frags of X = sca*t2 (fp16 gather)
    const __half* t2b = g_t2 + (size_t)b*C*HW + px0;
    uint32_t xh[4][4], xl[4][4];
    #pragma unroll
    for (int kk = 0; kk < 4; kk++) {
        float v0[4], v1[4];
        #pragma unroll
        for (int j = 0; j < 4; j++) {
            int ch = kk*16 + ((j < 2) ? (2*t + j) : (2*t + 8 + (j - 2)));
            float sc = SCS[ch];
            v0[j] = __half2float(t2b[(size_t)ch*HW + r0]) * sc;
            v1[j] = __half2float(t2b[(size_t)ch*HW + r1]) * sc;
        }
        bsplit2(v0[0], v0[1], xh[kk][0], xl[kk][0]);
        bsplit2(v1[0], v1[1], xh[kk][1], xl[kk][1]);
        bsplit2(v0[2], v0[3], xh[kk][2], xl[kk][2]);
        bsplit2(v1[2], v1[3], xh[kk][3], xl[kk][3]);
    }

    // ---- pw3 GEMM
    float d3[8][4];
    #pragma unroll
    for (int n = 0; n < 8; n++) { d3[n][0]=0; d3[n][1]=0; d3[n][2]=0; d3[n][3]=0; }
    #pragma unroll
    for (int kk = 0; kk < 4; kk++)
        #pragma unroll
        for (int n = 0; n < 8; n++) {
            int bb = (n*4 + kk)*32 + lane;
            uint2 bh = W3H[bb];
            uint2 bl = W3L[bb];
            mma16816(d3[n], xh[kk][0], xh[kk][1], xh[kk][2], xh[kk][3], bh.x, bh.y);
            mma16816(d3[n], xl[kk][0], xl[kk][1], xl[kk][2], xl[kk][3], bh.x, bh.y);
            mma16816(d3[n], xh[kk][0], xh[kk][1], xh[kk][2], xh[kk][3], bl.x, bl.y);
        }

    // ---- y = inp + (d3+b3)*beta; stats; y->YS; y-frags
    const float* ib = inp + (size_t)b*C*HW + px0;
    float y0v[16], y1v[16];
    float s0 = 0.f, q0 = 0.f, s1 = 0.f, q1 = 0.f;
    #pragma unroll
    for (int n = 0; n < 8; n++) {
        int oa = n*8 + 2*t;
        float bb0 = B3B[oa], bb1 = B3B[oa+1], bt0 = BETB[oa], bt1 = BETB[oa+1];
        float a0 = ib[(size_t)oa*HW + r0]     + (d3[n][0] + bb0) * bt0;
        float a1 = ib[(size_t)(oa+1)*HW + r0] + (d3[n][1] + bb1) * bt1;
        float a2 = ib[(size_t)oa*HW + r1]     + (d3[n][2] + bb0) * bt0;
        float a3 = ib[(size_t)(oa+1)*HW + r1] + (d3[n][3] + bb1) * bt1;
        y0v[n*2] = a0; y0v[n*2+1] = a1; y1v[n*2] = a2; y1v[n*2+1] = a3;
        s0 += a0 + a1; q0 += a0*a0 + a1*a1;
        s1 += a2 + a3; q1 += a2*a2 + a3*a3;
        float2 p0; p0.x = a0; p0.y = a1;
        float2 p1; p1.x = a2; p1.y = a3;
        *(float2*)&YS[r0*72 + oa] = p0;
        *(float2*)&YS[r1*72 + oa] = p1;
    }
    #pragma unroll
    for (int off = 1; off < 4; off <<= 1) {
        s0 += __shfl_xor_sync(0xffffffffu, s0, off);
        q0 += __shfl_xor_sync(0xffffffffu, q0, off);
        s1 += __shfl_xor_sync(0xffffffffu, s1, off);
        q1 += __shfl_xor_sync(0xffffffffu, q1, off);
    }
    float mu0 = s0*(1.f/64), mu1 = s1*(1.f/64);
    float rs0 = rsqrtf(q0*(1.f/64) - mu0*mu0 + EPS);
    float rs1 = rsqrtf(q1*(1.f/64) - mu1*mu1 + EPS);

    uint32_t yh[4][4], yl[4][4];
    #pragma unroll
    for (int kk = 0; kk < 4; kk++) {
        bsplit2(y0v[4*kk],   y0v[4*kk+1], yh[kk][0], yl[kk][0]);
        bsplit2(y1v[4*kk],   y1v[4*kk+1], yh[kk][1], yl[kk][1]);
        bsplit2(y0v[4*kk+2], y0v[4*kk+3], yh[kk][2], yl[kk][2]);
        bsplit2(y1v[4*kk+2], y1v[4*kk+3], yh[kk][3], yl[kk][3]);
    }

    CP_WAIT(0);
    __syncthreads();

    // ---- pw4 GEMM (ln2 folded)
    float d4[16][4];
    #pragma unroll
    for (int n = 0; n < 16; n++) { d4[n][0]=0; d4[n][1]=0; d4[n][2]=0; d4[n][3]=0; }
    #pragma unroll
    for (int kk = 0; kk < 4; kk++)
        #pragma unroll
        for (int n = 0; n < 16; n++) {
            int bb = (n*4 + kk)*32 + lane;
            uint2 bh = W4H[bb];
            uint2 bl = W4L[bb];
            mma16816(d4[n], yh[kk][0], yh[kk][1], yh[kk][2], yh[kk][3], bh.x, bh.y);
            mma16816(d4[n], yl[kk][0], yl[kk][1], yl[kk][2], yl[kk][3], bh.x, bh.y);
            mma16816(d4[n], yh[kk][0], yh[kk][1], yh[kk][2], yh[kk][3], bl.x, bl.y);
        }

    // ---- gate + LN-unfold in registers -> pw5 A-frags
    float g0v[16], g1v[16];
    #pragma unroll
    for (int n = 0; n < 8; n++) {
        int oa = n*8 + 2*t;
        float s4a0 = S4[oa],    s4a1 = S4[oa+1];
        float s4b0 = S4[oa+64], s4b1 = S4[oa+65];
        float ca0 = C4B[oa],    ca1 = C4B[oa+1];
        float cb0 = C4B[oa+64], cb1 = C4B[oa+65];
        g0v[n*2]   = (rs0*(d4[n][0] - mu0*s4a0) + ca0) * (rs0*(d4[n+8][0] - mu0*s4b0) + cb0);
        g0v[n*2+1] = (rs0*(d4[n][1] - mu0*s4a1) + ca1) * (rs0*(d4[n+8][1] - mu0*s4b1) + cb1);
        g1v[n*2]   = (rs1*(d4[n][2] - mu1*s4a0) + ca0) * (rs1*(d4[n+8][2] - mu1*s4b0) + cb0);
        g1v[n*2+1] = (rs1*(d4[n][3] - mu1*s4a1) + ca1) * (rs1*(d4[n+8][3] - mu1*s4b1) + cb1);
    }
    uint32_t gh[4][4], gl[4][4];
    #pragma unroll
    for (int kk = 0; kk < 4; kk++) {
        bsplit2(g0v[4*kk],   g0v[4*kk+1], gh[kk][0], gl[kk][0]);
        bsplit2(g1v[4*kk],   g1v[4*kk+1], gh[kk][1], gl[kk][1]);
        bsplit2(g0v[4*kk+2], g0v[4*kk+3], gh[kk][2], gl[kk][2]);
        bsplit2(g1v[4*kk+2], g1v[4*kk+3], gh[kk][3], gl[kk][3]);
    }

    // ---- pw5 GEMM
    float d5[8][4];
    #pragma unroll
    for (int n = 0; n < 8; n++) { d5[n][0]=0; d5[n][1]=0; d5[n][2]=0; d5[n][3]=0; }
    #pragma unroll
    for (int kk = 0; kk < 4; kk++)
        #pragma unroll
        for (int n = 0; n < 8; n++) {
            int bb = (n*4 + kk)*32 + lane;
            uint2 bh = W5H[bb];
            uint2 bl = W5L[bb];
            mma16816(d5[n], gh[kk][0], gh[kk][1], gh[kk][2], gh[kk][3], bh.x, bh.y);
            mma16816(d5[n], gl[kk][0], gl[kk][1], gl[kk][2], gl[kk][3], bh.x, bh.y);
            mma16816(d5[n], gh[kk][0], gh[kk][1], gh[kk][2], gh[kk][3], bl.x, bl.y);
        }

    // ---- final: out = y + (d5+b5)*gamma
    float* ob = out + (size_t)b*C*HW + px0;
    #pragma unroll
    for (int n = 0; n < 8; n++) {
        int oa = n*8 + 2*t;
        float bp0 = B5B[oa], bp1 = B5B[oa+1], gp0 = GAMB[oa], gp1 = GAMB[oa+1];
        float2 p0 = *(float2*)&YS[r0*72 + oa];
        float2 p1 = *(float2*)&YS[r1*72 + oa];
        ob[(size_t)oa*HW + r0]     = p0.x + (d5[n][0] + bp0) * gp0;
        ob[(size_t)(oa+1)*HW + r0] = p0.y + (d5[n][1] + bp1) * gp1;
        ob[(size_t)oa*HW + r1]     = p1.x + (d5[n][2] + bp0) * gp0;
        ob[(size_t)(oa+1)*HW + r1] = p1.y + (d5[n][3] + bp1) * gp1;
    }
}

// ---------------- launch ------------------------------------------------------
extern "C" void kernel_launch(void* const* d_in, const int* in_sizes, int n_in,
                              void* d_out, int out_size) {
    const float* inp   = (const float*)d_in[0];
    const float* w1    = (const float*)d_in[1];
    const float* b1    = (const float*)d_in[2];
    const float* w2    = (const float*)d_in[3];
    const float* b2    = (const float*)d_in[4];
    const float* w3    = (const float*)d_in[5];
    const float* b3    = (const float*)d_in[6];
    const float* w4    = (const float*)d_in[7];
    const float* b4    = (const float*)d_in[8];
    const float* w5    = (const float*)d_in[9];
    const float* b5    = (const float*)d_in[10];
    const float* ln1w  = (const float*)d_in[11];
    const float* ln1b  = (const float*)d_in[12];
    const float* ln2w  = (const float*)d_in[13];
    const float* ln2b  = (const float*)d_in[14];
    const float* scaw  = (const float*)d_in[15];
    const float* scab  = (const float*)d_in[16];
    const float* beta  = (const float*)d_in[17];
    const float* gamma = (const float*)d_in[18];
    float* out = (float*)d_out;

    cudaFuncSetAttribute(k1, cudaFuncAttributeMaxDynamicSharedMemorySize, 33792);
    cudaFuncSetAttribute(k2, cudaFuncAttributeMaxDynamicSharedMemorySize, K2_SMEM);

    k_prep<<<4097, 32>>>(w1, w2, w3, w4, w5, ln1w, ln1b, ln2w, ln2b);
    k1 <<<dim3(HW/128, B), 256, 33792>>>(inp, b1);
    kdw<<<dim3(IW/32, IH/32, B*C), 256>>>(b2);
    k2 <<<dim3(HW/128, B), 256, K2_SMEM>>>(inp, b3, b4, b5, beta, gamma, scaw, scab, out);
}

// round 14
// speedup vs baseline: 1.8883x; 1.1161x over previous
#include <cuda_runtime.h>
#include <cuda_bf16.h>
#include <cuda_fp16.h>
#include <cstdint>
#include <math.h>

#define B   8
#define C   64
#define DW  128
#define IH  256
#define IW  256
#define HW  65536
#define EPS 1e-6f

// ---------- bf16 split helper ----------
__device__ __forceinline__ void bsplit2(float f0, float f1, uint32_t& h, uint32_t& l) {
    __nv_bfloat16 h0 = __float2bfloat16(f0), h1 = __float2bfloat16(f1);
    float r0 = f0 - __bfloat162float(h0), r1 = f1 - __bfloat162float(h1);
    __nv_bfloat16 l0 = __float2bfloat16(r0), l1 = __float2bfloat16(r1);
    h = (uint32_t)__bfloat16_as_ushort(h0) | ((uint32_t)__bfloat16_as_ushort(h1) << 16);
    l = (uint32_t)__bfloat16_as_ushort(l0) | ((uint32_t)__bfloat16_as_ushort(l1) << 16);
}

// ---------- mma.sync m16n8k16 bf16 ----------
__device__ __forceinline__ void mma16816(float* d,
        uint32_t a0, uint32_t a1, uint32_t a2, uint32_t a3,
        uint32_t b0, uint32_t b1) {
    asm volatile("mma.sync.aligned.m16n8k16.row.col.f32.bf16.bf16.f32 "
        "{%0,%1,%2,%3}, {%4,%5,%6,%7}, {%8,%9}, {%0,%1,%2,%3};"
        : "+f"(d[0]), "+f"(d[1]), "+f"(d[2]), "+f"(d[3])
        : "r"(a0), "r"(a1), "r"(a2), "r"(a3), "r"(b0), "r"(b1));
}

// ---------- cp.async ----------
__device__ __forceinline__ uint32_t smem_u32(const void* p) {
    uint32_t a;
    asm("{ .reg .u64 t; cvta.to.shared.u64 t, %1; cvt.u32.u64 %0, t; }" : "=r"(a) : "l"(p));
    return a;
}
__device__ __forceinline__ void cpasync16(uint32_t s, const void* g) {
    asm volatile("cp.async.ca.shared.global [%0], [%1], 16;" :: "r"(s), "l"(g) : "memory");
}
#define CP_COMMIT() asm volatile("cp.async.commit_group;" ::: "memory")
#define CP_WAIT(n)  asm volatile("cp.async.wait_group %0;" :: "n"(n) : "memory")

// ---------------- device scratch ----------------------------------------------
__device__ __align__(16) uint2 g_w1f_h[B*2048], g_w1f_l[B*2048];
__device__ float g_s1 [B*DW];
__device__ float g_c1 [B*DW];
__device__ float g_w2 [B*DW*9];
__device__ __align__(16) uint2 g_w3f_h[B*1024], g_w3f_l[B*1024];
__device__ __align__(16) uint2 g_w4f_h[B*2048], g_w4f_l[B*2048];
__device__ float g_s4 [B*DW];
__device__ float g_c4 [B*DW];
__device__ __align__(16) uint2 g_w5f_h[B*1024], g_w5f_l[B*1024];
__device__ __half2 g_t1p[(size_t)B*64*HW];   // t1 channel-pair planes (2c,2c+1)
__device__ __half2 g_t2p[(size_t)B*32*HW];   // t2 channel-pair planes
__device__ float g_pool[B*C];

// ---------------- prep (unchanged from R13) -----------------------------------
__global__ void k_prep(const float* __restrict__ w1, const float* __restrict__ w2,
                       const float* __restrict__ w3, const float* __restrict__ w4,
                       const float* __restrict__ w5,
                       const float* __restrict__ ln1w, const float* __restrict__ ln1b,
                       const float* __restrict__ ln2w, const float* __restrict__ ln2b) {
    int blk = blockIdx.x, t = threadIdx.x;
    if (blk >= 4096) { for (int i = t; i < B*C; i += 32) g_pool[i] = 0.f; return; }

    if (blk < 1024 || (blk >= 2560 && blk < 3584)) {
        bool is1 = (blk < 1024);
        int r = is1 ? blk : blk - 2560;
        const float* src = (is1 ? w1 : w4) + r*64;
        const float* lw = is1 ? ln1w : ln2w;
        const float* lb = is1 ? ln1b : ln2b;
        int b = r >> 7, o = r & 127;
        int n = o >> 3, g = o & 7;
        float sq = 0.f;
        for (int i = t; i < 64; i += 32) { float v = src[i]; sq += v*v; }
        #pragma unroll
        for (int off = 16; off; off >>= 1) sq += __shfl_xor_sync(0xffffffffu, sq, off);
        float rn = 1.0f / sqrtf(sq);
        float s = 0.f, cx = 0.f;
        for (int i = t; i < 64; i += 32) {
            float wn = src[i] * rn;
            s += wn * lw[i]; cx += wn * lb[i];
        }
        #pragma unroll
        for (int off = 16; off; off >>= 1) {
            s  += __shfl_xor_sync(0xffffffffu, s,  off);
            cx += __shfl_xor_sync(0xffffffffu, cx, off);
        }
        if (t == 0) {
            if (is1) { g_s1[r] = s; g_c1[r] = cx; }
            else     { g_s4[r] = s; g_c4[r] = cx; }
        }
        if (t < 16) {
            int kk = t >> 2, tt = t & 3;
            int k0 = kk*16 + 2*tt;
            float f0 = src[k0]   * rn * lw[k0];
            float f1 = src[k0+1] * rn * lw[k0+1];
            float f2 = src[k0+8] * rn * lw[k0+8];
            float f3 = src[k0+9] * rn * lw[k0+9];
            uint32_t h0, l0, h1, l1;
            bsplit2(f0, f1, h0, l0);
            bsplit2(f2, f3, h1, l1);
            int idx = b*2048 + (n*4 + kk)*32 + g*4 + tt;
            uint2 vh; vh.x = h0; vh.y = h1;
            uint2 vl; vl.x = l0; vl.y = l1;
            if (is1) { g_w1f_h[idx] = vh; g_w1f_l[idx] = vl; }
            else     { g_w4f_h[idx] = vh; g_w4f_l[idx] = vl; }
        }
        return;
    }
    if (blk < 2048) {
        int r = blk - 1024;
        const float* src = w2 + r*9;
        float sq = 0.f;
        for (int i = t; i < 9; i += 32) { float v = src[i]; sq += v*v; }
        #pragma unroll
        for (int off = 16; off; off >>= 1) sq += __shfl_xor_sync(0xffffffffu, sq, off);
        float rn = 1.0f / sqrtf(sq);
        for (int i = t; i < 9; i += 32) g_w2[r*9 + i] = src[i] * rn;
        return;
    }
    bool is3 = (blk < 2560);
    int r = is3 ? (blk - 2048) : (blk - 3584);
    const float* src = (is3 ? w3 : w5) + r*64;
    int b = r >> 6, o = r & 63;
    int n = o >> 3, g = o & 7;
    float sq = 0.f;
    for (int i = t; i < 64; i += 32) { float v = src[i]; sq += v*v; }
    #pragma unroll
    for (int off = 16; off; off >>= 1) sq += __shfl_xor_sync(0xffffffffu, sq, off);
    float rn = 1.0f / sqrtf(sq);
    if (t < 16) {
        int kk = t >> 2, tt = t & 3;
        int k0 = kk*16 + 2*tt;
        uint32_t h0, l0, h1, l1;
        bsplit2(src[k0]*rn,   src[k0+1]*rn, h0, l0);
        bsplit2(src[k0+8]*rn, src[k0+9]*rn, h1, l1);
        int idx = b*1024 + (n*4 + kk)*32 + g*4 + tt;
        uint2 vh; vh.x = h0; vh.y = h1;
        uint2 vl; vl.x = l0; vl.y = l1;
        if (is3) { g_w3f_h[idx] = vh; g_w3f_l[idx] = vl; }
        else     { g_w5f_h[idx] = vh; g_w5f_l[idx] = vl; }
    }
}

// ---------------- K1: HMMA LN1(folded)+pw1, half2-pair output -----------------
__global__ void __launch_bounds__(256, 2) k1(const float* __restrict__ inp,
                                             const float* __restrict__ b1) {
    extern __shared__ __align__(16) char smem[];
    uint2* W1H = (uint2*)smem;
    uint2* W1L = (uint2*)(smem + 16384);
    float* S1B = (float*)(smem + 32768);
    float* C1B = (float*)(smem + 33280);
    int b = blockIdx.y, px0 = blockIdx.x * 128;
    int tid = threadIdx.x, lane = tid & 31, warp = tid >> 5;
    int g = lane >> 2, t = lane & 3;
    int m0 = warp * 16;
    int r0 = m0 + g, r1 = m0 + g + 8;

    {
        uint32_t sh = smem_u32(W1H), sl = smem_u32(W1L);
        const char* gh = (const char*)(g_w1f_h + b*2048);
        const char* gl = (const char*)(g_w1f_l + b*2048);
        for (int i = tid; i < 1024; i += 256) {
            cpasync16(sh + i*16, gh + i*16);
            cpasync16(sl + i*16, gl + i*16);
        }
        CP_COMMIT();
    }
    if (tid < 128) { S1B[tid] = g_s1[b*DW + tid]; C1B[tid] = g_c1[b*DW + tid] + b1[b*DW + tid]; }

    const float* ip = inp + (size_t)b*C*HW + px0;
    float xv0[16], xv1[16];
    float s0 = 0.f, q0 = 0.f, s1 = 0.f, q1 = 0.f;
    #pragma unroll
    for (int kk = 0; kk < 4; kk++)
        #pragma unroll
        for (int j = 0; j < 4; j++) {
            int ch = kk*16 + ((j < 2) ? (2*t + j) : (2*t + 8 + (j - 2)));
            float v0 = ip[(size_t)ch*HW + r0];
            float v1 = ip[(size_t)ch*HW + r1];
            xv0[kk*4 + j] = v0; xv1[kk*4 + j] = v1;
            s0 += v0; q0 += v0*v0; s1 += v1; q1 += v1*v1;
        }
    #pragma unroll
    for (int off = 1; off < 4; off <<= 1) {
        s0 += __shfl_xor_sync(0xffffffffu, s0, off);
        q0 += __shfl_xor_sync(0xffffffffu, q0, off);
        s1 += __shfl_xor_sync(0xffffffffu, s1, off);
        q1 += __shfl_xor_sync(0xffffffffu, q1, off);
    }
    float mu0 = s0*(1.f/64), mu1 = s1*(1.f/64);
    float rs0 = rsqrtf(q0*(1.f/64) - mu0*mu0 + EPS);
    float rs1 = rsqrtf(q1*(1.f/64) - mu1*mu1 + EPS);

    uint32_t ah[4][4], al[4][4];
    #pragma unroll
    for (int kk = 0; kk < 4; kk++) {
        bsplit2(xv0[kk*4+0], xv0[kk*4+1], ah[kk][0], al[kk][0]);
        bsplit2(xv1[kk*4+0], xv1[kk*4+1], ah[kk][1], al[kk][1]);
        bsplit2(xv0[kk*4+2], xv0[kk*4+3], ah[kk][2], al[kk][2]);
        bsplit2(xv1[kk*4+2], xv1[kk*4+3], ah[kk][3], al[kk][3]);
    }

    CP_WAIT(0);
    __syncthreads();

    float d[16][4];
    #pragma unroll
    for (int n = 0; n < 16; n++) { d[n][0]=0; d[n][1]=0; d[n][2]=0; d[n][3]=0; }
    #pragma unroll
    for (int kk = 0; kk < 4; kk++)
        #pragma unroll
        for (int n = 0; n < 16; n++) {
            int bb = (n*4 + kk)*32 + lane;
            uint2 bh = W1H[bb];
            uint2 bl = W1L[bb];
            mma16816(d[n], ah[kk][0], ah[kk][1], ah[kk][2], ah[kk][3], bh.x, bh.y);
            mma16816(d[n], al[kk][0], al[kk][1], al[kk][2], al[kk][3], bh.x, bh.y);
            mma16816(d[n], ah[kk][0], ah[kk][1], ah[kk][2], ah[kk][3], bl.x, bl.y);
        }

    // half2 channel-pair stores: pair index = oa/2 = n*4 + t
    __half2* op = g_t1p + (size_t)b*64*HW + px0;
    #pragma unroll
    for (int n = 0; n < 16; n++) {
        int oa = n*8 + 2*t;
        int pr = n*4 + t;
        float S0 = S1B[oa], Sv1 = S1B[oa+1], Cc0 = C1B[oa], Cc1 = C1B[oa+1];
        op[(size_t)pr*HW + r0] = __floats2half2_rn(rs0*(d[n][0] - mu0*S0) + Cc0,
                                                   rs0*(d[n][1] - mu0*Sv1) + Cc1);
        op[(size_t)pr*HW + r1] = __floats2half2_rn(rs1*(d[n][2] - mu1*S0) + Cc0,
                                                   rs1*(d[n][3] - mu1*Sv1) + Cc1);
    }
}

// ---------------- K_dw: channel-pair depthwise 3x3 + gate + pool --------------
__global__ void __launch_bounds__(256) kdw(const float* __restrict__ b2) {
    int bc = blockIdx.z; int b = bc >> 5; int cp = bc & 31;
    __shared__ float2 s1[34][36];
    __shared__ float2 s2[34][36];
    __shared__ float wA[2][9], wB[2][9], bb4[4];
    __shared__ float2 red[8];

    const __half2* in1 = g_t1p + ((size_t)b*64 + cp)      * HW;   // channels (2cp, 2cp+1)
    const __half2* in2 = g_t1p + ((size_t)b*64 + cp + 32) * HW;   // channels (2cp+64, 2cp+65)
    int x0 = blockIdx.x * 32, y0 = blockIdx.y * 32;

    for (int i = threadIdx.x; i < 34*34; i += 256) {
        int ly = i / 34, lx = i % 34;
        int gy = y0 + ly - 1, gx = x0 + lx - 1;
        bool ok = (gy >= 0 && gy < IH && gx >= 0 && gx < IW);
        float2 v1 = ok ? __half22float2(in1[gy*IW + gx]) : make_float2(0.f, 0.f);
        float2 v2 = ok ? __half22float2(in2[gy*IW + gx]) : make_float2(0.f, 0.f);
        s1[ly][lx] = v1;
        s2[ly][lx] = v2;
    }
    if (threadIdx.x < 18) {
        int u = threadIdx.x;
        wA[u/9][u%9] = g_w2[((size_t)b*DW + 2*cp + u/9)*9 + u%9];
    } else if (threadIdx.x < 36) {
        int u = threadIdx.x - 18;
        wB[u/9][u%9] = g_w2[((size_t)b*DW + 64 + 2*cp + u/9)*9 + u%9];
    } else if (threadIdx.x < 40) {
        int u = threadIdx.x - 36;
        bb4[u] = b2[b*DW + ((u < 2) ? (2*cp + u) : (64 + 2*cp + u - 2))];
    }
    __syncthreads();

    int lx = threadIdx.x & 31, ly0 = (threadIdx.x >> 5) * 4;
    __half2* ob = g_t2p + ((size_t)b*32 + cp)*HW;
    float ps0 = 0.f, ps1 = 0.f;
    #pragma unroll
    for (int r = 0; r < 4; r++) {
        int ly = ly0 + r;
        float a0 = bb4[0], a1 = bb4[1], d0 = bb4[2], d1 = bb4[3];
        #pragma unroll
        for (int ky = 0; ky < 3; ky++)
            #pragma unroll
            for (int kx = 0; kx < 3; kx++) {
                float2 v1 = s1[ly + ky][lx + kx];
                float2 v2 = s2[ly + ky][lx + kx];
                a0 += wA[0][ky*3 + kx] * v1.x;
                a1 += wA[1][ky*3 + kx] * v1.y;
                d0 += wB[0][ky*3 + kx] * v2.x;
                d1 += wB[1][ky*3 + kx] * v2.y;
            }
        float g0 = a0 * d0, g1 = a1 * d1;
        ob[(y0 + ly)*IW + (x0 + lx)] = __floats2half2_rn(g0, g1);
        ps0 += g0; ps1 += g1;
    }
    #pragma unroll
    for (int off = 16; off; off >>= 1) {
        ps0 += __shfl_down_sync(0xffffffffu, ps0, off);
        ps1 += __shfl_down_sync(0xffffffffu, ps1, off);
    }
    if (lx == 0) { red[threadIdx.x >> 5] = make_float2(ps0, ps1); }
    __syncthreads();
    if (threadIdx.x == 0) {
        float t0 = 0.f, t1 = 0.f;
        #pragma unroll
        for (int i = 0; i < 8; i++) { t0 += red[i].x; t1 += red[i].y; }
        atomicAdd(&g_pool[b*C + 2*cp],     t0);
        atomicAdd(&g_pool[b*C + 2*cp + 1], t1);
    }
}

// ---------------- K2: fused HMMA, half2 t2 gather -----------------------------
#define KO_W3H 0
#define KO_W3L 8192
#define KO_W4H 16384
#define KO_W4L 32768
#define KO_W5H 49152
#define KO_W5L 57344
#define KO_YS  65536
#define KO_S4  102400
#define KO_C4  102912
#define KO_B3  103424
#define KO_BT  103680
#define KO_B5  103936
#define KO_GM  104192
#define KO_SC  104448
#define KO_PL  104704
#define K2_SMEM 104960

__global__ void __launch_bounds__(256, 2) k2(const float* __restrict__ inp,
                                             const float* __restrict__ b3,
                                             const float* __restrict__ b4,
                                             const float* __restrict__ b5,
                                             const float* __restrict__ beta,
                                             const float* __restrict__ gamma,
                                             const float* __restrict__ sca_w,
                                             const float* __restrict__ sca_b,
                                             float* __restrict__ out) {
    extern __shared__ __align__(16) char smem[];
    uint2* W3H = (uint2*)(smem + KO_W3H);
    uint2* W3L = (uint2*)(smem + KO_W3L);
    uint2* W4H = (uint2*)(smem + KO_W4H);
    uint2* W4L = (uint2*)(smem + KO_W4L);
    uint2* W5H = (uint2*)(smem + KO_W5H);
    uint2* W5L = (uint2*)(smem + KO_W5L);
    float* YS  = (float*)(smem + KO_YS);
    float* S4  = (float*)(smem + KO_S4);
    float* C4B = (float*)(smem + KO_C4);
    float* B3B = (float*)(smem + KO_B3);
    float* BETB= (float*)(smem + KO_BT);
    float* B5B = (float*)(smem + KO_B5);
    float* GAMB= (float*)(smem + KO_GM);
    float* SCS = (float*)(smem + KO_SC);
    float* PLS = (float*)(smem + KO_PL);

    int b = blockIdx.y, px0 = blockIdx.x * 128;
    int tid = threadIdx.x, lane = tid & 31, warp = tid >> 5;
    int g = lane >> 2, t = lane & 3;
    int m0 = warp * 16;
    int r0 = m0 + g, r1 = m0 + g + 8;

    {
        uint32_t s3h = smem_u32(W3H), s3l = smem_u32(W3L);
        const char* g3h = (const char*)(g_w3f_h + b*1024);
        const char* g3l = (const char*)(g_w3f_l + b*1024);
        for (int i = tid; i < 512; i += 256) {
            cpasync16(s3h + i*16, g3h + i*16);
            cpasync16(s3l + i*16, g3l + i*16);
        }
        CP_COMMIT();
        uint32_t s4h = smem_u32(W4H), s4l = smem_u32(W4L);
        const char* g4h = (const char*)(g_w4f_h + b*2048);
        const char* g4l = (const char*)(g_w4f_l + b*2048);
        for (int i = tid; i < 1024; i += 256) {
            cpasync16(s4h + i*16, g4h + i*16);
            cpasync16(s4l + i*16, g4l + i*16);
        }
        uint32_t s5h = smem_u32(W5H), s5l = smem_u32(W5L);
        const char* g5h = (const char*)(g_w5f_h + b*1024);
        const char* g5l = (const char*)(g_w5f_l + b*1024);
        for (int i = tid; i < 512; i += 256) {
            cpasync16(s5h + i*16, g5h + i*16);
            cpasync16(s5l + i*16, g5l + i*16);
        }
        CP_COMMIT();
    }
    if (tid < 64) {
        B3B[tid] = b3[b*64 + tid]; BETB[tid] = beta[tid];
        B5B[tid] = b5[b*64 + tid]; GAMB[tid] = gamma[tid];
        PLS[tid] = g_pool[b*64 + tid] * (1.f/(float)HW);
    } else if (tid < 192) {
        int u = tid - 64;
        S4[u] = g_s4[b*128 + u];
        C4B[u] = g_c4[b*128 + u] + b4[b*128 + u];
    }
    CP_WAIT(1);
    __syncthreads();
    if (tid < 64) {
        float acc = sca_b[tid];
        #pragma unroll 8
        for (int cc = 0; cc < 64; cc++) acc += sca_w[tid*64 + cc] * PLS[cc];
        SCS[tid] = acc;
    }
    __syncthreads();

    // ---- A-frags of X = sca*t2 (half2 pair gather)
    const __half2* t2b = g_t2p + (size_t)b*32*HW + px0;
    uint32_t xh[4][4], xl[4][4];
    #pragma unroll
    for (int kk = 0; kk < 4; kk++) {
        int p0 = kk*8 + t, p1 = kk*8 + 4 + t;
        float2 va0 = __half22float2(t2b[(size_t)p0*HW + r0]);
        float2 va1 = __half22float2(t2b[(size_t)p1*HW + r0]);
        float2 vb0 = __half22float2(t2b[(size_t)p0*HW + r1]);
        float2 vb1 = __half22float2(t2b[(size_t)p1*HW + r1]);
        int c0 = kk*16 + 2*t, c1 = kk*16 + 8 + 2*t;
        float sc0 = SCS[c0], sc1 = SCS[c0+1], sc2 = SCS[c1], sc3 = SCS[c1+1];
        bsplit2(va0.x*sc0, va0.y*sc1, xh[kk][0], xl[kk][0]);
        bsplit2(vb0.x*sc0, vb0.y*sc1, xh[kk][1], xl[kk][1]);
        bsplit2(va1.x*sc2, va1.y*sc3, xh[kk][2], xl[kk][2]);
        bsplit2(vb1.x*sc2, vb1.y*sc3, xh[kk][3], xl[kk][3]);
    }

    // ---- pw3 GEMM
    float d3[8][4];
    #pragma unroll
    for (int n = 0; n < 8; n++) { d3[n][0]=0; d3[n][1]=0; d3[n][2]=0; d3[n][3]=0; }
    #pragma unroll
    for (int kk = 0; kk < 4; kk++)
        #pragma unroll
        for (int n = 0; n < 8; n++) {
            int bb = (n*4 + kk)*32 + lane;
            uint2 bh = W3H[bb];
            uint2 bl = W3L[bb];
            mma16816(d3[n], xh[kk][0], xh[kk][1], xh[kk][2], xh[kk][3], bh.x, bh.y);
            mma16816(d3[n], xl[kk][0], xl[kk][1], xl[kk][2], xl[kk][3], bh.x, bh.y);
            mma16816(d3[n], xh[kk][0], xh[kk][1], xh[kk][2], xh[kk][3], bl.x, bl.y);
        }

    // ---- y = inp + (d3+b3)*beta; stats; y->YS; y-frags
    const float* ib = inp + (size_t)b*C*HW + px0;
    float y0v[16], y1v[16];
    float s0 = 0.f, q0 = 0.f, s1 = 0.f, q1 = 0.f;
    #pragma unroll
    for (int n = 0; n < 8; n++) {
        int oa = n*8 + 2*t;
        float bb0 = B3B[oa], bb1 = B3B[oa+1], bt0 = BETB[oa], bt1 = BETB[oa+1];
        float a0 = ib[(size_t)oa*HW + r0]     + (d3[n][0] + bb0) * bt0;
        float a1 = ib[(size_t)(oa+1)*HW + r0] + (d3[n][1] + bb1) * bt1;
        float a2 = ib[(size_t)oa*HW + r1]     + (d3[n][2] + bb0) * bt0;
        float a3 = ib[(size_t)(oa+1)*HW + r1] + (d3[n][3] + bb1) * bt1;
        y0v[n*2] = a0; y0v[n*2+1] = a1; y1v[n*2] = a2; y1v[n*2+1] = a3;
        s0 += a0 + a1; q0 += a0*a0 + a1*a1;
        s1 += a2 + a3; q1 += a2*a2 + a3*a3;
        float2 p0; p0.x = a0; p0.y = a1;
        float2 p1; p1.x = a2; p1.y = a3;
        *(float2*)&YS[r0*72 + oa] = p0;
        *(float2*)&YS[r1*72 + oa] = p1;
    }
    #pragma unroll
    for (int off = 1; off < 4; off <<= 1) {
        s0 += __shfl_xor_sync(0xffffffffu, s0, off);
        q0 += __shfl_xor_sync(0xffffffffu, q0, off);
        s1 += __shfl_xor_sync(0xffffffffu, s1, off);
        q1 += __shfl_xor_sync(0xffffffffu, q1, off);
    }
    float mu0 = s0*(1.f/64), mu1 = s1*(1.f/64);
    float rs0 = rsqrtf(q0*(1.f/64) - mu0*mu0 + EPS);
    float rs1 = rsqrtf(q1*(1.f/64) - mu1*mu1 + EPS);

    uint32_t yh[4][4], yl[4][4];
    #pragma unroll
    for (int kk = 0; kk < 4; kk++) {
        bsplit2(y0v[4*kk],   y0v[4*kk+1], yh[kk][0], yl[kk][0]);
        bsplit2(y1v[4*kk],   y1v[4*kk+1], yh[kk][1], yl[kk][1]);
        bsplit2(y0v[4*kk+2], y0v[4*kk+3], yh[kk][2], yl[kk][2]);
        bsplit2(y1v[4*kk+2], y1v[4*kk+3], yh[kk][3], yl[kk][3]);
    }

    CP_WAIT(0);
    __syncthreads();

    // ---- pw4 GEMM (ln2 folded)
    float d4[16][4];
    #pragma unroll
    for (int n = 0; n < 16; n++) { d4[n][0]=0; d4[n][1]=0; d4[n][2]=0; d4[n][3]=0; }
    #pragma unroll
    for (int kk = 0; kk < 4; kk++)
        #pragma unroll
        for (int n = 0; n < 16; n++) {
            int bb = (n*4 + kk)*32 + lane;
            uint2 bh = W4H[bb];
            uint2 bl = W4L[bb];
            mma16816(d4[n], yh[kk][0], yh[kk][1], yh[kk][2], yh[kk][3], bh.x, bh.y);
            mma16816(d4[n], yl[kk][0], yl[kk][1], yl[kk][2], yl[kk][3], bh.x, bh.y);
            mma16816(d4[n], yh[kk][0], yh[kk][1], yh[kk][2], yh[kk][3], bl.x, bl.y);
        }

    // ---- gate + LN-unfold -> pw5 A-frags
    float g0v[16], g1v[16];
    #pragma unroll
    for (int n = 0; n < 8; n++) {
        int oa = n*8 + 2*t;
        float s4a0 = S4[oa],    s4a1 = S4[oa+1];
        float s4b0 = S4[oa+64], s4b1 = S4[oa+65];
        float ca0 = C4B[oa],    ca1 = C4B[oa+1];
        float cb0 = C4B[oa+64], cb1 = C4B[oa+65];
        g0v[n*2]   = (rs0*(d4[n][0] - mu0*s4a0) + ca0) * (rs0*(d4[n+8][0] - mu0*s4b0) + cb0);
        g0v[n*2+1] = (rs0*(d4[n][1] - mu0*s4a1) + ca1) * (rs0*(d4[n+8][1] - mu0*s4b1) + cb1);
        g1v[n*2]   = (rs1*(d4[n][2] - mu1*s4a0) + ca0) * (rs1*(d4[n+8][2] - mu1*s4b0) + cb0);
        g1v[n*2+1] = (rs1*(d4[n][3] - mu1*s4a1) + ca1) * (rs1*(d4[n+8][3] - mu1*s4b1) + cb1);
    }
    uint32_t gh[4][4], gl[4][4];
    #pragma unroll
    for (int kk = 0; kk < 4; kk++) {
        bsplit2(g0v[4*kk],   g0v[4*kk+1], gh[kk][0], gl[kk][0]);
        bsplit2(g1v[4*kk],   g1v[4*kk+1], gh[kk][1], gl[kk][1]);
        bsplit2(g0v[4*kk+2], g0v[4*kk+3], gh[kk][2], gl[kk][2]);
        bsplit2(g1v[4*kk+2], g1v[4*kk+3], gh[kk][3], gl[kk][3]);
    }

    // ---- pw5 GEMM
    float d5[8][4];
    #pragma unroll
    for (int n = 0; n < 8; n++) { d5[n][0]=0; d5[n][1]=0; d5[n][2]=0; d5[n][3]=0; }
    #pragma unroll
    for (int kk = 0; kk < 4; kk++)
        #pragma unroll
        for (int n = 0; n < 8; n++) {
            int bb = (n*4 + kk)*32 + lane;
            uint2 bh = W5H[bb];
            uint2 bl = W5L[bb];
            mma16816(d5[n], gh[kk][0], gh[kk][1], gh[kk][2], gh[kk][3], bh.x, bh.y);
            mma16816(d5[n], gl[kk][0], gl[kk][1], gl[kk][2], gl[kk][3], bh.x, bh.y);
            mma16816(d5[n], gh[kk][0], gh[kk][1], gh[kk][2], gh[kk][3], bl.x, bl.y);
        }

    // ---- final: out = y + (d5+b5)*gamma
    float* ob = out + (size_t)b*C*HW + px0;
    #pragma unroll
    for (int n = 0; n < 8; n++) {
        int oa = n*8 + 2*t;
        float bp0 = B5B[oa], bp1 = B5B[oa+1], gp0 = GAMB[oa], gp1 = GAMB[oa+1];
        float2 p0 = *(float2*)&YS[r0*72 + oa];
        float2 p1 = *(float2*)&YS[r1*72 + oa];
        ob[(size_t)oa*HW + r0]     = p0.x + (d5[n][0] + bp0) * gp0;
        ob[(size_t)(oa+1)*HW + r0] = p0.y + (d5[n][1] + bp1) * gp1;
        ob[(size_t)oa*HW + r1]     = p1.x + (d5[n][2] + bp0) * gp0;
        ob[(size_t)(oa+1)*HW + r1] = p1.y + (d5[n][3] + bp1) * gp1;
    }
}

// ---------------- launch ------------------------------------------------------
extern "C" void kernel_launch(void* const* d_in, const int* in_sizes, int n_in,
                              void* d_out, int out_size) {
    const float* inp   = (const float*)d_in[0];
    const float* w1    = (const float*)d_in[1];
    const float* b1    = (const float*)d_in[2];
    const float* w2    = (const float*)d_in[3];
    const float* b2    = (const float*)d_in[4];
    const float* w3    = (const float*)d_in[5];
    const float* b3    = (const float*)d_in[6];
    const float* w4    = (const float*)d_in[7];
    const float* b4    = (const float*)d_in[8];
    const float* w5    = (const float*)d_in[9];
    const float* b5    = (const float*)d_in[10];
    const float* ln1w  = (const float*)d_in[11];
    const float* ln1b  = (const float*)d_in[12];
    const float* ln2w  = (const float*)d_in[13];
    const float* ln2b  = (const float*)d_in[14];
    const float* scaw  = (const float*)d_in[15];
    const float* scab  = (const float*)d_in[16];
    const float* beta  = (const float*)d_in[17];
    const float* gamma = (const float*)d_in[18];
    float* out = (float*)d_out;

    cudaFuncSetAttribute(k1, cudaFuncAttributeMaxDynamicSharedMemorySize, 33792);
    cudaFuncSetAttribute(k2, cudaFuncAttributeMaxDynamicSharedMemorySize, K2_SMEM);

    k_prep<<<4097, 32>>>(w1, w2, w3, w4, w5, ln1w, ln1b, ln2w, ln2b);
    k1 <<<dim3(HW/128, B), 256, 33792>>>(inp, b1);
    kdw<<<dim3(IW/32, IH/32, B*32), 256>>>(b2);
    k2 <<<dim3(HW/128, B), 256, K2_SMEM>>>(inp, b3, b4, b5, beta, gamma, scaw, scab, out);
}

// round 15
// speedup vs baseline: 2.2577x; 1.1956x over previous
#include <cuda_runtime.h>
#include <cuda_fp16.h>
#include <cstdint>
#include <math.h>

#define B   8
#define C   64
#define DW  128
#define IH  256
#define IW  256
#define HW  65536
#define EPS 1e-6f

// ---------- fp16 pack helpers ----------
__device__ __forceinline__ uint32_t fh2(float a, float b) {
    __half2 h = __floats2half2_rn(a, b);
    return *(uint32_t*)&h;
}
__device__ __forceinline__ uint32_t h2u(__half2 h) { return *(uint32_t*)&h; }

// ---------- mma.sync m16n8k16 fp16 ----------
__device__ __forceinline__ void mma16816(float* d,
        uint32_t a0, uint32_t a1, uint32_t a2, uint32_t a3,
        uint32_t b0, uint32_t b1) {
    asm volatile("mma.sync.aligned.m16n8k16.row.col.f32.f16.f16.f32 "
        "{%0,%1,%2,%3}, {%4,%5,%6,%7}, {%8,%9}, {%0,%1,%2,%3};"
        : "+f"(d[0]), "+f"(d[1]), "+f"(d[2]), "+f"(d[3])
        : "r"(a0), "r"(a1), "r"(a2), "r"(a3), "r"(b0), "r"(b1));
}

// ---------- cp.async ----------
__device__ __forceinline__ uint32_t smem_u32(const void* p) {
    uint32_t a;
    asm("{ .reg .u64 t; cvta.to.shared.u64 t, %1; cvt.u32.u64 %0, t; }" : "=r"(a) : "l"(p));
    return a;
}
__device__ __forceinline__ void cpasync16(uint32_t s, const void* g) {
    asm volatile("cp.async.ca.shared.global [%0], [%1], 16;" :: "r"(s), "l"(g) : "memory");
}
#define CP_COMMIT() asm volatile("cp.async.commit_group;" ::: "memory")
#define CP_WAIT(n)  asm volatile("cp.async.wait_group %0;" :: "n"(n) : "memory")

// ---------------- device scratch (fp16 frag-ordered weights) ------------------
// frag layout: [(n*4 + kk)*32 + lane] -> uint2{b0,b1} (each a half2)
__device__ __align__(16) uint2 g_w1f[B*2048];
__device__ float g_s1 [B*DW];
__device__ float g_c1 [B*DW];
__device__ float g_w2 [B*DW*9];
__device__ __align__(16) uint2 g_w3f[B*1024];
__device__ __align__(16) uint2 g_w4f[B*2048];
__device__ float g_s4 [B*DW];
__device__ float g_c4 [B*DW];
__device__ __align__(16) uint2 g_w5f[B*1024];
__device__ __half2 g_t1p[(size_t)B*64*HW];
__device__ __half2 g_t2p[(size_t)B*32*HW];
__device__ float g_pool[B*C];

// ---------------- prep --------------------------------------------------------
__global__ void k_prep(const float* __restrict__ w1, const float* __restrict__ w2,
                       const float* __restrict__ w3, const float* __restrict__ w4,
                       const float* __restrict__ w5,
                       const float* __restrict__ ln1w, const float* __restrict__ ln1b,
                       const float* __restrict__ ln2w, const float* __restrict__ ln2b) {
    int blk = blockIdx.x, t = threadIdx.x;
    if (blk >= 4096) { for (int i = t; i < B*C; i += 32) g_pool[i] = 0.f; return; }

    if (blk < 1024 || (blk >= 2560 && blk < 3584)) {
        bool is1 = (blk < 1024);
        int r = is1 ? blk : blk - 2560;
        const float* src = (is1 ? w1 : w4) + r*64;
        const float* lw = is1 ? ln1w : ln2w;
        const float* lb = is1 ? ln1b : ln2b;
        int b = r >> 7, o = r & 127;
        int n = o >> 3, g = o & 7;
        float sq = 0.f;
        for (int i = t; i < 64; i += 32) { float v = src[i]; sq += v*v; }
        #pragma unroll
        for (int off = 16; off; off >>= 1) sq += __shfl_xor_sync(0xffffffffu, sq, off);
        float rn = 1.0f / sqrtf(sq);
        float s = 0.f, cx = 0.f;
        for (int i = t; i < 64; i += 32) {
            float wn = src[i] * rn;
            s += wn * lw[i]; cx += wn * lb[i];
        }
        #pragma unroll
        for (int off = 16; off; off >>= 1) {
            s  += __shfl_xor_sync(0xffffffffu, s,  off);
            cx += __shfl_xor_sync(0xffffffffu, cx, off);
        }
        if (t == 0) {
            if (is1) { g_s1[r] = s; g_c1[r] = cx; }
            else     { g_s4[r] = s; g_c4[r] = cx; }
        }
        if (t < 16) {
            int kk = t >> 2, tt = t & 3;
            int k0 = kk*16 + 2*tt;
            float f0 = src[k0]   * rn * lw[k0];
            float f1 = src[k0+1] * rn * lw[k0+1];
            float f2 = src[k0+8] * rn * lw[k0+8];
            float f3 = src[k0+9] * rn * lw[k0+9];
            int idx = b*2048 + (n*4 + kk)*32 + g*4 + tt;
            uint2 v; v.x = fh2(f0, f1); v.y = fh2(f2, f3);
            if (is1) g_w1f[idx] = v; else g_w4f[idx] = v;
        }
        return;
    }
    if (blk < 2048) {
        int r = blk - 1024;
        const float* src = w2 + r*9;
        float sq = 0.f;
        for (int i = t; i < 9; i += 32) { float v = src[i]; sq += v*v; }
        #pragma unroll
        for (int off = 16; off; off >>= 1) sq += __shfl_xor_sync(0xffffffffu, sq, off);
        float rn = 1.0f / sqrtf(sq);
        for (int i = t; i < 9; i += 32) g_w2[r*9 + i] = src[i] * rn;
        return;
    }
    bool is3 = (blk < 2560);
    int r = is3 ? (blk - 2048) : (blk - 3584);
    const float* src = (is3 ? w3 : w5) + r*64;
    int b = r >> 6, o = r & 63;
    int n = o >> 3, g = o & 7;
    float sq = 0.f;
    for (int i = t; i < 64; i += 32) { float v = src[i]; sq += v*v; }
    #pragma unroll
    for (int off = 16; off; off >>= 1) sq += __shfl_xor_sync(0xffffffffu, sq, off);
    float rn = 1.0f / sqrtf(sq);
    if (t < 16) {
        int kk = t >> 2, tt = t & 3;
        int k0 = kk*16 + 2*tt;
        int idx = b*1024 + (n*4 + kk)*32 + g*4 + tt;
        uint2 v;
        v.x = fh2(src[k0]*rn,   src[k0+1]*rn);
        v.y = fh2(src[k0+8]*rn, src[k0+9]*rn);
        if (is3) g_w3f[idx] = v; else g_w5f[idx] = v;
    }
}

// ---------------- K1: fp16 HMMA LN1(folded)+pw1 -------------------------------
// smem: W1@0 (2048 uint2 = 16384B) S1B@16384(512) C1B@16896(512) = 17408
__global__ void __launch_bounds__(256, 2) k1(const float* __restrict__ inp,
                                             const float* __restrict__ b1) {
    extern __shared__ __align__(16) char smem[];
    uint2* W1 = (uint2*)smem;
    float* S1B = (float*)(smem + 16384);
    float* C1B = (float*)(smem + 16896);
    int b = blockIdx.y, px0 = blockIdx.x * 128;
    int tid = threadIdx.x, lane = tid & 31, warp = tid >> 5;
    int g = lane >> 2, t = lane & 3;
    int m0 = warp * 16;
    int r0 = m0 + g, r1 = m0 + g + 8;

    {
        uint32_t sw = smem_u32(W1);
        const char* gw = (const char*)(g_w1f + b*2048);
        for (int i = tid; i < 1024; i += 256) cpasync16(sw + i*16, gw + i*16);
        CP_COMMIT();
    }
    if (tid < 128) { S1B[tid] = g_s1[b*DW + tid]; C1B[tid] = g_c1[b*DW + tid] + b1[b*DW + tid]; }

    const float* ip = inp + (size_t)b*C*HW + px0;
    float xv0[16], xv1[16];
    float s0 = 0.f, q0 = 0.f, s1 = 0.f, q1 = 0.f;
    #pragma unroll
    for (int kk = 0; kk < 4; kk++)
        #pragma unroll
        for (int j = 0; j < 4; j++) {
            int ch = kk*16 + ((j < 2) ? (2*t + j) : (2*t + 8 + (j - 2)));
            float v0 = ip[(size_t)ch*HW + r0];
            float v1 = ip[(size_t)ch*HW + r1];
            xv0[kk*4 + j] = v0; xv1[kk*4 + j] = v1;
            s0 += v0; q0 += v0*v0; s1 += v1; q1 += v1*v1;
        }
    #pragma unroll
    for (int off = 1; off < 4; off <<= 1) {
        s0 += __shfl_xor_sync(0xffffffffu, s0, off);
        q0 += __shfl_xor_sync(0xffffffffu, q0, off);
        s1 += __shfl_xor_sync(0xffffffffu, s1, off);
        q1 += __shfl_xor_sync(0xffffffffu, q1, off);
    }
    float mu0 = s0*(1.f/64), mu1 = s1*(1.f/64);
    float rs0 = rsqrtf(q0*(1.f/64) - mu0*mu0 + EPS);
    float rs1 = rsqrtf(q1*(1.f/64) - mu1*mu1 + EPS);

    uint32_t ah[4][4];
    #pragma unroll
    for (int kk = 0; kk < 4; kk++) {
        ah[kk][0] = fh2(xv0[kk*4+0], xv0[kk*4+1]);
        ah[kk][1] = fh2(xv1[kk*4+0], xv1[kk*4+1]);
        ah[kk][2] = fh2(xv0[kk*4+2], xv0[kk*4+3]);
        ah[kk][3] = fh2(xv1[kk*4+2], xv1[kk*4+3]);
    }

    CP_WAIT(0);
    __syncthreads();

    float d[16][4];
    #pragma unroll
    for (int n = 0; n < 16; n++) { d[n][0]=0; d[n][1]=0; d[n][2]=0; d[n][3]=0; }
    #pragma unroll
    for (int kk = 0; kk < 4; kk++)
        #pragma unroll
        for (int n = 0; n < 16; n++) {
            uint2 bw = W1[(n*4 + kk)*32 + lane];
            mma16816(d[n], ah[kk][0], ah[kk][1], ah[kk][2], ah[kk][3], bw.x, bw.y);
        }

    __half2* op = g_t1p + (size_t)b*64*HW + px0;
    #pragma unroll
    for (int n = 0; n < 16; n++) {
        int oa = n*8 + 2*t;
        int pr = n*4 + t;
        float S0 = S1B[oa], Sv1 = S1B[oa+1], Cc0 = C1B[oa], Cc1 = C1B[oa+1];
        op[(size_t)pr*HW + r0] = __floats2half2_rn(rs0*(d[n][0] - mu0*S0) + Cc0,
                                                   rs0*(d[n][1] - mu0*Sv1) + Cc1);
        op[(size_t)pr*HW + r1] = __floats2half2_rn(rs1*(d[n][2] - mu1*S0) + Cc0,
                                                   rs1*(d[n][3] - mu1*Sv1) + Cc1);
    }
}

// ---------------- K_dw: channel-pair depthwise 3x3 + gate + pool --------------
__global__ void __launch_bounds__(256) kdw(const float* __restrict__ b2) {
    int bc = blockIdx.z; int b = bc >> 5; int cp = bc & 31;
    __shared__ float2 s1[34][36];
    __shared__ float2 s2[34][36];
    __shared__ float wA[2][9], wB[2][9], bb4[4];
    __shared__ float2 red[8];

    const __half2* in1 = g_t1p + ((size_t)b*64 + cp)      * HW;
    const __half2* in2 = g_t1p + ((size_t)b*64 + cp + 32) * HW;
    int x0 = blockIdx.x * 32, y0 = blockIdx.y * 32;

    for (int i = threadIdx.x; i < 34*34; i += 256) {
        int ly = i / 34, lx = i % 34;
        int gy = y0 + ly - 1, gx = x0 + lx - 1;
        bool ok = (gy >= 0 && gy < IH && gx >= 0 && gx < IW);
        float2 v1 = ok ? __half22float2(in1[gy*IW + gx]) : make_float2(0.f, 0.f);
        float2 v2 = ok ? __half22float2(in2[gy*IW + gx]) : make_float2(0.f, 0.f);
        s1[ly][lx] = v1;
        s2[ly][lx] = v2;
    }
    if (threadIdx.x < 18) {
        int u = threadIdx.x;
        wA[u/9][u%9] = g_w2[((size_t)b*DW + 2*cp + u/9)*9 + u%9];
    } else if (threadIdx.x < 36) {
        int u = threadIdx.x - 18;
        wB[u/9][u%9] = g_w2[((size_t)b*DW + 64 + 2*cp + u/9)*9 + u%9];
    } else if (threadIdx.x < 40) {
        int u = threadIdx.x - 36;
        bb4[u] = b2[b*DW + ((u < 2) ? (2*cp + u) : (64 + 2*cp + u - 2))];
    }
    __syncthreads();

    int lx = threadIdx.x & 31, ly0 = (threadIdx.x >> 5) * 4;
    __half2* ob = g_t2p + ((size_t)b*32 + cp)*HW;
    float ps0 = 0.f, ps1 = 0.f;
    #pragma unroll
    for (int r = 0; r < 4; r++) {
        int ly = ly0 + r;
        float a0 = bb4[0], a1 = bb4[1], d0 = bb4[2], d1 = bb4[3];
        #pragma unroll
        for (int ky = 0; ky < 3; ky++)
            #pragma unroll
            for (int kx = 0; kx < 3; kx++) {
                float2 v1 = s1[ly + ky][lx + kx];
                float2 v2 = s2[ly + ky][lx + kx];
                a0 += wA[0][ky*3 + kx] * v1.x;
                a1 += wA[1][ky*3 + kx] * v1.y;
                d0 += wB[0][ky*3 + kx] * v2.x;
                d1 += wB[1][ky*3 + kx] * v2.y;
            }
        float g0 = a0 * d0, g1 = a1 * d1;
        ob[(y0 + ly)*IW + (x0 + lx)] = __floats2half2_rn(g0, g1);
        ps0 += g0; ps1 += g1;
    }
    #pragma unroll
    for (int off = 16; off; off >>= 1) {
        ps0 += __shfl_down_sync(0xffffffffu, ps0, off);
        ps1 += __shfl_down_sync(0xffffffffu, ps1, off);
    }
    if (lx == 0) { red[threadIdx.x >> 5] = make_float2(ps0, ps1); }
    __syncthreads();
    if (threadIdx.x == 0) {
        float t0 = 0.f, t1 = 0.f;
        #pragma unroll
        for (int i = 0; i < 8; i++) { t0 += red[i].x; t1 += red[i].y; }
        atomicAdd(&g_pool[b*C + 2*cp],     t0);
        atomicAdd(&g_pool[b*C + 2*cp + 1], t1);
    }
}

// ---------------- K2: fused fp16 HMMA ----------------------------------------
// smem: W3@0(8192) W4@8192(16384) W5@24576(8192) YS@32768(36864)
//   S4@69632(512) C4@70144(512) B3@70656(256) BT@70912(256) B5@71168(256)
//   GM@71424(256) SC@71680(256) SCH@71936(128) PL@72064(256)  total 72320
#define KO_W3 0
#define KO_W4 8192
#define KO_W5 24576
#define KO_YS 32768
#define KO_S4 69632
#define KO_C4 70144
#define KO_B3 70656
#define KO_BT 70912
#define KO_B5 71168
#define KO_GM 71424
#define KO_SC 71680
#define KO_SCH 71936
#define KO_PL 72064
#define K2_SMEM 72320

__global__ void __launch_bounds__(256, 2) k2(const float* __restrict__ inp,
                                             const float* __restrict__ b3,
                                             const float* __restrict__ b4,
                                             const float* __restrict__ b5,
                                             const float* __restrict__ beta,
                                             const float* __restrict__ gamma,
                                             const float* __restrict__ sca_w,
                                             const float* __restrict__ sca_b,
                                             float* __restrict__ out) {
    extern __shared__ __align__(16) char smem[];
    uint2* W3 = (uint2*)(smem + KO_W3);
    uint2* W4 = (uint2*)(smem + KO_W4);
    uint2* W5 = (uint2*)(smem + KO_W5);
    float* YS  = (float*)(smem + KO_YS);
    float* S4  = (float*)(smem + KO_S4);
    float* C4B = (float*)(smem + KO_C4);
    float* B3B = (float*)(smem + KO_B3);
    float* BETB= (float*)(smem + KO_BT);
    float* B5B = (float*)(smem + KO_B5);
    float* GAMB= (float*)(smem + KO_GM);
    float* SCS = (float*)(smem + KO_SC);
    __half2* SCH = (__half2*)(smem + KO_SCH);
    float* PLS = (float*)(smem + KO_PL);

    int b = blockIdx.y, px0 = blockIdx.x * 128;
    int tid = threadIdx.x, lane = tid & 31, warp = tid >> 5;
    int g = lane >> 2, t = lane & 3;
    int m0 = warp * 16;
    int r0 = m0 + g, r1 = m0 + g + 8;

    // ---- prefetch: W3 (group 0), W4+W5 (group 1)
    {
        uint32_t s3 = smem_u32(W3);
        const char* g3 = (const char*)(g_w3f + b*1024);
        for (int i = tid; i < 512; i += 256) cpasync16(s3 + i*16, g3 + i*16);
        CP_COMMIT();
        uint32_t s4 = smem_u32(W4);
        const char* g4 = (const char*)(g_w4f + b*2048);
        for (int i = tid; i < 1024; i += 256) cpasync16(s4 + i*16, g4 + i*16);
        uint32_t s5 = smem_u32(W5);
        const char* g5 = (const char*)(g_w5f + b*1024);
        for (int i = tid; i < 512; i += 256) cpasync16(s5 + i*16, g5 + i*16);
        CP_COMMIT();
    }
    if (tid < 64) {
        B3B[tid] = b3[b*64 + tid]; BETB[tid] = beta[tid];
        B5B[tid] = b5[b*64 + tid]; GAMB[tid] = gamma[tid];
        PLS[tid] = g_pool[b*64 + tid] * (1.f/(float)HW);
    } else if (tid < 192) {
        int u = tid - 64;
        S4[u] = g_s4[b*128 + u];
        C4B[u] = g_c4[b*128 + u] + b4[b*128 + u];
    }
    CP_WAIT(1);
    __syncthreads();
    if (tid < 64) {
        float acc = sca_b[tid];
        #pragma unroll 8
        for (int cc = 0; cc < 64; cc++) acc += sca_w[tid*64 + cc] * PLS[cc];
        SCS[tid] = acc;
    }
    __syncthreads();
    if (tid < 32) SCH[tid] = __floats2half2_rn(SCS[2*tid], SCS[2*tid + 1]);
    __syncthreads();

    // ---- A-frags of X = sca*t2 (half2 pair gather, fp16 multiply)
    const __half2* t2b = g_t2p + (size_t)b*32*HW + px0;
    uint32_t xa[4][4];
    #pragma unroll
    for (int kk = 0; kk < 4; kk++) {
        int p0 = kk*8 + t, p1 = kk*8 + 4 + t;
        __half2 sc0 = SCH[p0], sc1 = SCH[p1];
        xa[kk][0] = h2u(__hmul2(t2b[(size_t)p0*HW + r0], sc0));
        xa[kk][1] = h2u(__hmul2(t2b[(size_t)p0*HW + r1], sc0));
        xa[kk][2] = h2u(__hmul2(t2b[(size_t)p1*HW + r0], sc1));
        xa[kk][3] = h2u(__hmul2(t2b[(size_t)p1*HW + r1], sc1));
    }

    // ---- pw3 GEMM
    float d3[8][4];
    #pragma unroll
    for (int n = 0; n < 8; n++) { d3[n][0]=0; d3[n][1]=0; d3[n][2]=0; d3[n][3]=0; }
    #pragma unroll
    for (int kk = 0; kk < 4; kk++)
        #pragma unroll
        for (int n = 0; n < 8; n++) {
            uint2 bw = W3[(n*4 + kk)*32 + lane];
            mma16816(d3[n], xa[kk][0], xa[kk][1], xa[kk][2], xa[kk][3], bw.x, bw.y);
        }

    // ---- y = inp + (d3+b3)*beta; stats; y->YS; y-frags
    const float* ib = inp + (size_t)b*C*HW + px0;
    float y0v[16], y1v[16];
    float s0 = 0.f, q0 = 0.f, s1 = 0.f, q1 = 0.f;
    #pragma unroll
    for (int n = 0; n < 8; n++) {
        int oa = n*8 + 2*t;
        float bb0 = B3B[oa], bb1 = B3B[oa+1], bt0 = BETB[oa], bt1 = BETB[oa+1];
        float a0 = ib[(size_t)oa*HW + r0]     + (d3[n][0] + bb0) * bt0;
        float a1 = ib[(size_t)(oa+1)*HW + r0] + (d3[n][1] + bb1) * bt1;
        float a2 = ib[(size_t)oa*HW + r1]     + (d3[n][2] + bb0) * bt0;
        float a3 = ib[(size_t)(oa+1)*HW + r1] + (d3[n][3] + bb1) * bt1;
        y0v[n*2] = a0; y0v[n*2+1] = a1; y1v[n*2] = a2; y1v[n*2+1] = a3;
        s0 += a0 + a1; q0 += a0*a0 + a1*a1;
        s1 += a2 + a3; q1 += a2*a2 + a3*a3;
        float2 p0; p0.x = a0; p0.y = a1;
        float2 p1; p1.x = a2; p1.y = a3;
        *(float2*)&YS[r0*72 + oa] = p0;
        *(float2*)&YS[r1*72 + oa] = p1;
    }
    #pragma unroll
    for (int off = 1; off < 4; off <<= 1) {
        s0 += __shfl_xor_sync(0xffffffffu, s0, off);
        q0 += __shfl_xor_sync(0xffffffffu, q0, off);
        s1 += __shfl_xor_sync(0xffffffffu, s1, off);
        q1 += __shfl_xor_sync(0xffffffffu, q1, off);
    }
    float mu0 = s0*(1.f/64), mu1 = s1*(1.f/64);
    float rs0 = rsqrtf(q0*(1.f/64) - mu0*mu0 + EPS);
    float rs1 = rsqrtf(q1*(1.f/64) - mu1*mu1 + EPS);

    uint32_t ya[4][4];
    #pragma unroll
    for (int kk = 0; kk < 4; kk++) {
        ya[kk][0] = fh2(y0v[4*kk],   y0v[4*kk+1]);
        ya[kk][1] = fh2(y1v[4*kk],   y1v[4*kk+1]);
        ya[kk][2] = fh2(y0v[4*kk+2], y0v[4*kk+3]);
        ya[kk][3] = fh2(y1v[4*kk+2], y1v[4*kk+3]);
    }

    CP_WAIT(0);
    __syncthreads();

    // ---- pw4 GEMM (ln2 folded)
    float d4[16][4];
    #pragma unroll
    for (int n = 0; n < 16; n++) { d4[n][0]=0; d4[n][1]=0; d4[n][2]=0; d4[n][3]=0; }
    #pragma unroll
    for (int kk = 0; kk < 4; kk++)
        #pragma unroll
        for (int n = 0; n < 16; n++) {
            uint2 bw = W4[(n*4 + kk)*32 + lane];
            mma16816(d4[n], ya[kk][0], ya[kk][1], ya[kk][2], ya[kk][3], bw.x, bw.y);
        }

    // ---- gate + LN-unfold -> pw5 A-frags
    float g0v[16], g1v[16];
    #pragma unroll
    for (int n = 0; n < 8; n++) {
        int oa = n*8 + 2*t;
        float s4a0 = S4[oa],    s4a1 = S4[oa+1];
        float s4b0 = S4[oa+64], s4b1 = S4[oa+65];
        float ca0 = C4B[oa],    ca1 = C4B[oa+1];
        float cb0 = C4B[oa+64], cb1 = C4B[oa+65];
        g0v[n*2]   = (rs0*(d4[n][0] - mu0*s4a0) + ca0) * (rs0*(d4[n+8][0] - mu0*s4b0) + cb0);
        g0v[n*2+1] = (rs0*(d4[n][1] - mu0*s4a1) + ca1) * (rs0*(d4[n+8][1] - mu0*s4b1) + cb1);
        g1v[n*2]   = (rs1*(d4[n][2] - mu1*s4a0) + ca0) * (rs1*(d4[n+8][2] - mu1*s4b0) + cb0);
        g1v[n*2+1] = (rs1*(d4[n][3] - mu1*s4a1) + ca1) * (rs1*(d4[n+8][3] - mu1*s4b1) + cb1);
    }
    uint32_t ga[4][4];
    #pragma unroll
    for (int kk = 0; kk < 4; kk++) {
        ga[kk][0] = fh2(g0v[4*kk],   g0v[4*kk+1]);
        ga[kk][1] = fh2(g1v[4*kk],   g1v[4*kk+1]);
        ga[kk][2] = fh2(g0v[4*kk+2], g0v[4*kk+3]);
        ga[kk][3] = fh2(g1v[4*kk+2], g1v[4*kk+3]);
    }

    // ---- pw5 GEMM
    float d5[8][4];
    #pragma unroll
    for (int n = 0; n < 8; n++) { d5[n][0]=0; d5[n][1]=0; d5[n][2]=0; d5[n][3]=0; }
    #pragma unroll
    for (int kk = 0; kk < 4; kk++)
        #pragma unroll
        for (int n = 0; n < 8; n++) {
            uint2 bw = W5[(n*4 + kk)*32 + lane];
            mma16816(d5[n], ga[kk][0], ga[kk][1], ga[kk][2], ga[kk][3], bw.x, bw.y);
        }

    // ---- final: out = y + (d5+b5)*gamma
    float* ob = out + (size_t)b*C*HW + px0;
    #pragma unroll
    for (int n = 0; n < 8; n++) {
        int oa = n*8 + 2*t;
        float bp0 = B5B[oa], bp1 = B5B[oa+1], gp0 = GAMB[oa], gp1 = GAMB[oa+1];
        float2 p0 = *(float2*)&YS[r0*72 + oa];
        float2 p1 = *(float2*)&YS[r1*72 + oa];
        ob[(size_t)oa*HW + r0]     = p0.x + (d5[n][0] + bp0) * gp0;
        ob[(size_t)(oa+1)*HW + r0] = p0.y + (d5[n][1] + bp1) * gp1;
        ob[(size_t)oa*HW + r1]     = p1.x + (d5[n][2] + bp0) * gp0;
        ob[(size_t)(oa+1)*HW + r1] = p1.y + (d5[n][3] + bp1) * gp1;
    }
}

// ---------------- launch ------------------------------------------------------
extern "C" void kernel_launch(void* const* d_in, const int* in_sizes, int n_in,
                              void* d_out, int out_size) {
    const float* inp   = (const float*)d_in[0];
    const float* w1    = (const float*)d_in[1];
    const float* b1    = (const float*)d_in[2];
    const float* w2    = (const float*)d_in[3];
    const float* b2    = (const float*)d_in[4];
    const float* w3    = (const float*)d_in[5];
    const float* b3    = (const float*)d_in[6];
    const float* w4    = (const float*)d_in[7];
    const float* b4    = (const float*)d_in[8];
    const float* w5    = (const float*)d_in[9];
    const float* b5    = (const float*)d_in[10];
    const float* ln1w  = (const float*)d_in[11];
    const float* ln1b  = (const float*)d_in[12];
    const float* ln2w  = (const float*)d_in[13];
    const float* ln2b  = (const float*)d_in[14];
    const float* scaw  = (const float*)d_in[15];
    const float* scab  = (const float*)d_in[16];
    const float* beta  = (const float*)d_in[17];
    const float* gamma = (const float*)d_in[18];
    float* out = (float*)d_out;

    cudaFuncSetAttribute(k1, cudaFuncAttributeMaxDynamicSharedMemorySize, 17408);
    cudaFuncSetAttribute(k2, cudaFuncAttributeMaxDynamicSharedMemorySize, K2_SMEM);

    k_prep<<<4097, 32>>>(w1, w2, w3, w4, w5, ln1w, ln1b, ln2w, ln2b);
    k1 <<<dim3(HW/128, B), 256, 17408>>>(inp, b1);
    kdw<<<dim3(IW/32, IH/32, B*32), 256>>>(b2);
    k2 <<<dim3(HW/128, B), 256, K2_SMEM>>>(inp, b3, b4, b5, beta, gamma, scaw, scab, out);
}

// round 16
// speedup vs baseline: 2.3083x; 1.0224x over previous
#include <cuda_runtime.h>
#include <cuda_fp16.h>
#include <cstdint>
#include <math.h>

#define B   8
#define C   64
#define DW  128
#define IH  256
#define IW  256
#define HW  65536
#define EPS 1e-6f

// ---------- fp16 pack helpers ----------
__device__ __forceinline__ uint32_t fh2(float a, float b) {
    __half2 h = __floats2half2_rn(a, b);
    return *(uint32_t*)&h;
}
__device__ __forceinline__ uint32_t h2u(__half2 h) { return *(uint32_t*)&h; }

// ---------- mma.sync m16n8k16 fp16 ----------
__device__ __forceinline__ void mma16816(float* d,
        uint32_t a0, uint32_t a1, uint32_t a2, uint32_t a3,
        uint32_t b0, uint32_t b1) {
    asm volatile("mma.sync.aligned.m16n8k16.row.col.f32.f16.f16.f32 "
        "{%0,%1,%2,%3}, {%4,%5,%6,%7}, {%8,%9}, {%0,%1,%2,%3};"
        : "+f"(d[0]), "+f"(d[1]), "+f"(d[2]), "+f"(d[3])
        : "r"(a0), "r"(a1), "r"(a2), "r"(a3), "r"(b0), "r"(b1));
}

// ---------- cp.async ----------
__device__ __forceinline__ uint32_t smem_u32(const void* p) {
    uint32_t a;
    asm("{ .reg .u64 t; cvta.to.shared.u64 t, %1; cvt.u32.u64 %0, t; }" : "=r"(a) : "l"(p));
    return a;
}
__device__ __forceinline__ void cpasync16(uint32_t s, const void* g) {
    asm volatile("cp.async.ca.shared.global [%0], [%1], 16;" :: "r"(s), "l"(g) : "memory");
}
#define CP_COMMIT() asm volatile("cp.async.commit_group;" ::: "memory")
#define CP_WAIT(n)  asm volatile("cp.async.wait_group %0;" :: "n"(n) : "memory")

// ---------------- device scratch ----------------------------------------------
__device__ __align__(16) uint2 g_w1f[B*2048];
__device__ float g_s1 [B*DW];
__device__ float g_c1 [B*DW];
__device__ float g_w2 [B*DW*9];
__device__ __align__(16) uint2 g_w3f[B*1024];
__device__ __align__(16) uint2 g_w4f[B*2048];
__device__ float g_s4 [B*DW];
__device__ float g_c4 [B*DW];
__device__ __align__(16) uint2 g_w5f[B*1024];
__device__ __half2 g_t1p[(size_t)B*64*HW];
__device__ __half2 g_t2p[(size_t)B*32*HW];
__device__ float g_pool[B*C];

// ---------------- prep (unchanged) --------------------------------------------
__global__ void k_prep(const float* __restrict__ w1, const float* __restrict__ w2,
                       const float* __restrict__ w3, const float* __restrict__ w4,
                       const float* __restrict__ w5,
                       const float* __restrict__ ln1w, const float* __restrict__ ln1b,
                       const float* __restrict__ ln2w, const float* __restrict__ ln2b) {
    int blk = blockIdx.x, t = threadIdx.x;
    if (blk >= 4096) { for (int i = t; i < B*C; i += 32) g_pool[i] = 0.f; return; }

    if (blk < 1024 || (blk >= 2560 && blk < 3584)) {
        bool is1 = (blk < 1024);
        int r = is1 ? blk : blk - 2560;
        const float* src = (is1 ? w1 : w4) + r*64;
        const float* lw = is1 ? ln1w : ln2w;
        const float* lb = is1 ? ln1b : ln2b;
        int b = r >> 7, o = r & 127;
        int n = o >> 3, g = o & 7;
        float sq = 0.f;
        for (int i = t; i < 64; i += 32) { float v = src[i]; sq += v*v; }
        #pragma unroll
        for (int off = 16; off; off >>= 1) sq += __shfl_xor_sync(0xffffffffu, sq, off);
        float rn = 1.0f / sqrtf(sq);
        float s = 0.f, cx = 0.f;
        for (int i = t; i < 64; i += 32) {
            float wn = src[i] * rn;
            s += wn * lw[i]; cx += wn * lb[i];
        }
        #pragma unroll
        for (int off = 16; off; off >>= 1) {
            s  += __shfl_xor_sync(0xffffffffu, s,  off);
            cx += __shfl_xor_sync(0xffffffffu, cx, off);
        }
        if (t == 0) {
            if (is1) { g_s1[r] = s; g_c1[r] = cx; }
            else     { g_s4[r] = s; g_c4[r] = cx; }
        }
        if (t < 16) {
            int kk = t >> 2, tt = t & 3;
            int k0 = kk*16 + 2*tt;
            float f0 = src[k0]   * rn * lw[k0];
            float f1 = src[k0+1] * rn * lw[k0+1];
            float f2 = src[k0+8] * rn * lw[k0+8];
            float f3 = src[k0+9] * rn * lw[k0+9];
            int idx = b*2048 + (n*4 + kk)*32 + g*4 + tt;
            uint2 v; v.x = fh2(f0, f1); v.y = fh2(f2, f3);
            if (is1) g_w1f[idx] = v; else g_w4f[idx] = v;
        }
        return;
    }
    if (blk < 2048) {
        int r = blk - 1024;
        const float* src = w2 + r*9;
        float sq = 0.f;
        for (int i = t; i < 9; i += 32) { float v = src[i]; sq += v*v; }
        #pragma unroll
        for (int off = 16; off; off >>= 1) sq += __shfl_xor_sync(0xffffffffu, sq, off);
        float rn = 1.0f / sqrtf(sq);
        for (int i = t; i < 9; i += 32) g_w2[r*9 + i] = src[i] * rn;
        return;
    }
    bool is3 = (blk < 2560);
    int r = is3 ? (blk - 2048) : (blk - 3584);
    const float* src = (is3 ? w3 : w5) + r*64;
    int b = r >> 6, o = r & 63;
    int n = o >> 3, g = o & 7;
    float sq = 0.f;
    for (int i = t; i < 64; i += 32) { float v = src[i]; sq += v*v; }
    #pragma unroll
    for (int off = 16; off; off >>= 1) sq += __shfl_xor_sync(0xffffffffu, sq, off);
    float rn = 1.0f / sqrtf(sq);
    if (t < 16) {
        int kk = t >> 2, tt = t & 3;
        int k0 = kk*16 + 2*tt;
        int idx = b*1024 + (n*4 + kk)*32 + g*4 + tt;
        uint2 v;
        v.x = fh2(src[k0]*rn,   src[k0+1]*rn);
        v.y = fh2(src[k0+8]*rn, src[k0+9]*rn);
        if (is3) g_w3f[idx] = v; else g_w5f[idx] = v;
    }
}

// ---------------- K1: fp16 HMMA, cp.async-staged inp --------------------------
// smem bytes: W1@0(16384) INP@16384(64*132*4=33792) S1B@50176(512) C1B@50688(512) = 51200
#define K1_INP 16384
#define K1_S1  50176
#define K1_C1  50688
#define K1_SMEM 51200

__global__ void __launch_bounds__(256, 2) k1(const float* __restrict__ inp,
                                             const float* __restrict__ b1) {
    extern __shared__ __align__(16) char smem[];
    uint2* W1 = (uint2*)smem;
    float* INP = (float*)(smem + K1_INP);
    float* S1B = (float*)(smem + K1_S1);
    float* C1B = (float*)(smem + K1_C1);
    int b = blockIdx.y, px0 = blockIdx.x * 128;
    int tid = threadIdx.x, lane = tid & 31, warp = tid >> 5;
    int g = lane >> 2, t = lane & 3;
    int m0 = warp * 16;
    int r0 = m0 + g, r1 = m0 + g + 8;

    {
        uint32_t sw = smem_u32(W1);
        const char* gw = (const char*)(g_w1f + b*2048);
        for (int i = tid; i < 1024; i += 256) cpasync16(sw + i*16, gw + i*16);
        uint32_t si = smem_u32(INP);
        const char* gi = (const char*)(inp + (size_t)b*C*HW + px0);
        for (int i = tid; i < 2048; i += 256) {
            int row = i >> 5, col = i & 31;
            cpasync16(si + row*528 + col*16, gi + (size_t)row*HW*4 + col*16);
        }
        CP_COMMIT();
    }
    if (tid < 128) { S1B[tid] = g_s1[b*DW + tid]; C1B[tid] = g_c1[b*DW + tid] + b1[b*DW + tid]; }
    CP_WAIT(0);
    __syncthreads();

    float xv0[16], xv1[16];
    float s0 = 0.f, q0 = 0.f, s1 = 0.f, q1 = 0.f;
    #pragma unroll
    for (int kk = 0; kk < 4; kk++)
        #pragma unroll
        for (int j = 0; j < 4; j++) {
            int ch = kk*16 + ((j < 2) ? (2*t + j) : (2*t + 8 + (j - 2)));
            float v0 = INP[ch*132 + r0];
            float v1 = INP[ch*132 + r1];
            xv0[kk*4 + j] = v0; xv1[kk*4 + j] = v1;
            s0 += v0; q0 += v0*v0; s1 += v1; q1 += v1*v1;
        }
    #pragma unroll
    for (int off = 1; off < 4; off <<= 1) {
        s0 += __shfl_xor_sync(0xffffffffu, s0, off);
        q0 += __shfl_xor_sync(0xffffffffu, q0, off);
        s1 += __shfl_xor_sync(0xffffffffu, s1, off);
        q1 += __shfl_xor_sync(0xffffffffu, q1, off);
    }
    float mu0 = s0*(1.f/64), mu1 = s1*(1.f/64);
    float rs0 = rsqrtf(q0*(1.f/64) - mu0*mu0 + EPS);
    float rs1 = rsqrtf(q1*(1.f/64) - mu1*mu1 + EPS);

    uint32_t ah[4][4];
    #pragma unroll
    for (int kk = 0; kk < 4; kk++) {
        ah[kk][0] = fh2(xv0[kk*4+0], xv0[kk*4+1]);
        ah[kk][1] = fh2(xv1[kk*4+0], xv1[kk*4+1]);
        ah[kk][2] = fh2(xv0[kk*4+2], xv0[kk*4+3]);
        ah[kk][3] = fh2(xv1[kk*4+2], xv1[kk*4+3]);
    }

    float d[16][4];
    #pragma unroll
    for (int n = 0; n < 16; n++) { d[n][0]=0; d[n][1]=0; d[n][2]=0; d[n][3]=0; }
    #pragma unroll
    for (int kk = 0; kk < 4; kk++)
        #pragma unroll
        for (int n = 0; n < 16; n++) {
            uint2 bw = W1[(n*4 + kk)*32 + lane];
            mma16816(d[n], ah[kk][0], ah[kk][1], ah[kk][2], ah[kk][3], bw.x, bw.y);
        }

    __half2* op = g_t1p + (size_t)b*64*HW + px0;
    #pragma unroll
    for (int n = 0; n < 16; n++) {
        int oa = n*8 + 2*t;
        int pr = n*4 + t;
        float S0 = S1B[oa], Sv1 = S1B[oa+1], Cc0 = C1B[oa], Cc1 = C1B[oa+1];
        op[(size_t)pr*HW + r0] = __floats2half2_rn(rs0*(d[n][0] - mu0*S0) + Cc0,
                                                   rs0*(d[n][1] - mu0*Sv1) + Cc1);
        op[(size_t)pr*HW + r1] = __floats2half2_rn(rs1*(d[n][2] - mu1*S0) + Cc0,
                                                   rs1*(d[n][3] - mu1*Sv1) + Cc1);
    }
}

// ---------------- K_dw (unchanged) --------------------------------------------
__global__ void __launch_bounds__(256) kdw(const float* __restrict__ b2) {
    int bc = blockIdx.z; int b = bc >> 5; int cp = bc & 31;
    __shared__ float2 s1[34][36];
    __shared__ float2 s2[34][36];
    __shared__ float wA[2][9], wB[2][9], bb4[4];
    __shared__ float2 red[8];

    const __half2* in1 = g_t1p + ((size_t)b*64 + cp)      * HW;
    const __half2* in2 = g_t1p + ((size_t)b*64 + cp + 32) * HW;
    int x0 = blockIdx.x * 32, y0 = blockIdx.y * 32;

    for (int i = threadIdx.x; i < 34*34; i += 256) {
        int ly = i / 34, lx = i % 34;
        int gy = y0 + ly - 1, gx = x0 + lx - 1;
        bool ok = (gy >= 0 && gy < IH && gx >= 0 && gx < IW);
        float2 v1 = ok ? __half22float2(in1[gy*IW + gx]) : make_float2(0.f, 0.f);
        float2 v2 = ok ? __half22float2(in2[gy*IW + gx]) : make_float2(0.f, 0.f);
        s1[ly][lx] = v1;
        s2[ly][lx] = v2;
    }
    if (threadIdx.x < 18) {
        int u = threadIdx.x;
        wA[u/9][u%9] = g_w2[((size_t)b*DW + 2*cp + u/9)*9 + u%9];
    } else if (threadIdx.x < 36) {
        int u = threadIdx.x - 18;
        wB[u/9][u%9] = g_w2[((size_t)b*DW + 64 + 2*cp + u/9)*9 + u%9];
    } else if (threadIdx.x < 40) {
        int u = threadIdx.x - 36;
        bb4[u] = b2[b*DW + ((u < 2) ? (2*cp + u) : (64 + 2*cp + u - 2))];
    }
    __syncthreads();

    int lx = threadIdx.x & 31, ly0 = (threadIdx.x >> 5) * 4;
    __half2* ob = g_t2p + ((size_t)b*32 + cp)*HW;
    float ps0 = 0.f, ps1 = 0.f;
    #pragma unroll
    for (int r = 0; r < 4; r++) {
        int ly = ly0 + r;
        float a0 = bb4[0], a1 = bb4[1], d0 = bb4[2], d1 = bb4[3];
        #pragma unroll
        for (int ky = 0; ky < 3; ky++)
            #pragma unroll
            for (int kx = 0; kx < 3; kx++) {
                float2 v1 = s1[ly + ky][lx + kx];
                float2 v2 = s2[ly + ky][lx + kx];
                a0 += wA[0][ky*3 + kx] * v1.x;
                a1 += wA[1][ky*3 + kx] * v1.y;
                d0 += wB[0][ky*3 + kx] * v2.x;
                d1 += wB[1][ky*3 + kx] * v2.y;
            }
        float g0 = a0 * d0, g1 = a1 * d1;
        ob[(y0 + ly)*IW + (x0 + lx)] = __floats2half2_rn(g0, g1);
        ps0 += g0; ps1 += g1;
    }
    #pragma unroll
    for (int off = 16; off; off >>= 1) {
        ps0 += __shfl_down_sync(0xffffffffu, ps0, off);
        ps1 += __shfl_down_sync(0xffffffffu, ps1, off);
    }
    if (lx == 0) { red[threadIdx.x >> 5] = make_float2(ps0, ps1); }
    __syncthreads();
    if (threadIdx.x == 0) {
        float t0 = 0.f, t1 = 0.f;
        #pragma unroll
        for (int i = 0; i < 8; i++) { t0 += red[i].x; t1 += red[i].y; }
        atomicAdd(&g_pool[b*C + 2*cp],     t0);
        atomicAdd(&g_pool[b*C + 2*cp + 1], t1);
    }
}

// ---------------- K2: fused fp16 HMMA, fully cp.async pipelined ---------------
// smem bytes:
#define KO_W3  0        // 8192
#define KO_W4  8192     // 16384
#define KO_W5  24576    // 8192
#define KO_T2S 32768    // 32 rows * 528 = 16896
#define KO_INP 49664    // 64 rows * 528 = 33792
#define KO_S4  83456
#define KO_C4  83968
#define KO_B3  84480
#define KO_BT  84736
#define KO_B5  84992
#define KO_GM  85248
#define KO_SC  85504
#define KO_SCH 85760
#define KO_PL  85888
#define K2_SMEM 86144

__global__ void __launch_bounds__(256, 2) k2(const float* __restrict__ inp,
                                             const float* __restrict__ b3,
                                             const float* __restrict__ b4,
                                             const float* __restrict__ b5,
                                             const float* __restrict__ beta,
                                             const float* __restrict__ gamma,
                                             const float* __restrict__ sca_w,
                                             const float* __restrict__ sca_b,
                                             float* __restrict__ out) {
    extern __shared__ __align__(16) char smem[];
    uint2* W3 = (uint2*)(smem + KO_W3);
    uint2* W4 = (uint2*)(smem + KO_W4);
    uint2* W5 = (uint2*)(smem + KO_W5);
    __half2* T2S = (__half2*)(smem + KO_T2S);   // pitch 132 half2
    float* INP = (float*)(smem + KO_INP);       // pitch 132 floats
    float* S4  = (float*)(smem + KO_S4);
    float* C4B = (float*)(smem + KO_C4);
    float* B3B = (float*)(smem + KO_B3);
    float* BETB= (float*)(smem + KO_BT);
    float* B5B = (float*)(smem + KO_B5);
    float* GAMB= (float*)(smem + KO_GM);
    float* SCS = (float*)(smem + KO_SC);
    __half2* SCH = (__half2*)(smem + KO_SCH);
    float* PLS = (float*)(smem + KO_PL);

    int b = blockIdx.y, px0 = blockIdx.x * 128;
    int tid = threadIdx.x, lane = tid & 31, warp = tid >> 5;
    int g = lane >> 2, t = lane & 3;
    int m0 = warp * 16;
    int r0 = m0 + g, r1 = m0 + g + 8;

    // ---- G0: W3 + t2 tile
    {
        uint32_t s3 = smem_u32(W3);
        const char* g3 = (const char*)(g_w3f + b*1024);
        for (int i = tid; i < 512; i += 256) cpasync16(s3 + i*16, g3 + i*16);
        uint32_t st = smem_u32(T2S);
        const char* gt = (const char*)(g_t2p + (size_t)b*32*HW + px0);
        for (int i = tid; i < 1024; i += 256) {
            int row = i >> 5, col = i & 31;
            cpasync16(st + row*528 + col*16, gt + (size_t)row*HW*4 + col*16);
        }
        CP_COMMIT();
    }
    // ---- G1: inp tile
    {
        uint32_t si = smem_u32(INP);
        const char* gi = (const char*)(inp + (size_t)b*C*HW + px0);
        for (int i = tid; i < 2048; i += 256) {
            int row = i >> 5, col = i & 31;
            cpasync16(si + row*528 + col*16, gi + (size_t)row*HW*4 + col*16);
        }
        CP_COMMIT();
    }
    // ---- G2: W4 + W5
    {
        uint32_t s4 = smem_u32(W4);
        const char* g4 = (const char*)(g_w4f + b*2048);
        for (int i = tid; i < 1024; i += 256) cpasync16(s4 + i*16, g4 + i*16);
        uint32_t s5 = smem_u32(W5);
        const char* g5 = (const char*)(g_w5f + b*1024);
        for (int i = tid; i < 512; i += 256) cpasync16(s5 + i*16, g5 + i*16);
        CP_COMMIT();
    }

    if (tid < 64) {
        B3B[tid] = b3[b*64 + tid]; BETB[tid] = beta[tid];
        B5B[tid] = b5[b*64 + tid]; GAMB[tid] = gamma[tid];
        PLS[tid] = g_pool[b*64 + tid] * (1.f/(float)HW);
    } else if (tid < 192) {
        int u = tid - 64;
        S4[u] = g_s4[b*128 + u];
        C4B[u] = g_c4[b*128 + u] + b4[b*128 + u];
    }
    __syncthreads();
    if (tid < 64) {
        float acc = sca_b[tid];
        #pragma unroll 8
        for (int cc = 0; cc < 64; cc++) acc += sca_w[tid*64 + cc] * PLS[cc];
        SCS[tid] = acc;
    }
    __syncthreads();
    if (tid < 32) SCH[tid] = __floats2half2_rn(SCS[2*tid], SCS[2*tid + 1]);
    CP_WAIT(2);        // G0 (W3 + t2) complete
    __syncthreads();

    // ---- A-frags of X = sca*t2 from smem
    uint32_t xa[4][4];
    #pragma unroll
    for (int kk = 0; kk < 4; kk++) {
        int p0 = kk*8 + t, p1 = kk*8 + 4 + t;
        __half2 sc0 = SCH[p0], sc1 = SCH[p1];
        xa[kk][0] = h2u(__hmul2(T2S[p0*132 + r0], sc0));
        xa[kk][1] = h2u(__hmul2(T2S[p0*132 + r1], sc0));
        xa[kk][2] = h2u(__hmul2(T2S[p1*132 + r0], sc1));
        xa[kk][3] = h2u(__hmul2(T2S[p1*132 + r1], sc1));
    }

    // ---- pw3 GEMM (inp tile streams in behind this)
    float d3[8][4];
    #pragma unroll
    for (int n = 0; n < 8; n++) { d3[n][0]=0; d3[n][1]=0; d3[n][2]=0; d3[n][3]=0; }
    #pragma unroll
    for (int kk = 0; kk < 4; kk++)
        #pragma unroll
        for (int n = 0; n < 8; n++) {
            uint2 bw = W3[(n*4 + kk)*32 + lane];
            mma16816(d3[n], xa[kk][0], xa[kk][1], xa[kk][2], xa[kk][3], bw.x, bw.y);
        }

    CP_WAIT(1);        // G1 (inp) complete
    __syncthreads();

    // ---- y = inp + (d3+b3)*beta; y back into INP; stats; y-frags
    float y0v[16], y1v[16];
    float s0 = 0.f, q0 = 0.f, s1 = 0.f, q1 = 0.f;
    #pragma unroll
    for (int n = 0; n < 8; n++) {
        int oa = n*8 + 2*t;
        float bb0 = B3B[oa], bb1 = B3B[oa+1], bt0 = BETB[oa], bt1 = BETB[oa+1];
        float a0 = INP[oa*132 + r0]     + (d3[n][0] + bb0) * bt0;
        float a1 = INP[(oa+1)*132 + r0] + (d3[n][1] + bb1) * bt1;
        float a2 = INP[oa*132 + r1]     + (d3[n][2] + bb0) * bt0;
        float a3 = INP[(oa+1)*132 + r1] + (d3[n][3] + bb1) * bt1;
        INP[oa*132 + r0]     = a0;
        INP[(oa+1)*132 + r0] = a1;
        INP[oa*132 + r1]     = a2;
        INP[(oa+1)*132 + r1] = a3;
        y0v[n*2] = a0; y0v[n*2+1] = a1; y1v[n*2] = a2; y1v[n*2+1] = a3;
        s0 += a0 + a1; q0 += a0*a0 + a1*a1;
        s1 += a2 + a3; q1 += a2*a2 + a3*a3;
    }
    #pragma unroll
    for (int off = 1; off < 4; off <<= 1) {
        s0 += __shfl_xor_sync(0xffffffffu, s0, off);
        q0 += __shfl_xor_sync(0xffffffffu, q0, off);
        s1 += __shfl_xor_sync(0xffffffffu, s1, off);
        q1 += __shfl_xor_sync(0xffffffffu, q1, off);
    }
    float mu0 = s0*(1.f/64), mu1 = s1*(1.f/64);
    float rs0 = rsqrtf(q0*(1.f/64) - mu0*mu0 + EPS);
    float rs1 = rsqrtf(q1*(1.f/64) - mu1*mu1 + EPS);

    uint32_t ya[4][4];
    #pragma unroll
    for (int kk = 0; kk < 4; kk++) {
        ya[kk][0] = fh2(y0v[4*kk],   y0v[4*kk+1]);
        ya[kk][1] = fh2(y1v[4*kk],   y1v[4*kk+1]);
        ya[kk][2] = fh2(y0v[4*kk+2], y0v[4*kk+3]);
        ya[kk][3] = fh2(y1v[4*kk+2], y1v[4*kk+3]);
    }

    CP_WAIT(0);        // G2 (W4 + W5) complete
    __syncthreads();

    // ---- pw4 GEMM (ln2 folded)
    float d4[16][4];
    #pragma unroll
    for (int n = 0; n < 16; n++) { d4[n][0]=0; d4[n][1]=0; d4[n][2]=0; d4[n][3]=0; }
    #pragma unroll
    for (int kk = 0; kk < 4; kk++)
        #pragma unroll
        for (int n = 0; n < 16; n++) {
            uint2 bw = W4[(n*4 + kk)*32 + lane];
            mma16816(d4[n], ya[kk][0], ya[kk][1], ya[kk][2], ya[kk][3], bw.x, bw.y);
        }

    // ---- gate + LN-unfold -> pw5 A-frags
    float g0v[16], g1v[16];
    #pragma unroll
    for (int n = 0; n < 8; n++) {
        int oa = n*8 + 2*t;
        float s4a0 = S4[oa],    s4a1 = S4[oa+1];
        float s4b0 = S4[oa+64], s4b1 = S4[oa+65];
        float ca0 = C4B[oa],    ca1 = C4B[oa+1];
        float cb0 = C4B[oa+64], cb1 = C4B[oa+65];
        g0v[n*2]   = (rs0*(d4[n][0] - mu0*s4a0) + ca0) * (rs0*(d4[n+8][0] - mu0*s4b0) + cb0);
        g0v[n*2+1] = (rs0*(d4[n][1] - mu0*s4a1) + ca1) * (rs0*(d4[n+8][1] - mu0*s4b1) + cb1);
        g1v[n*2]   = (rs1*(d4[n][2] - mu1*s4a0) + ca0) * (rs1*(d4[n+8][2] - mu1*s4b0) + cb0);
        g1v[n*2+1] = (rs1*(d4[n][3] - mu1*s4a1) + ca1) * (rs1*(d4[n+8][3] - mu1*s4b1) + cb1);
    }
    uint32_t ga[4][4];
    #pragma unroll
    for (int kk = 0; kk < 4; kk++) {
        ga[kk][0] = fh2(g0v[4*kk],   g0v[4*kk+1]);
        ga[kk][1] = fh2(g1v[4*kk],   g1v[4*kk+1]);
        ga[kk][2] = fh2(g0v[4*kk+2], g0v[4*kk+3]);
        ga[kk][3] = fh2(g1v[4*kk+2], g1v[4*kk+3]);
    }

    // ---- pw5 GEMM
    float d5[8][4];
    #pragma unroll
    for (int n = 0; n < 8; n++) { d5[n][0]=0; d5[n][1]=0; d5[n][2]=0; d5[n][3]=0; }
    #pragma unroll
    for (int kk = 0; kk < 4; kk++)
        #pragma unroll
        for (int n = 0; n < 8; n++) {
            uint2 bw = W5[(n*4 + kk)*32 + lane];
            mma16816(d5[n], ga[kk][0], ga[kk][1], ga[kk][2], ga[kk][3], bw.x, bw.y);
        }

    // ---- final: out = y(INP) + (d5+b5)*gamma
    float* ob = out + (size_t)b*C*HW + px0;
    #pragma unroll
    for (int n = 0; n < 8; n++) {
        int oa = n*8 + 2*t;
        float bp0 = B5B[oa], bp1 = B5B[oa+1], gp0 = GAMB[oa], gp1 = GAMB[oa+1];
        ob[(size_t)oa*HW + r0]     = INP[oa*132 + r0]     + (d5[n][0] + bp0) * gp0;
        ob[(size_t)(oa+1)*HW + r0] = INP[(oa+1)*132 + r0] + (d5[n][1] + bp1) * gp1;
        ob[(size_t)oa*HW + r1]     = INP[oa*132 + r1]     + (d5[n][2] + bp0) * gp0;
        ob[(size_t)(oa+1)*HW + r1] = INP[(oa+1)*132 + r1] + (d5[n][3] + bp1) * gp1;
    }
}

// ---------------- launch ------------------------------------------------------
extern "C" void kernel_launch(void* const* d_in, const int* in_sizes, int n_in,
                              void* d_out, int out_size) {
    const float* inp   = (const float*)d_in[0];
    const float* w1    = (const float*)d_in[1];
    const float* b1    = (const float*)d_in[2];
    const float* w2    = (const float*)d_in[3];
    const float* b2    = (const float*)d_in[4];
    const float* w3    = (const float*)d_in[5];
    const float* b3    = (const float*)d_in[6];
    const float* w4    = (const float*)d_in[7];
    const float* b4    = (const float*)d_in[8];
    const float* w5    = (const float*)d_in[9];
    const float* b5    = (const float*)d_in[10];
    const float* ln1w  = (const float*)d_in[11];
    const float* ln1b  = (const float*)d_in[12];
    const float* ln2w  = (const float*)d_in[13];
    const float* ln2b  = (const float*)d_in[14];
    const float* scaw  = (const float*)d_in[15];
    const float* scab  = (const float*)d_in[16];
    const float* beta  = (const float*)d_in[17];
    const float* gamma = (const float*)d_in[18];
    float* out = (float*)d_out;

    cudaFuncSetAttribute(k1, cudaFuncAttributeMaxDynamicSharedMemorySize, K1_SMEM);
    cudaFuncSetAttribute(k2, cudaFuncAttributeMaxDynamicSharedMemorySize, K2_SMEM);

    k_prep<<<4097, 32>>>(w1, w2, w3, w4, w5, ln1w, ln1b, ln2w, ln2b);
    k1 <<<dim3(HW/128, B), 256, K1_SMEM>>>(inp, b1);
    kdw<<<dim3(IW/32, IH/32, B*32), 256>>>(b2);
    k2 <<<dim3(HW/128, B), 256, K2_SMEM>>>(inp, b3, b4, b5, beta, gamma, scaw, scab, out);
}

// round 17
// speedup vs baseline: 2.5612x; 1.1096x over previous
#include <cuda_runtime.h>
#include <cuda_fp16.h>
#include <cstdint>
#include <math.h>

#define B   8
#define C   64
#define DW  128
#define IH  256
#define IW  256
#define HW  65536
#define EPS 1e-6f

// ---------- fp16 pack helpers ----------
__device__ __forceinline__ uint32_t fh2(float a, float b) {
    __half2 h = __floats2half2_rn(a, b);
    return *(uint32_t*)&h;
}
__device__ __forceinline__ uint32_t h2u(__half2 h) { return *(uint32_t*)&h; }

// ---------- mma.sync m16n8k16 fp16 ----------
__device__ __forceinline__ void mma16816(float* d,
        uint32_t a0, uint32_t a1, uint32_t a2, uint32_t a3,
        uint32_t b0, uint32_t b1) {
    asm volatile("mma.sync.aligned.m16n8k16.row.col.f32.f16.f16.f32 "
        "{%0,%1,%2,%3}, {%4,%5,%6,%7}, {%8,%9}, {%0,%1,%2,%3};"
        : "+f"(d[0]), "+f"(d[1]), "+f"(d[2]), "+f"(d[3])
        : "r"(a0), "r"(a1), "r"(a2), "r"(a3), "r"(b0), "r"(b1));
}

// ---------- cp.async ----------
__device__ __forceinline__ uint32_t smem_u32(const void* p) {
    uint32_t a;
    asm("{ .reg .u64 t; cvta.to.shared.u64 t, %1; cvt.u32.u64 %0, t; }" : "=r"(a) : "l"(p));
    return a;
}
__device__ __forceinline__ void cpasync16(uint32_t s, const void* g) {
    asm volatile("cp.async.ca.shared.global [%0], [%1], 16;" :: "r"(s), "l"(g) : "memory");
}
#define CP_COMMIT() asm volatile("cp.async.commit_group;" ::: "memory")
#define CP_WAIT(n)  asm volatile("cp.async.wait_group %0;" :: "n"(n) : "memory")

// ---------------- device scratch ----------------------------------------------
__device__ __align__(16) uint2 g_w1f[B*2048];
__device__ float g_s1 [B*DW];
__device__ float g_c1 [B*DW];
__device__ float g_w2 [B*DW*9];
__device__ __align__(16) uint2 g_w3f[B*1024];
__device__ __align__(16) uint2 g_w4f[B*2048];
__device__ float g_s4 [B*DW];
__device__ float g_c4 [B*DW];
__device__ __align__(16) uint2 g_w5f[B*1024];
__device__ __half2 g_t1p[(size_t)B*64*HW];
__device__ __half2 g_t2p[(size_t)B*32*HW];
__device__ float g_pool[B*C];

// ---------------- prep (unchanged) --------------------------------------------
__global__ void k_prep(const float* __restrict__ w1, const float* __restrict__ w2,
                       const float* __restrict__ w3, const float* __restrict__ w4,
                       const float* __restrict__ w5,
                       const float* __restrict__ ln1w, const float* __restrict__ ln1b,
                       const float* __restrict__ ln2w, const float* __restrict__ ln2b) {
    int blk = blockIdx.x, t = threadIdx.x;
    if (blk >= 4096) { for (int i = t; i < B*C; i += 32) g_pool[i] = 0.f; return; }

    if (blk < 1024 || (blk >= 2560 && blk < 3584)) {
        bool is1 = (blk < 1024);
        int r = is1 ? blk : blk - 2560;
        const float* src = (is1 ? w1 : w4) + r*64;
        const float* lw = is1 ? ln1w : ln2w;
        const float* lb = is1 ? ln1b : ln2b;
        int b = r >> 7, o = r & 127;
        int n = o >> 3, g = o & 7;
        float sq = 0.f;
        for (int i = t; i < 64; i += 32) { float v = src[i]; sq += v*v; }
        #pragma unroll
        for (int off = 16; off; off >>= 1) sq += __shfl_xor_sync(0xffffffffu, sq, off);
        float rn = 1.0f / sqrtf(sq);
        float s = 0.f, cx = 0.f;
        for (int i = t; i < 64; i += 32) {
            float wn = src[i] * rn;
            s += wn * lw[i]; cx += wn * lb[i];
        }
        #pragma unroll
        for (int off = 16; off; off >>= 1) {
            s  += __shfl_xor_sync(0xffffffffu, s,  off);
            cx += __shfl_xor_sync(0xffffffffu, cx, off);
        }
        if (t == 0) {
            if (is1) { g_s1[r] = s; g_c1[r] = cx; }
            else     { g_s4[r] = s; g_c4[r] = cx; }
        }
        if (t < 16) {
            int kk = t >> 2, tt = t & 3;
            int k0 = kk*16 + 2*tt;
            float f0 = src[k0]   * rn * lw[k0];
            float f1 = src[k0+1] * rn * lw[k0+1];
            float f2 = src[k0+8] * rn * lw[k0+8];
            float f3 = src[k0+9] * rn * lw[k0+9];
            int idx = b*2048 + (n*4 + kk)*32 + g*4 + tt;
            uint2 v; v.x = fh2(f0, f1); v.y = fh2(f2, f3);
            if (is1) g_w1f[idx] = v; else g_w4f[idx] = v;
        }
        return;
    }
    if (blk < 2048) {
        int r = blk - 1024;
        const float* src = w2 + r*9;
        float sq = 0.f;
        for (int i = t; i < 9; i += 32) { float v = src[i]; sq += v*v; }
        #pragma unroll
        for (int off = 16; off; off >>= 1) sq += __shfl_xor_sync(0xffffffffu, sq, off);
        float rn = 1.0f / sqrtf(sq);
        for (int i = t; i < 9; i += 32) g_w2[r*9 + i] = src[i] * rn;
        return;
    }
    bool is3 = (blk < 2560);
    int r = is3 ? (blk - 2048) : (blk - 3584);
    const float* src = (is3 ? w3 : w5) + r*64;
    int b = r >> 6, o = r & 63;
    int n = o >> 3, g = o & 7;
    float sq = 0.f;
    for (int i = t; i < 64; i += 32) { float v = src[i]; sq += v*v; }
    #pragma unroll
    for (int off = 16; off; off >>= 1) sq += __shfl_xor_sync(0xffffffffu, sq, off);
    float rn = 1.0f / sqrtf(sq);
    if (t < 16) {
        int kk = t >> 2, tt = t & 3;
        int k0 = kk*16 + 2*tt;
        int idx = b*1024 + (n*4 + kk)*32 + g*4 + tt;
        uint2 v;
        v.x = fh2(src[k0]*rn,   src[k0+1]*rn);
        v.y = fh2(src[k0+8]*rn, src[k0+9]*rn);
        if (is3) g_w3f[idx] = v; else g_w5f[idx] = v;
    }
}

// ---------------- K1: fp16 HMMA, cp.async inp, coalesced t1 stores ------------
// smem: W1@0(16384) BUF@16384(34816: inp pitch-132 f32 / t1-stage pitch-136 half2)
//       S1B@51200(512) C1B@51712(512) = 52224
#define K1_BUF 16384
#define K1_S1  51200
#define K1_C1  51712
#define K1_SMEM 52224

__global__ void __launch_bounds__(256, 2) k1(const float* __restrict__ inp,
                                             const float* __restrict__ b1) {
    extern __shared__ __align__(16) char smem[];
    uint2* W1 = (uint2*)smem;
    float* INP = (float*)(smem + K1_BUF);          // pitch 132 floats
    uint32_t* ST = (uint32_t*)(smem + K1_BUF);     // pitch 136 words (half2 slots)
    float* S1B = (float*)(smem + K1_S1);
    float* C1B = (float*)(smem + K1_C1);
    int b = blockIdx.y, px0 = blockIdx.x * 128;
    int tid = threadIdx.x, lane = tid & 31, warp = tid >> 5;
    int g = lane >> 2, t = lane & 3;
    int m0 = warp * 16;
    int r0 = m0 + g, r1 = m0 + g + 8;

    {
        uint32_t sw = smem_u32(W1);
        const char* gw = (const char*)(g_w1f + b*2048);
        for (int i = tid; i < 1024; i += 256) cpasync16(sw + i*16, gw + i*16);
        uint32_t si = smem_u32(INP);
        const char* gi = (const char*)(inp + (size_t)b*C*HW + px0);
        for (int i = tid; i < 2048; i += 256) {
            int row = i >> 5, col = i & 31;
            cpasync16(si + row*528 + col*16, gi + (size_t)row*HW*4 + col*16);
        }
        CP_COMMIT();
    }
    if (tid < 128) { S1B[tid] = g_s1[b*DW + tid]; C1B[tid] = g_c1[b*DW + tid] + b1[b*DW + tid]; }
    CP_WAIT(0);
    __syncthreads();

    float xv0[16], xv1[16];
    float s0 = 0.f, q0 = 0.f, s1 = 0.f, q1 = 0.f;
    #pragma unroll
    for (int kk = 0; kk < 4; kk++)
        #pragma unroll
        for (int j = 0; j < 4; j++) {
            int ch = kk*16 + ((j < 2) ? (2*t + j) : (2*t + 8 + (j - 2)));
            float v0 = INP[ch*132 + r0];
            float v1 = INP[ch*132 + r1];
            xv0[kk*4 + j] = v0; xv1[kk*4 + j] = v1;
            s0 += v0; q0 += v0*v0; s1 += v1; q1 += v1*v1;
        }
    #pragma unroll
    for (int off = 1; off < 4; off <<= 1) {
        s0 += __shfl_xor_sync(0xffffffffu, s0, off);
        q0 += __shfl_xor_sync(0xffffffffu, q0, off);
        s1 += __shfl_xor_sync(0xffffffffu, s1, off);
        q1 += __shfl_xor_sync(0xffffffffu, q1, off);
    }
    float mu0 = s0*(1.f/64), mu1 = s1*(1.f/64);
    float rs0 = rsqrtf(q0*(1.f/64) - mu0*mu0 + EPS);
    float rs1 = rsqrtf(q1*(1.f/64) - mu1*mu1 + EPS);

    uint32_t ah[4][4];
    #pragma unroll
    for (int kk = 0; kk < 4; kk++) {
        ah[kk][0] = fh2(xv0[kk*4+0], xv0[kk*4+1]);
        ah[kk][1] = fh2(xv1[kk*4+0], xv1[kk*4+1]);
        ah[kk][2] = fh2(xv0[kk*4+2], xv0[kk*4+3]);
        ah[kk][3] = fh2(xv1[kk*4+2], xv1[kk*4+3]);
    }
    __syncthreads();   // all INP reads done before staging overwrite

    float d[16][4];
    #pragma unroll
    for (int n = 0; n < 16; n++) { d[n][0]=0; d[n][1]=0; d[n][2]=0; d[n][3]=0; }
    #pragma unroll
    for (int kk = 0; kk < 4; kk++)
        #pragma unroll
        for (int n = 0; n < 16; n++) {
            uint2 bw = W1[(n*4 + kk)*32 + lane];
            mma16816(d[n], ah[kk][0], ah[kk][1], ah[kk][2], ah[kk][3], bw.x, bw.y);
        }

    // stage t1 (half2) into ST, pitch 136 words (bank: pr*8+... conflict-free)
    #pragma unroll
    for (int n = 0; n < 16; n++) {
        int oa = n*8 + 2*t;
        int pr = n*4 + t;
        float S0 = S1B[oa], Sv1 = S1B[oa+1], Cc0 = C1B[oa], Cc1 = C1B[oa+1];
        ST[pr*136 + r0] = fh2(rs0*(d[n][0] - mu0*S0) + Cc0, rs0*(d[n][1] - mu0*Sv1) + Cc1);
        ST[pr*136 + r1] = fh2(rs1*(d[n][2] - mu1*S0) + Cc0, rs1*(d[n][3] - mu1*Sv1) + Cc1);
    }
    __syncthreads();

    // coalesced copy: 64 rows x 512B
    char* ob = (char*)(g_t1p + (size_t)b*64*HW + px0);
    const char* sb = (const char*)ST;
    #pragma unroll
    for (int i = tid; i < 2048; i += 256) {
        int pr = i >> 5, c = i & 31;
        *(uint4*)(ob + (size_t)pr*HW*4 + c*16) = *(const uint4*)(sb + pr*544 + c*16);
    }
}

// ---------------- K_dw: 64x32 tiles, 8 px/thread ------------------------------
__global__ void __launch_bounds__(256) kdw(const float* __restrict__ b2) {
    int bc = blockIdx.z; int b = bc >> 5; int cp = bc & 31;
    __shared__ float2 s1[34][66];
    __shared__ float2 s2[34][66];
    __shared__ float wA[2][9], wB[2][9], bb4[4];
    __shared__ float2 red[8];

    const __half2* in1 = g_t1p + ((size_t)b*64 + cp)      * HW;
    const __half2* in2 = g_t1p + ((size_t)b*64 + cp + 32) * HW;
    int x0 = blockIdx.x * 64, y0 = blockIdx.y * 32;

    for (int i = threadIdx.x; i < 34*66; i += 256) {
        int ly = i / 66, lx = i % 66;
        int gy = y0 + ly - 1, gx = x0 + lx - 1;
        bool ok = (gy >= 0 && gy < IH && gx >= 0 && gx < IW);
        float2 v1 = ok ? __half22float2(in1[gy*IW + gx]) : make_float2(0.f, 0.f);
        float2 v2 = ok ? __half22float2(in2[gy*IW + gx]) : make_float2(0.f, 0.f);
        s1[ly][lx] = v1;
        s2[ly][lx] = v2;
    }
    if (threadIdx.x < 18) {
        int u = threadIdx.x;
        wA[u/9][u%9] = g_w2[((size_t)b*DW + 2*cp + u/9)*9 + u%9];
    } else if (threadIdx.x < 36) {
        int u = threadIdx.x - 18;
        wB[u/9][u%9] = g_w2[((size_t)b*DW + 64 + 2*cp + u/9)*9 + u%9];
    } else if (threadIdx.x < 40) {
        int u = threadIdx.x - 36;
        bb4[u] = b2[b*DW + ((u < 2) ? (2*cp + u) : (64 + 2*cp + u - 2))];
    }
    __syncthreads();

    int lx = threadIdx.x & 63, ly0 = (threadIdx.x >> 6) * 8;
    __half2* ob = g_t2p + ((size_t)b*32 + cp)*HW;
    float ps0 = 0.f, ps1 = 0.f;
    #pragma unroll
    for (int r = 0; r < 8; r++) {
        int ly = ly0 + r;
        float a0 = bb4[0], a1 = bb4[1], d0 = bb4[2], d1 = bb4[3];
        #pragma unroll
        for (int ky = 0; ky < 3; ky++)
            #pragma unroll
            for (int kx = 0; kx < 3; kx++) {
                float2 v1 = s1[ly + ky][lx + kx];
                float2 v2 = s2[ly + ky][lx + kx];
                a0 += wA[0][ky*3 + kx] * v1.x;
                a1 += wA[1][ky*3 + kx] * v1.y;
                d0 += wB[0][ky*3 + kx] * v2.x;
                d1 += wB[1][ky*3 + kx] * v2.y;
            }
        float g0 = a0 * d0, g1 = a1 * d1;
        ob[(y0 + ly)*IW + (x0 + lx)] = __floats2half2_rn(g0, g1);
        ps0 += g0; ps1 += g1;
    }
    #pragma unroll
    for (int off = 16; off; off >>= 1) {
        ps0 += __shfl_down_sync(0xffffffffu, ps0, off);
        ps1 += __shfl_down_sync(0xffffffffu, ps1, off);
    }
    if ((threadIdx.x & 31) == 0) red[threadIdx.x >> 5] = make_float2(ps0, ps1);
    __syncthreads();
    if (threadIdx.x == 0) {
        float t0 = 0.f, t1 = 0.f;
        #pragma unroll
        for (int i = 0; i < 8; i++) { t0 += red[i].x; t1 += red[i].y; }
        atomicAdd(&g_pool[b*C + 2*cp],     t0);
        atomicAdd(&g_pool[b*C + 2*cp + 1], t1);
    }
}

// ---------------- K2: fused fp16 HMMA, coalesced out --------------------------
#define KO_W3  0
#define KO_W4  8192
#define KO_W5  24576
#define KO_T2S 32768
#define KO_INP 49664
#define KO_S4  83456
#define KO_C4  83968
#define KO_B3  84480
#define KO_BT  84736
#define KO_B5  84992
#define KO_GM  85248
#define KO_SC  85504
#define KO_SCH 85760
#define KO_PL  85888
#define K2_SMEM 86144

__global__ void __launch_bounds__(256, 2) k2(const float* __restrict__ inp,
                                             const float* __restrict__ b3,
                                             const float* __restrict__ b4,
                                             const float* __restrict__ b5,
                                             const float* __restrict__ beta,
                                             const float* __restrict__ gamma,
                                             const float* __restrict__ sca_w,
                                             const float* __restrict__ sca_b,
                                             float* __restrict__ out) {
    extern __shared__ __align__(16) char smem[];
    uint2* W3 = (uint2*)(smem + KO_W3);
    uint2* W4 = (uint2*)(smem + KO_W4);
    uint2* W5 = (uint2*)(smem + KO_W5);
    __half2* T2S = (__half2*)(smem + KO_T2S);
    float* INP = (float*)(smem + KO_INP);
    float* S4  = (float*)(smem + KO_S4);
    float* C4B = (float*)(smem + KO_C4);
    float* B3B = (float*)(smem + KO_B3);
    float* BETB= (float*)(smem + KO_BT);
    float* B5B = (float*)(smem + KO_B5);
    float* GAMB= (float*)(smem + KO_GM);
    float* SCS = (float*)(smem + KO_SC);
    __half2* SCH = (__half2*)(smem + KO_SCH);
    float* PLS = (float*)(smem + KO_PL);

    int b = blockIdx.y, px0 = blockIdx.x * 128;
    int tid = threadIdx.x, lane = tid & 31, warp = tid >> 5;
    int g = lane >> 2, t = lane & 3;
    int m0 = warp * 16;
    int r0 = m0 + g, r1 = m0 + g + 8;

    {
        uint32_t s3 = smem_u32(W3);
        const char* g3 = (const char*)(g_w3f + b*1024);
        for (int i = tid; i < 512; i += 256) cpasync16(s3 + i*16, g3 + i*16);
        uint32_t st = smem_u32(T2S);
        const char* gt = (const char*)(g_t2p + (size_t)b*32*HW + px0);
        for (int i = tid; i < 1024; i += 256) {
            int row = i >> 5, col = i & 31;
            cpasync16(st + row*528 + col*16, gt + (size_t)row*HW*4 + col*16);
        }
        CP_COMMIT();
    }
    {
        uint32_t si = smem_u32(INP);
        const char* gi = (const char*)(inp + (size_t)b*C*HW + px0);
        for (int i = tid; i < 2048; i += 256) {
            int row = i >> 5, col = i & 31;
            cpasync16(si + row*528 + col*16, gi + (size_t)row*HW*4 + col*16);
        }
        CP_COMMIT();
    }
    {
        uint32_t s4 = smem_u32(W4);
        const char* g4 = (const char*)(g_w4f + b*2048);
        for (int i = tid; i < 1024; i += 256) cpasync16(s4 + i*16, g4 + i*16);
        uint32_t s5 = smem_u32(W5);
        const char* g5 = (const char*)(g_w5f + b*1024);
        for (int i = tid; i < 512; i += 256) cpasync16(s5 + i*16, g5 + i*16);
        CP_COMMIT();
    }

    if (tid < 64) {
        B3B[tid] = b3[b*64 + tid]; BETB[tid] = beta[tid];
        B5B[tid] = b5[b*64 + tid]; GAMB[tid] = gamma[tid];
        PLS[tid] = g_pool[b*64 + tid] * (1.f/(float)HW);
    } else if (tid < 192) {
        int u = tid - 64;
        S4[u] = g_s4[b*128 + u];
        C4B[u] = g_c4[b*128 + u] + b4[b*128 + u];
    }
    __syncthreads();
    if (tid < 64) {
        float acc = sca_b[tid];
        #pragma unroll 8
        for (int cc = 0; cc < 64; cc++) acc += sca_w[tid*64 + cc] * PLS[cc];
        SCS[tid] = acc;
    }
    __syncthreads();
    if (tid < 32) SCH[tid] = __floats2half2_rn(SCS[2*tid], SCS[2*tid + 1]);
    CP_WAIT(2);
    __syncthreads();

    uint32_t xa[4][4];
    #pragma unroll
    for (int kk = 0; kk < 4; kk++) {
        int p0 = kk*8 + t, p1 = kk*8 + 4 + t;
        __half2 sc0 = SCH[p0], sc1 = SCH[p1];
        xa[kk][0] = h2u(__hmul2(T2S[p0*132 + r0], sc0));
        xa[kk][1] = h2u(__hmul2(T2S[p0*132 + r1], sc0));
        xa[kk][2] = h2u(__hmul2(T2S[p1*132 + r0], sc1));
        xa[kk][3] = h2u(__hmul2(T2S[p1*132 + r1], sc1));
    }

    float d3[8][4];
    #pragma unroll
    for (int n = 0; n < 8; n++) { d3[n][0]=0; d3[n][1]=0; d3[n][2]=0; d3[n][3]=0; }
    #pragma unroll
    for (int kk = 0; kk < 4; kk++)
        #pragma unroll
        for (int n = 0; n < 8; n++) {
            uint2 bw = W3[(n*4 + kk)*32 + lane];
            mma16816(d3[n], xa[kk][0], xa[kk][1], xa[kk][2], xa[kk][3], bw.x, bw.y);
        }

    CP_WAIT(1);
    __syncthreads();

    float y0v[16], y1v[16];
    float s0 = 0.f, q0 = 0.f, s1 = 0.f, q1 = 0.f;
    #pragma unroll
    for (int n = 0; n < 8; n++) {
        int oa = n*8 + 2*t;
        float bb0 = B3B[oa], bb1 = B3B[oa+1], bt0 = BETB[oa], bt1 = BETB[oa+1];
        float a0 = INP[oa*132 + r0]     + (d3[n][0] + bb0) * bt0;
        float a1 = INP[(oa+1)*132 + r0] + (d3[n][1] + bb1) * bt1;
        float a2 = INP[oa*132 + r1]     + (d3[n][2] + bb0) * bt0;
        float a3 = INP[(oa+1)*132 + r1] + (d3[n][3] + bb1) * bt1;
        INP[oa*132 + r0]     = a0;
        INP[(oa+1)*132 + r0] = a1;
        INP[oa*132 + r1]     = a2;
        INP[(oa+1)*132 + r1] = a3;
        y0v[n*2] = a0; y0v[n*2+1] = a1; y1v[n*2] = a2; y1v[n*2+1] = a3;
        s0 += a0 + a1; q0 += a0*a0 + a1*a1;
        s1 += a2 + a3; q1 += a2*a2 + a3*a3;
    }
    #pragma unroll
    for (int off = 1; off < 4; off <<= 1) {
        s0 += __shfl_xor_sync(0xffffffffu, s0, off);
        q0 += __shfl_xor_sync(0xffffffffu, q0, off);
        s1 += __shfl_xor_sync(0xffffffffu, s1, off);
        q1 += __shfl_xor_sync(0xffffffffu, q1, off);
    }
    float mu0 = s0*(1.f/64), mu1 = s1*(1.f/64);
    float rs0 = rsqrtf(q0*(1.f/64) - mu0*mu0 + EPS);
    float rs1 = rsqrtf(q1*(1.f/64) - mu1*mu1 + EPS);

    uint32_t ya[4][4];
    #pragma unroll
    for (int kk = 0; kk < 4; kk++) {
        ya[kk][0] = fh2(y0v[4*kk],   y0v[4*kk+1]);
        ya[kk][1] = fh2(y1v[4*kk],   y1v[4*kk+1]);
        ya[kk][2] = fh2(y0v[4*kk+2], y0v[4*kk+3]);
        ya[kk][3] = fh2(y1v[4*kk+2], y1v[4*kk+3]);
    }

    CP_WAIT(0);
    __syncthreads();

    float d4[16][4];
    #pragma unroll
    for (int n = 0; n < 16; n++) { d4[n][0]=0; d4[n][1]=0; d4[n][2]=0; d4[n][3]=0; }
    #pragma unroll
    for (int kk = 0; kk < 4; kk++)
        #pragma unroll
        for (int n = 0; n < 16; n++) {
            uint2 bw = W4[(n*4 + kk)*32 + lane];
            mma16816(d4[n], ya[kk][0], ya[kk][1], ya[kk][2], ya[kk][3], bw.x, bw.y);
        }

    float g0v[16], g1v[16];
    #pragma unroll
    for (int n = 0; n < 8; n++) {
        int oa = n*8 + 2*t;
        float s4a0 = S4[oa],    s4a1 = S4[oa+1];
        float s4b0 = S4[oa+64], s4b1 = S4[oa+65];
        float ca0 = C4B[oa],    ca1 = C4B[oa+1];
        float cb0 = C4B[oa+64], cb1 = C4B[oa+65];
        g0v[n*2]   = (rs0*(d4[n][0] - mu0*s4a0) + ca0) * (rs0*(d4[n+8][0] - mu0*s4b0) + cb0);
        g0v[n*2+1] = (rs0*(d4[n][1] - mu0*s4a1) + ca1) * (rs0*(d4[n+8][1] - mu0*s4b1) + cb1);
        g1v[n*2]   = (rs1*(d4[n][2] - mu1*s4a0) + ca0) * (rs1*(d4[n+8][2] - mu1*s4b0) + cb0);
        g1v[n*2+1] = (rs1*(d4[n][3] - mu1*s4a1) + ca1) * (rs1*(d4[n+8][3] - mu1*s4b1) + cb1);
    }
    uint32_t ga[4][4];
    #pragma unroll
    for (int kk = 0; kk < 4; kk++) {
        ga[kk][0] = fh2(g0v[4*kk],   g0v[4*kk+1]);
        ga[kk][1] = fh2(g1v[4*kk],   g1v[4*kk+1]);
        ga[kk][2] = fh2(g0v[4*kk+2], g0v[4*kk+3]);
        ga[kk][3] = fh2(g1v[4*kk+2], g1v[4*kk+3]);
    }

    float d5[8][4];
    #pragma unroll
    for (int n = 0; n < 8; n++) { d5[n][0]=0; d5[n][1]=0; d5[n][2]=0; d5[n][3]=0; }
    #pragma unroll
    for (int kk = 0; kk < 4; kk++)
        #pragma unroll
        for (int n = 0; n < 8; n++) {
            uint2 bw = W5[(n*4 + kk)*32 + lane];
            mma16816(d5[n], ga[kk][0], ga[kk][1], ga[kk][2], ga[kk][3], bw.x, bw.y);
        }

    // ---- out = y + (d5+b5)*gamma, written over lane-private y slots, then coalesced
    #pragma unroll
    for (int n = 0; n < 8; n++) {
        int oa = n*8 + 2*t;
        float bp0 = B5B[oa], bp1 = B5B[oa+1], gp0 = GAMB[oa], gp1 = GAMB[oa+1];
        INP[oa*132 + r0]     += (d5[n][0] + bp0) * gp0;
        INP[(oa+1)*132 + r0] += (d5[n][1] + bp1) * gp1;
        INP[oa*132 + r1]     += (d5[n][2] + bp0) * gp0;
        INP[(oa+1)*132 + r1] += (d5[n][3] + bp1) * gp1;
    }
    __syncthreads();
    char* ob = (char*)(out + (size_t)b*C*HW + px0);
    const char* sb = (const char*)INP;
    #pragma unroll
    for (int i = tid; i < 2048; i += 256) {
        int row = i >> 5, c = i & 31;
        *(uint4*)(ob + (size_t)row*HW*4 + c*16) = *(const uint4*)(sb + row*528 + c*16);
    }
}

// ---------------- launch ------------------------------------------------------
extern "C" void kernel_launch(void* const* d_in, const int* in_sizes, int n_in,
                              void* d_out, int out_size) {
    const float* inp   = (const float*)d_in[0];
    const float* w1    = (const float*)d_in[1];
    const float* b1    = (const float*)d_in[2];
    const float* w2    = (const float*)d_in[3];
    const float* b2    = (const float*)d_in[4];
    const float* w3    = (const float*)d_in[5];
    const float* b3    = (const float*)d_in[6];
    const float* w4    = (const float*)d_in[7];
    const float* b4    = (const float*)d_in[8];
    const float* w5    = (const float*)d_in[9];
    const float* b5    = (const float*)d_in[10];
    const float* ln1w  = (const float*)d_in[11];
    const float* ln1b  = (const float*)d_in[12];
    const float* ln2w  = (const float*)d_in[13];
    const float* ln2b  = (const float*)d_in[14];
    const float* scaw  = (const float*)d_in[15];
    const float* scab  = (const float*)d_in[16];
    const float* beta  = (const float*)d_in[17];
    const float* gamma = (const float*)d_in[18];
    float* out = (float*)d_out;

    cudaFuncSetAttribute(k1, cudaFuncAttributeMaxDynamicSharedMemorySize, K1_SMEM);
    cudaFuncSetAttribute(k2, cudaFuncAttributeMaxDynamicSharedMemorySize, K2_SMEM);

    k_prep<<<4097, 32>>>(w1, w2, w3, w4, w5, ln1w, ln1b, ln2w, ln2b);
    k1 <<<dim3(HW/128, B), 256, K1_SMEM>>>(inp, b1);
    kdw<<<dim3(IW/64, IH/32, B*32), 256>>>(b2);
    k2 <<<dim3(HW/128, B), 256, K2_SMEM>>>(inp, b3, b4, b5, beta, gamma, scaw, scab, out);
}